// round 2
// baseline (speedup 1.0000x reference)
#include <cuda_runtime.h>
#include <cuda_bf16.h>
#include <cstddef>

// ---------------- problem constants ----------------
#define S_LEN   4096
#define HDIM    2048
#define NH      16
#define NKV     8
#define HD      128
#define D2      64
#define QKV_N   4096          // NH*HD + 2*NKV*HD
#define ATT_SCALE 0.08838834764831845f   // 128^-0.5
#define EPS_RMS 1e-6f

// ---------------- scratch (device globals: allowed) ----------------
__device__ float g_qkv[(size_t)S_LEN * QKV_N];       // 64 MB
__device__ float g_q[(size_t)NH  * S_LEN * HD];      // 32 MB  [h][s][d]
__device__ float g_k[(size_t)NKV * S_LEN * HD];      // 16 MB  [kv][s][d]
__device__ float g_ao[(size_t)S_LEN * (NH * HD)];    // 32 MB  [s][h*128+d]

// ---------------- generic fp32 GEMM: C[M,N] = A[M,K] @ B[K,N] ----------------
// 128x128 block tile, BK=8, 256 threads, 8x8 register micro-tile.
__global__ void gemm128_kernel(const float* __restrict__ A,
                               const float* __restrict__ B,
                               float* __restrict__ C,
                               int M, int N, int K) {
    __shared__ float As[8 * 128];   // As[kk][r]  (transposed A tile)
    __shared__ float Bs[8 * 128];   // Bs[kk][c]
    const int tid = threadIdx.x;
    const int tx = tid & 15;        // 0..15  -> column group
    const int ty = tid >> 4;        // 0..15  -> row group
    const int bm = blockIdx.y * 128;
    const int bn = blockIdx.x * 128;

    // A-tile loader mapping: 256 threads x float4 = 1024 floats = 128 rows x 8 cols
    const int ar = tid >> 1;                 // row 0..127
    const int ac = (tid & 1) * 4;            // col 0 or 4
    // B-tile loader mapping: 256 threads x float4 = 8 rows x 128 cols
    const int br = tid >> 5;                 // row 0..7
    const int bc = (tid & 31) * 4;           // col 0..124

    float acc[8][8];
#pragma unroll
    for (int i = 0; i < 8; i++)
#pragma unroll
        for (int j = 0; j < 8; j++) acc[i][j] = 0.f;

    for (int k0 = 0; k0 < K; k0 += 8) {
        // load A tile 128x8 via float4, store transposed As[c][r]
        {
            float4 av = *(const float4*)&A[(size_t)(bm + ar) * K + (k0 + ac)];
            As[(ac + 0) * 128 + ar] = av.x;
            As[(ac + 1) * 128 + ar] = av.y;
            As[(ac + 2) * 128 + ar] = av.z;
            As[(ac + 3) * 128 + ar] = av.w;
        }
        // load B tile 8x128 via float4
        {
            float4 bv = *(const float4*)&B[(size_t)(k0 + br) * N + (bn + bc)];
            *(float4*)&Bs[br * 128 + bc] = bv;
        }
        __syncthreads();

#pragma unroll
        for (int kk = 0; kk < 8; kk++) {
            float a[8], b[8];
            float4 t;
            t = *(const float4*)&As[kk * 128 + ty * 8];     a[0]=t.x; a[1]=t.y; a[2]=t.z; a[3]=t.w;
            t = *(const float4*)&As[kk * 128 + ty * 8 + 4]; a[4]=t.x; a[5]=t.y; a[6]=t.z; a[7]=t.w;
            t = *(const float4*)&Bs[kk * 128 + tx * 8];     b[0]=t.x; b[1]=t.y; b[2]=t.z; b[3]=t.w;
            t = *(const float4*)&Bs[kk * 128 + tx * 8 + 4]; b[4]=t.x; b[5]=t.y; b[6]=t.z; b[7]=t.w;
#pragma unroll
            for (int i = 0; i < 8; i++)
#pragma unroll
                for (int j = 0; j < 8; j++)
                    acc[i][j] += a[i] * b[j];
        }
        __syncthreads();
    }

#pragma unroll
    for (int i = 0; i < 8; i++) {
        size_t row = (size_t)(bm + ty * 8 + i) * N + bn + tx * 8;
        *(float4*)&C[row]     = make_float4(acc[i][0], acc[i][1], acc[i][2], acc[i][3]);
        *(float4*)&C[row + 4] = make_float4(acc[i][4], acc[i][5], acc[i][6], acc[i][7]);
    }
}

// ---------------- RMSNorm + mRoPE, scatter into attention layouts ----------------
// grid = S, block = 256 (8 warps). Warp handles heads h, h+8, h+16 (24 heads: 16 q + 8 k).
__global__ void normrope_kernel(const float* __restrict__ qkv,
                                const int*   __restrict__ positions,
                                const float* __restrict__ qw,
                                const float* __restrict__ kw,
                                const float* __restrict__ cache,
                                float* __restrict__ gq,
                                float* __restrict__ gk) {
    const int s = blockIdx.x;
    __shared__ float cs[D2], sn[D2];
    const int tid = threadIdx.x;

    if (tid < D2) {
        int i = tid;
        int m3 = i % 3;
        int sec = (i < 60) ? ((m3 == 1) ? 1 : ((m3 == 2) ? 2 : 0)) : 0;
        int pos = positions[sec * S_LEN + s];
        cs[i] = cache[(size_t)pos * HD + i];
        sn[i] = cache[(size_t)pos * HD + D2 + i];
    }
    __syncthreads();

    const int warp = tid >> 5;
    const int lane = tid & 31;
    const int dbase = lane * 4;          // each lane owns 4 consecutive dims

    for (int h = warp; h < NH + NKV; h += 8) {
        const float* src;
        const float* w;
        float* dst;
        if (h < NH) {
            src = qkv + (size_t)s * QKV_N + h * HD;
            w = qw;
            dst = gq + ((size_t)h * S_LEN + s) * HD;
        } else {
            int kh = h - NH;
            src = qkv + (size_t)s * QKV_N + NH * HD + kh * HD;
            w = kw;
            dst = gk + ((size_t)kh * S_LEN + s) * HD;
        }
        float4 xv = *(const float4*)(src + dbase);
        float x[4] = {xv.x, xv.y, xv.z, xv.w};
        float ss = x[0]*x[0] + x[1]*x[1] + x[2]*x[2] + x[3]*x[3];
#pragma unroll
        for (int o = 16; o > 0; o >>= 1)
            ss += __shfl_xor_sync(0xffffffffu, ss, o);
        float inv = rsqrtf(ss * (1.0f / HD) + EPS_RMS);
        float4 wv = *(const float4*)(w + dbase);
        float nx[4] = {x[0]*inv*wv.x, x[1]*inv*wv.y, x[2]*inv*wv.z, x[3]*inv*wv.w};

        float out[4];
        const bool lo = (lane < 16);     // d < 64 half
#pragma unroll
        for (int j = 0; j < 4; j++) {
            float partner = __shfl_xor_sync(0xffffffffu, nx[j], 16);
            int i2 = (dbase + j) & (D2 - 1);
            float c = cs[i2], si = sn[i2];
            // lo half: x1*c - x2*s ; hi half: x2*c + x1*s
            out[j] = lo ? (nx[j] * c - partner * si)
                        : (nx[j] * c + partner * si);
        }
        *(float4*)(dst + dbase) = make_float4(out[0], out[1], out[2], out[3]);
    }
}

// ---------------- causal flash attention, fp32 ----------------
// grid = (64 q-tiles, 16 heads), block = 256. Bq = Bk = 64.
// Q/K smem rows padded to 132 floats (float4-aligned; row shift = 4 banks),
// V unpadded (float4 natural), P padded to 65.
#define QK_PITCH 132
#define ATTN_SMEM_FLOATS (64*QK_PITCH + 64*QK_PITCH + 64*128 + 64*65 + 3*64)

__global__ void attn_kernel(const float* __restrict__ gq,
                            const float* __restrict__ gk,
                            const float* __restrict__ gqkv,
                            float* __restrict__ gao) {
    extern __shared__ float sm[];
    float* Qs = sm;                       // 64 x 132
    float* Ks = Qs + 64 * QK_PITCH;       // 64 x 132
    float* Vs = Ks + 64 * QK_PITCH;       // 64 x 128
    float* Ps = Vs + 64 * 128;            // 64 x 65
    float* row_m     = Ps + 64 * 65;
    float* row_l     = row_m + 64;
    float* row_scale = row_l + 64;

    const int h  = blockIdx.y;
    const int qt = (int)gridDim.x - 1 - (int)blockIdx.x;  // heavy tiles first
    const int q0 = qt * 64;
    const int kv = h >> 1;                                // NH/NKV = 2
    const int tid = threadIdx.x;
    const int tx = tid & 15, ty = tid >> 4;

    // load Q tile (float4, padded rows)
    const float* qbase = gq + ((size_t)h * S_LEN + q0) * HD;
    for (int i = tid * 4; i < 64 * 128; i += 1024) {
        int r = i >> 7, d = i & 127;
        *(float4*)(Qs + r * QK_PITCH + d) = *(const float4*)(qbase + r * 128 + d);
    }
    if (tid < 64) { row_m[tid] = -1e30f; row_l[tid] = 0.f; }

    float acc[4][8];
#pragma unroll
    for (int i = 0; i < 4; i++)
#pragma unroll
        for (int j = 0; j < 8; j++) acc[i][j] = 0.f;

    __syncthreads();

    for (int kt = 0; kt <= qt; kt++) {
        const int k0 = kt * 64;

        // --- load K (float4, padded) and V (float4, unpadded) ---
        const float* kbase = gk + ((size_t)kv * S_LEN + k0) * HD;
        for (int i = tid * 4; i < 64 * 128; i += 1024) {
            int r = i >> 7, d = i & 127;
            *(float4*)(Ks + r * QK_PITCH + d) = *(const float4*)(kbase + r * 128 + d);
        }
        const float* vbase = gqkv + (size_t)k0 * QKV_N + NH * HD + NKV * HD + kv * HD;
        for (int i = tid * 4; i < 64 * 128; i += 1024) {
            int r = i >> 7, d = i & 127;
            *(float4*)(Vs + r * 128 + d) = *(const float4*)(vbase + (size_t)r * QKV_N + d);
        }
        __syncthreads();

        // --- scores: 4x4 per thread over 64x64 tile ---
        float sc[4][4];
#pragma unroll
        for (int i = 0; i < 4; i++)
#pragma unroll
            for (int j = 0; j < 4; j++) sc[i][j] = 0.f;

        for (int d = 0; d < 128; d++) {
            float a[4], b[4];
#pragma unroll
            for (int i = 0; i < 4; i++) a[i] = Qs[(ty * 4 + i) * QK_PITCH + d];
#pragma unroll
            for (int j = 0; j < 4; j++) b[j] = Ks[(tx * 4 + j) * QK_PITCH + d];
#pragma unroll
            for (int i = 0; i < 4; i++)
#pragma unroll
                for (int j = 0; j < 4; j++)
                    sc[i][j] += a[i] * b[j];
        }
#pragma unroll
        for (int i = 0; i < 4; i++)
#pragma unroll
            for (int j = 0; j < 4; j++) {
                int r = ty * 4 + i, c = tx * 4 + j;
                float v = sc[i][j] * ATT_SCALE;
                if (k0 + c > q0 + r) v = -1e30f;
                Ps[r * 65 + c] = v;
            }
        __syncthreads();

        // --- online softmax per row (threads 0..63) ---
        if (tid < 64) {
            int r = tid;
            float m_old = row_m[r];
            float mx = m_old;
#pragma unroll 8
            for (int c = 0; c < 64; c++) mx = fmaxf(mx, Ps[r * 65 + c]);
            float l_add = 0.f;
#pragma unroll 8
            for (int c = 0; c < 64; c++) {
                float p = __expf(Ps[r * 65 + c] - mx);
                Ps[r * 65 + c] = p;
                l_add += p;
            }
            float scale = __expf(m_old - mx);
            row_scale[r] = scale;
            row_m[r] = mx;
            row_l[r] = row_l[r] * scale + l_add;
        }
        __syncthreads();

        // --- rescale accumulators, then O += P @ V ---
        float rs[4];
#pragma unroll
        for (int i = 0; i < 4; i++) rs[i] = row_scale[ty * 4 + i];
#pragma unroll
        for (int i = 0; i < 4; i++)
#pragma unroll
            for (int j = 0; j < 8; j++) acc[i][j] *= rs[i];

        for (int c = 0; c < 64; c++) {
            float p[4];
#pragma unroll
            for (int i = 0; i < 4; i++) p[i] = Ps[(ty * 4 + i) * 65 + c];
            float4 v0 = *(const float4*)(Vs + c * 128 + tx * 8);
            float4 v1 = *(const float4*)(Vs + c * 128 + tx * 8 + 4);
#pragma unroll
            for (int i = 0; i < 4; i++) {
                acc[i][0] += p[i] * v0.x;  acc[i][1] += p[i] * v0.y;
                acc[i][2] += p[i] * v0.z;  acc[i][3] += p[i] * v0.w;
                acc[i][4] += p[i] * v1.x;  acc[i][5] += p[i] * v1.y;
                acc[i][6] += p[i] * v1.z;  acc[i][7] += p[i] * v1.w;
            }
        }
        __syncthreads();
    }

    // --- epilogue: divide by l, write [s][h*128+d] ---
    float linv[4];
#pragma unroll
    for (int i = 0; i < 4; i++) linv[i] = 1.f / row_l[ty * 4 + i];
#pragma unroll
    for (int i = 0; i < 4; i++) {
        size_t row = (size_t)(q0 + ty * 4 + i) * (NH * HD) + h * HD + tx * 8;
        *(float4*)&gao[row]     = make_float4(acc[i][0] * linv[i], acc[i][1] * linv[i],
                                              acc[i][2] * linv[i], acc[i][3] * linv[i]);
        *(float4*)&gao[row + 4] = make_float4(acc[i][4] * linv[i], acc[i][5] * linv[i],
                                              acc[i][6] * linv[i], acc[i][7] * linv[i]);
    }
}

// ---------------- launch ----------------
extern "C" void kernel_launch(void* const* d_in, const int* in_sizes, int n_in,
                              void* d_out, int out_size) {
    const float* hidden    = (const float*)d_in[0];   // S x H
    const int*   positions = (const int*)  d_in[1];   // 3 x S
    const float* w_qkv     = (const float*)d_in[2];   // H x 4096
    const float* w_o       = (const float*)d_in[3];   // 2048 x 2048
    const float* q_norm_w  = (const float*)d_in[4];   // 128
    const float* k_norm_w  = (const float*)d_in[5];   // 128
    const float* cache     = (const float*)d_in[6];   // 32768 x 128
    float* out = (float*)d_out;                       // S x H

    float *qkv_p, *q_p, *k_p, *ao_p;
    cudaGetSymbolAddress((void**)&qkv_p, g_qkv);
    cudaGetSymbolAddress((void**)&q_p,   g_q);
    cudaGetSymbolAddress((void**)&k_p,   g_k);
    cudaGetSymbolAddress((void**)&ao_p,  g_ao);

    // 1) QKV projection: (4096x2048) @ (2048x4096)
    gemm128_kernel<<<dim3(QKV_N / 128, S_LEN / 128), 256>>>(
        hidden, w_qkv, qkv_p, S_LEN, QKV_N, HDIM);

    // 2) RMSNorm + mRoPE
    normrope_kernel<<<S_LEN, 256>>>(qkv_p, positions, q_norm_w, k_norm_w,
                                    cache, q_p, k_p);

    // 3) causal attention
    static const size_t attn_smem = ATTN_SMEM_FLOATS * sizeof(float);
    cudaFuncSetAttribute(attn_kernel,
                         cudaFuncAttributeMaxDynamicSharedMemorySize,
                         (int)attn_smem);
    attn_kernel<<<dim3(S_LEN / 64, NH), 256, attn_smem>>>(q_p, k_p, qkv_p, ao_p);

    // 4) output projection: (4096x2048) @ (2048x2048)
    gemm128_kernel<<<dim3(HDIM / 128, S_LEN / 128), 256>>>(
        ao_p, w_o, out, S_LEN, HDIM, HDIM);
}

// round 3
// speedup vs baseline: 2.1865x; 2.1865x over previous
#include <cuda_runtime.h>
#include <cstdint>
#include <cstddef>

// ---------------- problem constants ----------------
#define S_LEN   4096
#define HDIM    2048
#define NH      16
#define NKV     8
#define HD      128
#define QKV_N   4096
#define VOFF    3072                     // NH*HD + NKV*HD
#define ATT_SCALE 0.08838834764831845f   // 128^-0.5
#define EPS_RMS 1e-6f
#define LOG2E   1.4426950408889634f

// ---------------- scratch (device globals: allowed) ----------------
__device__ float g_qkv[(size_t)S_LEN * QKV_N];       // 64 MB
__device__ float g_q[(size_t)NH  * S_LEN * HD];      // 32 MB  [h][s][d]
__device__ float g_k[(size_t)NKV * S_LEN * HD];      // 16 MB  [kv][s][d]
__device__ float g_ao[(size_t)S_LEN * (NH * HD)];    // 32 MB  [s][h*128+d]

// ---------------- helpers ----------------
__device__ __forceinline__ uint32_t f2tf(float x) {
    uint32_t r;
    asm("cvt.rna.tf32.f32 %0, %1;" : "=r"(r) : "f"(x));
    return r;
}

__device__ __forceinline__ void mma8(float c[4], const uint32_t a[4], const uint32_t b[2]) {
    asm volatile(
        "mma.sync.aligned.m16n8k8.row.col.f32.tf32.tf32.f32 "
        "{%0,%1,%2,%3}, {%4,%5,%6,%7}, {%8,%9}, {%0,%1,%2,%3};"
        : "+f"(c[0]), "+f"(c[1]), "+f"(c[2]), "+f"(c[3])
        : "r"(a[0]), "r"(a[1]), "r"(a[2]), "r"(a[3]), "r"(b[0]), "r"(b[1]));
}

// fast exp2 on the FMA pipe (x <= ~0; clamped at -126)
__device__ __forceinline__ float fexp2(float x) {
    x = fmaxf(x, -126.0f);
    int n = __float2int_rn(x);
    float f = x - (float)n;                     // f in [-0.5, 0.5]
    float p = 0.0013333558f;
    p = fmaf(p, f, 0.0096181291f);
    p = fmaf(p, f, 0.0555041087f);
    p = fmaf(p, f, 0.2402265069f);
    p = fmaf(p, f, 0.6931471806f);
    p = fmaf(p, f, 1.0f);
    return p * __int_as_float((n + 127) << 23);
}

// ---------------- tf32 GEMM: C[M,N] = A[M,K] @ B[K,N] ----------------
// 128x128 block tile, BK=32, 256 threads (8 warps), warp tile 64x32.
// smem holds mma-fragment-layout tiles (tf32-converted at staging).
__global__ __launch_bounds__(256, 2)
void gemm_tf32(const float* __restrict__ A, const float* __restrict__ B,
               float* __restrict__ C, int M, int N, int K) {
    __shared__ uint32_t As[4 * 8 * 32 * 4];    // [kstep][mfrag][lane][4]
    __shared__ uint32_t Bs[4 * 16 * 32 * 2];   // [kstep][nfrag][lane][2]
    const int tid  = threadIdx.x;
    const int lane = tid & 31;
    const int warp = tid >> 5;
    const int wm = warp >> 2, wn = warp & 3;   // 2 x 4 warp grid
    const int g = lane >> 2, t = lane & 3;
    const int bm = blockIdx.y * 128, bn = blockIdx.x * 128;

    float acc[4][4][4];
#pragma unroll
    for (int i = 0; i < 4; i++)
#pragma unroll
        for (int j = 0; j < 4; j++)
#pragma unroll
            for (int e = 0; e < 4; e++) acc[i][j][e] = 0.f;

    for (int k0 = 0; k0 < K; k0 += 32) {
        // stage A tile 128x32 -> fragment layout
#pragma unroll
        for (int p = 0; p < 4; p++) {
            int idx = tid + p * 256;
            int r = idx >> 3, c4 = (idx & 7) * 4;
            float4 v = *(const float4*)&A[(size_t)(bm + r) * K + k0 + c4];
            float vv[4] = {v.x, v.y, v.z, v.w};
#pragma unroll
            for (int e = 0; e < 4; e++) {
                int c = c4 + e;
                int ks = c >> 3, mf = r >> 4, mr = r & 15, kc = c & 7;
                As[((ks * 8 + mf) * 32 + (mr & 7) * 4 + (kc & 3)) * 4 +
                   (mr >> 3) + 2 * (kc >> 2)] = f2tf(vv[e]);
            }
        }
        // stage B tile 32x128 -> fragment layout
#pragma unroll
        for (int p = 0; p < 4; p++) {
            int idx = tid + p * 256;
            int r = idx >> 5, c4 = (idx & 31) * 4;
            float4 v = *(const float4*)&B[(size_t)(k0 + r) * N + bn + c4];
            float vv[4] = {v.x, v.y, v.z, v.w};
#pragma unroll
            for (int e = 0; e < 4; e++) {
                int c = c4 + e;
                Bs[(((r >> 3) * 16 + (c >> 3)) * 32 + (c & 7) * 4 + (r & 3)) * 2 +
                   ((r & 7) >> 2)] = f2tf(vv[e]);
            }
        }
        __syncthreads();

#pragma unroll
        for (int ks = 0; ks < 4; ks++) {
            uint32_t a[4][4], b[4][2];
#pragma unroll
            for (int i = 0; i < 4; i++) {
                uint4 av = *(const uint4*)&As[((ks * 8 + wm * 4 + i) * 32 + lane) * 4];
                a[i][0] = av.x; a[i][1] = av.y; a[i][2] = av.z; a[i][3] = av.w;
            }
#pragma unroll
            for (int j = 0; j < 4; j++) {
                uint2 bv = *(const uint2*)&Bs[((ks * 16 + wn * 4 + j) * 32 + lane) * 2];
                b[j][0] = bv.x; b[j][1] = bv.y;
            }
#pragma unroll
            for (int i = 0; i < 4; i++)
#pragma unroll
                for (int j = 0; j < 4; j++)
                    mma8(acc[i][j], a[i], b[j]);
        }
        __syncthreads();
    }

#pragma unroll
    for (int i = 0; i < 4; i++)
#pragma unroll
        for (int j = 0; j < 4; j++) {
            int row0 = bm + wm * 64 + i * 16 + g;
            int col  = bn + wn * 32 + j * 8 + 2 * t;
            *(float2*)&C[(size_t)row0 * N + col]       = make_float2(acc[i][j][0], acc[i][j][1]);
            *(float2*)&C[(size_t)(row0 + 8) * N + col] = make_float2(acc[i][j][2], acc[i][j][3]);
        }
}

// ---------------- RMSNorm + mRoPE (unchanged) ----------------
__global__ void normrope_kernel(const float* __restrict__ qkv,
                                const int*   __restrict__ positions,
                                const float* __restrict__ qw,
                                const float* __restrict__ kw,
                                const float* __restrict__ cache,
                                float* __restrict__ gq,
                                float* __restrict__ gk) {
    const int s = blockIdx.x;
    __shared__ float cs[64], sn[64];
    const int tid = threadIdx.x;

    if (tid < 64) {
        int i = tid;
        int m3 = i % 3;
        int sec = (i < 60) ? ((m3 == 1) ? 1 : ((m3 == 2) ? 2 : 0)) : 0;
        int pos = positions[sec * S_LEN + s];
        cs[i] = cache[(size_t)pos * HD + i];
        sn[i] = cache[(size_t)pos * HD + 64 + i];
    }
    __syncthreads();

    const int warp = tid >> 5;
    const int lane = tid & 31;
    const int dbase = lane * 4;

    for (int h = warp; h < NH + NKV; h += 8) {
        const float* src;
        const float* w;
        float* dst;
        if (h < NH) {
            src = qkv + (size_t)s * QKV_N + h * HD;
            w = qw;
            dst = gq + ((size_t)h * S_LEN + s) * HD;
        } else {
            int kh = h - NH;
            src = qkv + (size_t)s * QKV_N + NH * HD + kh * HD;
            w = kw;
            dst = gk + ((size_t)kh * S_LEN + s) * HD;
        }
        float4 xv = *(const float4*)(src + dbase);
        float x[4] = {xv.x, xv.y, xv.z, xv.w};
        float ss = x[0]*x[0] + x[1]*x[1] + x[2]*x[2] + x[3]*x[3];
#pragma unroll
        for (int o = 16; o > 0; o >>= 1)
            ss += __shfl_xor_sync(0xffffffffu, ss, o);
        float inv = rsqrtf(ss * (1.0f / HD) + EPS_RMS);
        float4 wv = *(const float4*)(w + dbase);
        float nx[4] = {x[0]*inv*wv.x, x[1]*inv*wv.y, x[2]*inv*wv.z, x[3]*inv*wv.w};

        float out[4];
        const bool lo = (lane < 16);
#pragma unroll
        for (int j = 0; j < 4; j++) {
            float partner = __shfl_xor_sync(0xffffffffu, nx[j], 16);
            int i2 = (dbase + j) & 63;
            float c = cs[i2], si = sn[i2];
            out[j] = lo ? (nx[j] * c - partner * si)
                        : (nx[j] * c + partner * si);
        }
        *(float4*)(dst + dbase) = make_float4(out[0], out[1], out[2], out[3]);
    }
}

// ---------------- tf32 flash attention ----------------
// Bq=128, Bk=64. 256 threads (8 warps); warp w owns rows w*16..w*16+15,
// so online softmax is warp-local (quad shfl reductions).
// Q fragments live in registers; K/V/P staged in smem fragment layout.
#define ATTN_SMEM_BYTES (3 * 8192 * 4)   // Ks + Vs + Ps (Qlin aliases: 67584 < 98304)

__global__ __launch_bounds__(256, 1)
void attn_tf32(const float* __restrict__ gq, const float* __restrict__ gk,
               const float* __restrict__ gqkv, float* __restrict__ gao) {
    extern __shared__ uint32_t smu[];
    uint32_t* Ks = smu;              // [16][8][32][2] = 8192 u32
    uint32_t* Vs = smu + 8192;       // [8][16][32][2] = 8192 u32
    uint32_t* Ps = smu + 16384;      // [8][8][32][4]  = 8192 u32
    float* Qlin = (float*)smu;       // [128][132] during prologue (aliased)

    const int tid  = threadIdx.x;
    const int lane = tid & 31;
    const int w    = tid >> 5;
    const int g = lane >> 2, t = lane & 3;
    const int h  = blockIdx.y;
    const int qt = (int)gridDim.x - 1 - (int)blockIdx.x;   // heavy tiles first
    const int q0 = qt * 128;
    const int kv = h >> 1;

    // ---- prologue: Q tile -> smem linear -> register fragments ----
    const float* qbase = gq + ((size_t)h * S_LEN + q0) * HD;
#pragma unroll
    for (int p = 0; p < 16; p++) {
        int idx = tid + p * 256;
        int r = idx >> 5, c4 = (idx & 31) * 4;
        *(float4*)&Qlin[r * 132 + c4] = *(const float4*)&qbase[(size_t)r * HD + c4];
    }
    __syncthreads();

    uint32_t aq[16][4];
    {
        int r0 = w * 16 + g;
#pragma unroll
        for (int ks = 0; ks < 16; ks++) {
            aq[ks][0] = f2tf(Qlin[r0 * 132 + ks * 8 + t]);
            aq[ks][1] = f2tf(Qlin[(r0 + 8) * 132 + ks * 8 + t]);
            aq[ks][2] = f2tf(Qlin[r0 * 132 + ks * 8 + t + 4]);
            aq[ks][3] = f2tf(Qlin[(r0 + 8) * 132 + ks * 8 + t + 4]);
        }
    }

    float oacc[16][4];
#pragma unroll
    for (int j = 0; j < 16; j++)
#pragma unroll
        for (int e = 0; e < 4; e++) oacc[j][e] = 0.f;
    float m2a = -1e30f, m2b = -1e30f;
    float la = 0.f, lb = 0.f;

    const int r0g = q0 + w * 16 + g;
    const float CC = ATT_SCALE * LOG2E;
    const int nkt = 2 * qt + 2;

#pragma unroll 1
    for (int kt = 0; kt < nkt; kt++) {
        const int k0 = kt * 64;
        __syncthreads();   // protect Ks/Vs (and Qlin on first iter)

        // ---- stage K,V (64 rows x 128 dims) into fragment layout ----
        const float* kbase = gk + ((size_t)kv * S_LEN + k0) * HD;
        const float* vbase = gqkv + (size_t)k0 * QKV_N + VOFF + kv * HD;
#pragma unroll
        for (int p = 0; p < 8; p++) {
            int idx = tid + p * 256;
            int r = idx >> 5, d4 = (idx & 31) * 4;
            float4 vk = *(const float4*)&kbase[(size_t)r * HD + d4];
            float4 vv = *(const float4*)&vbase[(size_t)r * QKV_N + d4];
            float ak[4] = {vk.x, vk.y, vk.z, vk.w};
            float av[4] = {vv.x, vv.y, vv.z, vv.w};
#pragma unroll
            for (int e = 0; e < 4; e++) {
                int d = d4 + e;
                // K as B-operand of QK^T: k-dim = d, n-dim = r
                Ks[(((d >> 3) * 8 + (r >> 3)) * 32 + (r & 7) * 4 + (d & 3)) * 2 +
                   ((d & 7) >> 2)] = f2tf(ak[e]);
                // V as B-operand of PV: k-dim = r, n-dim = d
                Vs[(((r >> 3) * 16 + (d >> 3)) * 32 + (d & 7) * 4 + (r & 3)) * 2 +
                   ((r & 7) >> 2)] = f2tf(av[e]);
            }
        }
        __syncthreads();

        // ---- scores: 16 rows x 64 cols per warp ----
        float sc[8][4];
#pragma unroll
        for (int j = 0; j < 8; j++)
#pragma unroll
            for (int e = 0; e < 4; e++) sc[j][e] = 0.f;
#pragma unroll
        for (int ks = 0; ks < 16; ks++) {
#pragma unroll
            for (int j = 0; j < 8; j++) {
                uint2 bv = *(const uint2*)&Ks[((ks * 8 + j) * 32 + lane) * 2];
                uint32_t b[2] = {bv.x, bv.y};
                mma8(sc[j], aq[ks], b);
            }
        }

        // ---- scale (base-2) + causal mask ----
#pragma unroll
        for (int j = 0; j < 8; j++) {
            int c0 = k0 + j * 8 + 2 * t;
            sc[j][0] = (c0     > r0g)     ? -1e30f : sc[j][0] * CC;
            sc[j][1] = (c0 + 1 > r0g)     ? -1e30f : sc[j][1] * CC;
            sc[j][2] = (c0     > r0g + 8) ? -1e30f : sc[j][2] * CC;
            sc[j][3] = (c0 + 1 > r0g + 8) ? -1e30f : sc[j][3] * CC;
        }

        // ---- online softmax (warp-local, quad reduction) ----
        float mx0 = -1e30f, mx1 = -1e30f;
#pragma unroll
        for (int j = 0; j < 8; j++) {
            mx0 = fmaxf(mx0, fmaxf(sc[j][0], sc[j][1]));
            mx1 = fmaxf(mx1, fmaxf(sc[j][2], sc[j][3]));
        }
        mx0 = fmaxf(mx0, __shfl_xor_sync(0xffffffffu, mx0, 1));
        mx0 = fmaxf(mx0, __shfl_xor_sync(0xffffffffu, mx0, 2));
        mx1 = fmaxf(mx1, __shfl_xor_sync(0xffffffffu, mx1, 1));
        mx1 = fmaxf(mx1, __shfl_xor_sync(0xffffffffu, mx1, 2));
        float mn0 = fmaxf(m2a, mx0), mn1 = fmaxf(m2b, mx1);
        float f0 = fexp2(m2a - mn0), f1 = fexp2(m2b - mn1);
        m2a = mn0; m2b = mn1;

        float s0 = 0.f, s1 = 0.f;
#pragma unroll
        for (int j = 0; j < 8; j++) {
            sc[j][0] = fexp2(sc[j][0] - mn0);
            sc[j][1] = fexp2(sc[j][1] - mn0);
            sc[j][2] = fexp2(sc[j][2] - mn1);
            sc[j][3] = fexp2(sc[j][3] - mn1);
            s0 += sc[j][0] + sc[j][1];
            s1 += sc[j][2] + sc[j][3];
        }
        s0 += __shfl_xor_sync(0xffffffffu, s0, 1);
        s0 += __shfl_xor_sync(0xffffffffu, s0, 2);
        s1 += __shfl_xor_sync(0xffffffffu, s1, 1);
        s1 += __shfl_xor_sync(0xffffffffu, s1, 2);
        la = la * f0 + s0;
        lb = lb * f1 + s1;

#pragma unroll
        for (int j = 0; j < 16; j++) {
            oacc[j][0] *= f0; oacc[j][1] *= f0;
            oacc[j][2] *= f1; oacc[j][3] *= f1;
        }

        // ---- store P as A-fragments (warp-private region) ----
        {
            int l0 = g * 4 + ((2 * t) & 3);
            int l1 = g * 4 + ((2 * t + 1) & 3);
            int shi = 2 * (t >> 1);
#pragma unroll
            for (int j = 0; j < 8; j++) {
                uint32_t base = (uint32_t)((j * 8 + w) * 32) * 4;
                Ps[base + l0 * 4 + shi]     = f2tf(sc[j][0]);
                Ps[base + l1 * 4 + shi]     = f2tf(sc[j][1]);
                Ps[base + l0 * 4 + shi + 1] = f2tf(sc[j][2]);
                Ps[base + l1 * 4 + shi + 1] = f2tf(sc[j][3]);
            }
        }
        __syncwarp();

        // ---- O += P @ V ----
#pragma unroll
        for (int kk = 0; kk < 8; kk++) {
            uint4 av = *(const uint4*)&Ps[((kk * 8 + w) * 32 + lane) * 4];
            uint32_t a[4] = {av.x, av.y, av.z, av.w};
#pragma unroll
            for (int j = 0; j < 16; j++) {
                uint2 bv = *(const uint2*)&Vs[((kk * 16 + j) * 32 + lane) * 2];
                uint32_t b[2] = {bv.x, bv.y};
                mma8(oacc[j], a, b);
            }
        }
    }

    // ---- epilogue ----
    float inv0 = 1.f / la, inv1 = 1.f / lb;
    int row0 = q0 + w * 16 + g;
#pragma unroll
    for (int j = 0; j < 16; j++) {
        int col = h * HD + j * 8 + 2 * t;
        *(float2*)&gao[(size_t)row0 * HDIM + col] =
            make_float2(oacc[j][0] * inv0, oacc[j][1] * inv0);
        *(float2*)&gao[(size_t)(row0 + 8) * HDIM + col] =
            make_float2(oacc[j][2] * inv1, oacc[j][3] * inv1);
    }
}

// ---------------- launch ----------------
extern "C" void kernel_launch(void* const* d_in, const int* in_sizes, int n_in,
                              void* d_out, int out_size) {
    const float* hidden    = (const float*)d_in[0];
    const int*   positions = (const int*)  d_in[1];
    const float* w_qkv     = (const float*)d_in[2];
    const float* w_o       = (const float*)d_in[3];
    const float* q_norm_w  = (const float*)d_in[4];
    const float* k_norm_w  = (const float*)d_in[5];
    const float* cache     = (const float*)d_in[6];
    float* out = (float*)d_out;

    float *qkv_p, *q_p, *k_p, *ao_p;
    cudaGetSymbolAddress((void**)&qkv_p, g_qkv);
    cudaGetSymbolAddress((void**)&q_p,   g_q);
    cudaGetSymbolAddress((void**)&k_p,   g_k);
    cudaGetSymbolAddress((void**)&ao_p,  g_ao);

    // 1) QKV projection (tf32 tensor cores)
    gemm_tf32<<<dim3(QKV_N / 128, S_LEN / 128), 256>>>(
        hidden, w_qkv, qkv_p, S_LEN, QKV_N, HDIM);

    // 2) RMSNorm + mRoPE
    normrope_kernel<<<S_LEN, 256>>>(qkv_p, positions, q_norm_w, k_norm_w,
                                    cache, q_p, k_p);

    // 3) causal flash attention (tf32 tensor cores)
    cudaFuncSetAttribute(attn_tf32,
                         cudaFuncAttributeMaxDynamicSharedMemorySize,
                         ATTN_SMEM_BYTES);
    attn_tf32<<<dim3(S_LEN / 128, NH), 256, ATTN_SMEM_BYTES>>>(
        q_p, k_p, qkv_p, ao_p);

    // 4) output projection (tf32 tensor cores)
    gemm_tf32<<<dim3(HDIM / 128, S_LEN / 128), 256>>>(
        ao_p, w_o, out, S_LEN, HDIM, HDIM);
}

// round 4
// speedup vs baseline: 7.6358x; 3.4923x over previous
#include <cuda_runtime.h>
#include <cstdint>
#include <cstddef>

// ---------------- problem constants ----------------
#define S_LEN   4096
#define HDIM    2048
#define NH      16
#define NKV     8
#define HD      128
#define QKV_N   4096
#define VOFF    3072                     // NH*HD + NKV*HD
#define ATT_SCALE 0.08838834764831845f   // 128^-0.5
#define EPS_RMS 1e-6f
#define LOG2E   1.4426950408889634f

// ---------------- scratch (device globals: allowed) ----------------
__device__ float g_qkv[(size_t)S_LEN * QKV_N];       // 64 MB
__device__ float g_q[(size_t)NH  * S_LEN * HD];      // 32 MB  [h][s][d]
__device__ float g_k[(size_t)NKV * S_LEN * HD];      // 16 MB  [kv][s][d]
__device__ float g_ao[(size_t)S_LEN * (NH * HD)];    // 32 MB  [s][h*128+d]
// fragment-layout (tf32) scratch, reused across the two GEMMs
__device__ uint32_t g_af[(size_t)32 * 64 * 4096];    // 32 MB  A tiles [mb][kb][4096]
__device__ uint32_t g_bf[(size_t)64 * 32 * 4096];    // 32 MB  B tiles [kb][nb][4096]
__device__ uint32_t g_kf[(size_t)NKV * 64 * 8192];   // 16 MB  K tiles [kv][kt][8192]
__device__ uint32_t g_vf[(size_t)NKV * 64 * 8192];   // 16 MB  V tiles [kv][kt][8192]

// ---------------- helpers ----------------
__device__ __forceinline__ uint32_t f2tf(float x) {
    uint32_t r;
    asm("cvt.rna.tf32.f32 %0, %1;" : "=r"(r) : "f"(x));
    return r;
}

__device__ __forceinline__ void mma8(float c[4], const uint32_t a[4], const uint32_t b[2]) {
    asm volatile(
        "mma.sync.aligned.m16n8k8.row.col.f32.tf32.tf32.f32 "
        "{%0,%1,%2,%3}, {%4,%5,%6,%7}, {%8,%9}, {%0,%1,%2,%3};"
        : "+f"(c[0]), "+f"(c[1]), "+f"(c[2]), "+f"(c[3])
        : "r"(a[0]), "r"(a[1]), "r"(a[2]), "r"(a[3]), "r"(b[0]), "r"(b[1]));
}

__device__ __forceinline__ void cpasync16(uint32_t saddr, const void* gptr) {
    asm volatile("cp.async.cg.shared.global [%0], [%1], 16;"
                 :: "r"(saddr), "l"(gptr));
}
#define CP_COMMIT() asm volatile("cp.async.commit_group;")
#define CP_WAIT1()  asm volatile("cp.async.wait_group 1;")

// fast exp2 on the FMA pipe
__device__ __forceinline__ float fexp2(float x) {
    x = fmaxf(x, -126.0f);
    int n = __float2int_rn(x);
    float f = x - (float)n;
    float p = 0.0013333558f;
    p = fmaf(p, f, 0.0096181291f);
    p = fmaf(p, f, 0.0555041087f);
    p = fmaf(p, f, 0.2402265069f);
    p = fmaf(p, f, 0.6931471806f);
    p = fmaf(p, f, 1.0f);
    return p * __int_as_float((n + 127) << 23);
}

// ================= permute kernels (f32 gmem -> tf32 fragment-layout gmem) ====

// A tiles: [M][K] row-major -> [mb][kb][4096], layout o = frag*128 + slot*4 + rem
// frag = (c>>3)*8 + (r>>4); slot = (r&7)*4 + (c&3); rem = ((r>>3)&1) + 2*((c>>2)&1)
__global__ void permA_kernel(const float* __restrict__ A, uint32_t* __restrict__ out,
                             int M, int K) {
    __shared__ float t[128 * 36];
    const int kb = blockIdx.x, mb = blockIdx.y, nkb = gridDim.x;
    const int tid = threadIdx.x;
#pragma unroll
    for (int p = 0; p < 4; p++) {
        int idx = tid + p * 256;
        int r = idx >> 3, c4 = (idx & 7) * 4;
        float4 v = *(const float4*)&A[(size_t)(mb * 128 + r) * K + kb * 32 + c4];
        *(float4*)&t[r * 36 + c4] = v;
    }
    __syncthreads();
    uint32_t* dst = out + ((size_t)mb * nkb + kb) * 4096;
#pragma unroll
    for (int q = 0; q < 4; q++) {
        int o = q * 1024 + tid * 4;
        int slot = (o >> 2) & 31, frag = o >> 7;
        int rb = (frag & 7) * 16 + (slot >> 2);   // + rem&1 * 8
        int cb = (frag >> 3) * 8 + (slot & 3);    // + (rem>>1) * 4
        uint4 u;
        u.x = f2tf(t[rb * 36 + cb]);
        u.y = f2tf(t[(rb + 8) * 36 + cb]);
        u.z = f2tf(t[rb * 36 + cb + 4]);
        u.w = f2tf(t[(rb + 8) * 36 + cb + 4]);
        *(uint4*)&dst[o] = u;
    }
}

// B tiles: [K][N] row-major -> [kb][nb][4096], o = f*64 + slot*2 + half
// f = (r>>3)*16 + (c>>3); slot = (c&7)*4 + (r&3); half = (r>>2)&1
__global__ void permB_kernel(const float* __restrict__ B, uint32_t* __restrict__ out,
                             int K, int N) {
    __shared__ float t[32 * 132];
    const int nb = blockIdx.x, kb = blockIdx.y, nnb = gridDim.x;
    const int tid = threadIdx.x;
#pragma unroll
    for (int p = 0; p < 4; p++) {
        int idx = tid + p * 256;
        int r = idx >> 5, c4 = (idx & 31) * 4;
        float4 v = *(const float4*)&B[(size_t)(kb * 32 + r) * N + nb * 128 + c4];
        *(float4*)&t[r * 132 + c4] = v;
    }
    __syncthreads();
    uint32_t* dst = out + ((size_t)kb * nnb + nb) * 4096;
#pragma unroll
    for (int q = 0; q < 4; q++) {
        int o = q * 1024 + tid * 4;
        uint32_t u[4];
#pragma unroll
        for (int e = 0; e < 4; e++) {
            int oe = o + e;
            int half = oe & 1, slot = (oe >> 1) & 31, f = oe >> 6;
            int r = (f >> 4) * 8 + half * 4 + (slot & 3);
            int c = (f & 15) * 8 + (slot >> 2);
            u[e] = f2tf(t[r * 132 + c]);
        }
        *(uint4*)&dst[o] = make_uint4(u[0], u[1], u[2], u[3]);
    }
}

// K tiles: g_k [kv][s][d] -> [kv][kt][8192], o = f*64 + slot*2 + half
// f = (d>>3)*8 + (r>>3); slot = (r&7)*4 + (d&3); half = (d>>2)&1
__global__ void permK_kernel(const float* __restrict__ gk, uint32_t* __restrict__ out) {
    __shared__ float t[64 * 132];
    const int kt = blockIdx.x, kv = blockIdx.y;
    const int tid = threadIdx.x;
#pragma unroll
    for (int p = 0; p < 8; p++) {
        int idx = tid + p * 256;
        int r = idx >> 5, c4 = (idx & 31) * 4;
        float4 v = *(const float4*)&gk[((size_t)kv * S_LEN + kt * 64 + r) * HD + c4];
        *(float4*)&t[r * 132 + c4] = v;
    }
    __syncthreads();
    uint32_t* dst = out + ((size_t)kv * (S_LEN / 64) + kt) * 8192;
#pragma unroll
    for (int q = 0; q < 8; q++) {
        int o = q * 1024 + tid * 4;
        uint32_t u[4];
#pragma unroll
        for (int e = 0; e < 4; e++) {
            int oe = o + e;
            int half = oe & 1, slot = (oe >> 1) & 31, f = oe >> 6;
            int r = (f & 7) * 8 + (slot >> 2);
            int d = (f >> 3) * 8 + half * 4 + (slot & 3);
            u[e] = f2tf(t[r * 132 + d]);
        }
        *(uint4*)&dst[o] = make_uint4(u[0], u[1], u[2], u[3]);
    }
}

// V tiles: g_qkv strided -> [kv][kt][8192], o = f*64 + slot*2 + half
// f = (r>>3)*16 + (d>>3); slot = (d&7)*4 + (r&3); half = (r>>2)&1
__global__ void permV_kernel(const float* __restrict__ gqkv, uint32_t* __restrict__ out) {
    __shared__ float t[64 * 132];
    const int kt = blockIdx.x, kv = blockIdx.y;
    const int tid = threadIdx.x;
#pragma unroll
    for (int p = 0; p < 8; p++) {
        int idx = tid + p * 256;
        int r = idx >> 5, c4 = (idx & 31) * 4;
        float4 v = *(const float4*)&gqkv[(size_t)(kt * 64 + r) * QKV_N + VOFF + kv * HD + c4];
        *(float4*)&t[r * 132 + c4] = v;
    }
    __syncthreads();
    uint32_t* dst = out + ((size_t)kv * (S_LEN / 64) + kt) * 8192;
#pragma unroll
    for (int q = 0; q < 8; q++) {
        int o = q * 1024 + tid * 4;
        uint32_t u[4];
#pragma unroll
        for (int e = 0; e < 4; e++) {
            int oe = o + e;
            int half = oe & 1, slot = (oe >> 1) & 31, f = oe >> 6;
            int d = (f & 15) * 8 + (slot >> 2);
            int r = (f >> 4) * 8 + half * 4 + (slot & 3);
            u[e] = f2tf(t[r * 132 + d]);
        }
        *(uint4*)&dst[o] = make_uint4(u[0], u[1], u[2], u[3]);
    }
}

// ================= tf32 GEMM on pre-permuted tiles =================
// 128x128 block tile, BK=32, 256 threads, warp tile 64x32.
// 3-stage cp.async pipeline; per stage: A tile 16KB + B tile 16KB contiguous.
#define GEMM_SMEM_BYTES (3 * 8192 * 4)

__global__ __launch_bounds__(256, 2)
void gemm_pre(const uint32_t* __restrict__ Af, const uint32_t* __restrict__ Bf,
              float* __restrict__ C, int M, int N, int K) {
    extern __shared__ uint32_t smg[];
    const int tid  = threadIdx.x;
    const int lane = tid & 31;
    const int warp = tid >> 5;
    const int wm = warp >> 2, wn = warp & 3;
    const int g = lane >> 2, t = lane & 3;
    const int mb = blockIdx.y, nb = blockIdx.x;
    const int nkb = K / 32, nnb = N / 128;
    const uint32_t sbase = (uint32_t)__cvta_generic_to_shared(smg);
    const uint32_t* Asrc = Af + (size_t)mb * nkb * 4096;

    auto issue = [&](int kb, int st) {
        uint32_t dst = sbase + (uint32_t)st * 32768;
        const uint32_t* a = Asrc + (size_t)kb * 4096;
        const uint32_t* b = Bf + ((size_t)kb * nnb + nb) * 4096;
#pragma unroll
        for (int p = 0; p < 4; p++) {
            int i = tid + p * 256;
            cpasync16(dst + i * 16, a + i * 4);
            cpasync16(dst + 16384 + i * 16, b + i * 4);
        }
    };

    issue(0, 0); CP_COMMIT();
    issue(1, 1); CP_COMMIT();

    float acc[4][4][4];
#pragma unroll
    for (int i = 0; i < 4; i++)
#pragma unroll
        for (int j = 0; j < 4; j++)
#pragma unroll
            for (int e = 0; e < 4; e++) acc[i][j][e] = 0.f;

    for (int kb = 0; kb < nkb; kb++) {
        CP_WAIT1();
        __syncthreads();
        if (kb + 2 < nkb) issue(kb + 2, (kb + 2) % 3);
        CP_COMMIT();

        const uint32_t* As = smg + (kb % 3) * 8192;
        const uint32_t* Bs = As + 4096;
#pragma unroll
        for (int ks = 0; ks < 4; ks++) {
            uint32_t a[4][4], b[4][2];
#pragma unroll
            for (int i = 0; i < 4; i++) {
                uint4 av = *(const uint4*)&As[((ks * 8 + wm * 4 + i) * 32 + lane) * 4];
                a[i][0] = av.x; a[i][1] = av.y; a[i][2] = av.z; a[i][3] = av.w;
            }
#pragma unroll
            for (int j = 0; j < 4; j++) {
                uint2 bv = *(const uint2*)&Bs[((ks * 16 + wn * 4 + j) * 32 + lane) * 2];
                b[j][0] = bv.x; b[j][1] = bv.y;
            }
#pragma unroll
            for (int i = 0; i < 4; i++)
#pragma unroll
                for (int j = 0; j < 4; j++)
                    mma8(acc[i][j], a[i], b[j]);
        }
    }

#pragma unroll
    for (int i = 0; i < 4; i++)
#pragma unroll
        for (int j = 0; j < 4; j++) {
            int row0 = mb * 128 + wm * 64 + i * 16 + g;
            int col  = nb * 128 + wn * 32 + j * 8 + 2 * t;
            *(float2*)&C[(size_t)row0 * N + col]       = make_float2(acc[i][j][0], acc[i][j][1]);
            *(float2*)&C[(size_t)(row0 + 8) * N + col] = make_float2(acc[i][j][2], acc[i][j][3]);
        }
}

// ---------------- RMSNorm + mRoPE (unchanged) ----------------
__global__ void normrope_kernel(const float* __restrict__ qkv,
                                const int*   __restrict__ positions,
                                const float* __restrict__ qw,
                                const float* __restrict__ kw,
                                const float* __restrict__ cache,
                                float* __restrict__ gq,
                                float* __restrict__ gk) {
    const int s = blockIdx.x;
    __shared__ float cs[64], sn[64];
    const int tid = threadIdx.x;

    if (tid < 64) {
        int i = tid;
        int m3 = i % 3;
        int sec = (i < 60) ? ((m3 == 1) ? 1 : ((m3 == 2) ? 2 : 0)) : 0;
        int pos = positions[sec * S_LEN + s];
        cs[i] = cache[(size_t)pos * HD + i];
        sn[i] = cache[(size_t)pos * HD + 64 + i];
    }
    __syncthreads();

    const int warp = tid >> 5;
    const int lane = tid & 31;
    const int dbase = lane * 4;

    for (int h = warp; h < NH + NKV; h += 8) {
        const float* src;
        const float* w;
        float* dst;
        if (h < NH) {
            src = qkv + (size_t)s * QKV_N + h * HD;
            w = qw;
            dst = gq + ((size_t)h * S_LEN + s) * HD;
        } else {
            int kh = h - NH;
            src = qkv + (size_t)s * QKV_N + NH * HD + kh * HD;
            w = kw;
            dst = gk + ((size_t)kh * S_LEN + s) * HD;
        }
        float4 xv = *(const float4*)(src + dbase);
        float x[4] = {xv.x, xv.y, xv.z, xv.w};
        float ss = x[0]*x[0] + x[1]*x[1] + x[2]*x[2] + x[3]*x[3];
#pragma unroll
        for (int o = 16; o > 0; o >>= 1)
            ss += __shfl_xor_sync(0xffffffffu, ss, o);
        float inv = rsqrtf(ss * (1.0f / HD) + EPS_RMS);
        float4 wv = *(const float4*)(w + dbase);
        float nx[4] = {x[0]*inv*wv.x, x[1]*inv*wv.y, x[2]*inv*wv.z, x[3]*inv*wv.w};

        float out[4];
        const bool lo = (lane < 16);
#pragma unroll
        for (int j = 0; j < 4; j++) {
            float partner = __shfl_xor_sync(0xffffffffu, nx[j], 16);
            int i2 = (dbase + j) & 63;
            float c = cs[i2], si = sn[i2];
            out[j] = lo ? (nx[j] * c - partner * si)
                        : (nx[j] * c + partner * si);
        }
        *(float4*)(dst + dbase) = make_float4(out[0], out[1], out[2], out[3]);
    }
}

// ================= tf32 flash attention on pre-permuted K/V =================
// Bq=128, Bk=64, 256 threads; warp w owns rows w*16..w*16+15 (warp-local softmax).
// 2-stage cp.async pipeline of 64KB (Ks 32KB + Vs 32KB) fragment tiles.
// smem: stages [0,131072) bytes, Ps at [131072,163840). Qlin aliases stages.
#define ATTN_SMEM_BYTES ((32768 + 8192) * 4)

__global__ __launch_bounds__(256, 1)
void attn_pre(const float* __restrict__ gq, const uint32_t* __restrict__ Kf,
              const uint32_t* __restrict__ Vf, float* __restrict__ gao) {
    extern __shared__ uint32_t smu[];
    uint32_t* Ps = smu + 32768;          // [8][8][32][4]
    float* Qlin = (float*)smu;           // [128][132] prologue only

    const int tid  = threadIdx.x;
    const int lane = tid & 31;
    const int w    = tid >> 5;
    const int g = lane >> 2, t = lane & 3;
    const int h  = blockIdx.y;
    const int qt = (int)gridDim.x - 1 - (int)blockIdx.x;
    const int q0 = qt * 128;
    const int kv = h >> 1;
    const int nkt = 2 * qt + 2;
    const uint32_t sbase = (uint32_t)__cvta_generic_to_shared(smu);

    // ---- prologue: Q tile -> smem linear -> register fragments ----
    const float* qbase = gq + ((size_t)h * S_LEN + q0) * HD;
#pragma unroll
    for (int p = 0; p < 16; p++) {
        int idx = tid + p * 256;
        int r = idx >> 5, c4 = (idx & 31) * 4;
        *(float4*)&Qlin[r * 132 + c4] = *(const float4*)&qbase[(size_t)r * HD + c4];
    }
    __syncthreads();

    uint32_t aq[16][4];
    {
        int r0 = w * 16 + g;
#pragma unroll
        for (int ks = 0; ks < 16; ks++) {
            aq[ks][0] = f2tf(Qlin[r0 * 132 + ks * 8 + t]);
            aq[ks][1] = f2tf(Qlin[(r0 + 8) * 132 + ks * 8 + t]);
            aq[ks][2] = f2tf(Qlin[r0 * 132 + ks * 8 + t + 4]);
            aq[ks][3] = f2tf(Qlin[(r0 + 8) * 132 + ks * 8 + t + 4]);
        }
    }
    __syncthreads();   // everyone done reading Qlin before cp.async clobbers it

    const uint32_t* Ksrc = Kf + (size_t)kv * (S_LEN / 64) * 8192;
    const uint32_t* Vsrc = Vf + (size_t)kv * (S_LEN / 64) * 8192;
    auto issue = [&](int kt, int st) {
        if (kt < nkt) {
            uint32_t dst = sbase + (uint32_t)st * 65536;
            const uint32_t* kp = Ksrc + (size_t)kt * 8192;
            const uint32_t* vp = Vsrc + (size_t)kt * 8192;
#pragma unroll
            for (int p = 0; p < 8; p++) {
                int i = tid + p * 256;
                cpasync16(dst + i * 16, kp + i * 4);
                cpasync16(dst + 32768 + i * 16, vp + i * 4);
            }
        }
    };
    issue(0, 0); CP_COMMIT();
    issue(1, 1); CP_COMMIT();

    float oacc[16][4];
#pragma unroll
    for (int j = 0; j < 16; j++)
#pragma unroll
        for (int e = 0; e < 4; e++) oacc[j][e] = 0.f;
    float m2a = -1e30f, m2b = -1e30f;
    float la = 0.f, lb = 0.f;

    const int r0g = q0 + w * 16 + g;
    const float CC = ATT_SCALE * LOG2E;

#pragma unroll 1
    for (int kt = 0; kt < nkt; kt++) {
        const int k0 = kt * 64;
        CP_WAIT1();
        __syncthreads();
        const uint32_t* Ks = smu + (kt & 1) * 16384;
        const uint32_t* Vs = Ks + 8192;

        // ---- scores: 16 rows x 64 cols per warp ----
        float sc[8][4];
#pragma unroll
        for (int j = 0; j < 8; j++)
#pragma unroll
            for (int e = 0; e < 4; e++) sc[j][e] = 0.f;
#pragma unroll
        for (int ks = 0; ks < 16; ks++) {
#pragma unroll
            for (int j = 0; j < 8; j++) {
                uint2 bv = *(const uint2*)&Ks[((ks * 8 + j) * 32 + lane) * 2];
                uint32_t b[2] = {bv.x, bv.y};
                mma8(sc[j], aq[ks], b);
            }
        }

        // ---- scale (base-2) + causal mask ----
#pragma unroll
        for (int j = 0; j < 8; j++) {
            int c0 = k0 + j * 8 + 2 * t;
            sc[j][0] = (c0     > r0g)     ? -1e30f : sc[j][0] * CC;
            sc[j][1] = (c0 + 1 > r0g)     ? -1e30f : sc[j][1] * CC;
            sc[j][2] = (c0     > r0g + 8) ? -1e30f : sc[j][2] * CC;
            sc[j][3] = (c0 + 1 > r0g + 8) ? -1e30f : sc[j][3] * CC;
        }

        // ---- online softmax (warp-local, quad reduction) ----
        float mx0 = -1e30f, mx1 = -1e30f;
#pragma unroll
        for (int j = 0; j < 8; j++) {
            mx0 = fmaxf(mx0, fmaxf(sc[j][0], sc[j][1]));
            mx1 = fmaxf(mx1, fmaxf(sc[j][2], sc[j][3]));
        }
        mx0 = fmaxf(mx0, __shfl_xor_sync(0xffffffffu, mx0, 1));
        mx0 = fmaxf(mx0, __shfl_xor_sync(0xffffffffu, mx0, 2));
        mx1 = fmaxf(mx1, __shfl_xor_sync(0xffffffffu, mx1, 1));
        mx1 = fmaxf(mx1, __shfl_xor_sync(0xffffffffu, mx1, 2));
        float mn0 = fmaxf(m2a, mx0), mn1 = fmaxf(m2b, mx1);
        float f0 = fexp2(m2a - mn0), f1 = fexp2(m2b - mn1);
        m2a = mn0; m2b = mn1;

        float s0 = 0.f, s1 = 0.f;
#pragma unroll
        for (int j = 0; j < 8; j++) {
            sc[j][0] = fexp2(sc[j][0] - mn0);
            sc[j][1] = fexp2(sc[j][1] - mn0);
            sc[j][2] = fexp2(sc[j][2] - mn1);
            sc[j][3] = fexp2(sc[j][3] - mn1);
            s0 += sc[j][0] + sc[j][1];
            s1 += sc[j][2] + sc[j][3];
        }
        s0 += __shfl_xor_sync(0xffffffffu, s0, 1);
        s0 += __shfl_xor_sync(0xffffffffu, s0, 2);
        s1 += __shfl_xor_sync(0xffffffffu, s1, 1);
        s1 += __shfl_xor_sync(0xffffffffu, s1, 2);
        la = la * f0 + s0;
        lb = lb * f1 + s1;

#pragma unroll
        for (int j = 0; j < 16; j++) {
            oacc[j][0] *= f0; oacc[j][1] *= f0;
            oacc[j][2] *= f1; oacc[j][3] *= f1;
        }

        // ---- store P as A-fragments (warp-private region) ----
        {
            int l0 = g * 4 + ((2 * t) & 3);
            int l1 = g * 4 + ((2 * t + 1) & 3);
            int shi = 2 * (t >> 1);
#pragma unroll
            for (int j = 0; j < 8; j++) {
                uint32_t base = (uint32_t)((j * 8 + w) * 32) * 4;
                Ps[base + l0 * 4 + shi]     = f2tf(sc[j][0]);
                Ps[base + l1 * 4 + shi]     = f2tf(sc[j][1]);
                Ps[base + l0 * 4 + shi + 1] = f2tf(sc[j][2]);
                Ps[base + l1 * 4 + shi + 1] = f2tf(sc[j][3]);
            }
        }
        __syncwarp();

        // ---- O += P @ V ----
#pragma unroll
        for (int kk = 0; kk < 8; kk++) {
            uint4 av = *(const uint4*)&Ps[((kk * 8 + w) * 32 + lane) * 4];
            uint32_t a[4] = {av.x, av.y, av.z, av.w};
#pragma unroll
            for (int j = 0; j < 16; j++) {
                uint2 bv = *(const uint2*)&Vs[((kk * 16 + j) * 32 + lane) * 2];
                uint32_t b[2] = {bv.x, bv.y};
                mma8(oacc[j], a, b);
            }
        }
        __syncthreads();          // all warps done with this stage
        issue(kt + 2, kt & 1);    // refill consumed stage
        CP_COMMIT();
    }

    // ---- epilogue ----
    float inv0 = 1.f / la, inv1 = 1.f / lb;
    int row0 = q0 + w * 16 + g;
#pragma unroll
    for (int j = 0; j < 16; j++) {
        int col = h * HD + j * 8 + 2 * t;
        *(float2*)&gao[(size_t)row0 * HDIM + col] =
            make_float2(oacc[j][0] * inv0, oacc[j][1] * inv0);
        *(float2*)&gao[(size_t)(row0 + 8) * HDIM + col] =
            make_float2(oacc[j][2] * inv1, oacc[j][3] * inv1);
    }
}

// ---------------- launch ----------------
extern "C" void kernel_launch(void* const* d_in, const int* in_sizes, int n_in,
                              void* d_out, int out_size) {
    const float* hidden    = (const float*)d_in[0];
    const int*   positions = (const int*)  d_in[1];
    const float* w_qkv     = (const float*)d_in[2];
    const float* w_o       = (const float*)d_in[3];
    const float* q_norm_w  = (const float*)d_in[4];
    const float* k_norm_w  = (const float*)d_in[5];
    const float* cache     = (const float*)d_in[6];
    float* out = (float*)d_out;

    float *qkv_p, *q_p, *k_p, *ao_p;
    uint32_t *af_p, *bf_p, *kf_p, *vf_p;
    cudaGetSymbolAddress((void**)&qkv_p, g_qkv);
    cudaGetSymbolAddress((void**)&q_p,   g_q);
    cudaGetSymbolAddress((void**)&k_p,   g_k);
    cudaGetSymbolAddress((void**)&ao_p,  g_ao);
    cudaGetSymbolAddress((void**)&af_p,  g_af);
    cudaGetSymbolAddress((void**)&bf_p,  g_bf);
    cudaGetSymbolAddress((void**)&kf_p,  g_kf);
    cudaGetSymbolAddress((void**)&vf_p,  g_vf);

    cudaFuncSetAttribute(gemm_pre, cudaFuncAttributeMaxDynamicSharedMemorySize,
                         GEMM_SMEM_BYTES);
    cudaFuncSetAttribute(attn_pre, cudaFuncAttributeMaxDynamicSharedMemorySize,
                         ATTN_SMEM_BYTES);

    // 1) QKV projection
    permA_kernel<<<dim3(64, 32), 256>>>(hidden, af_p, S_LEN, HDIM);
    permB_kernel<<<dim3(32, 64), 256>>>(w_qkv, bf_p, HDIM, QKV_N);
    gemm_pre<<<dim3(32, 32), 256, GEMM_SMEM_BYTES>>>(af_p, bf_p, qkv_p,
                                                     S_LEN, QKV_N, HDIM);

    // 2) RMSNorm + mRoPE
    normrope_kernel<<<S_LEN, 256>>>(qkv_p, positions, q_norm_w, k_norm_w,
                                    cache, q_p, k_p);

    // 3) permute K/V to fragment tiles, then flash attention
    permK_kernel<<<dim3(S_LEN / 64, NKV), 256>>>(k_p, kf_p);
    permV_kernel<<<dim3(S_LEN / 64, NKV), 256>>>(qkv_p, vf_p);
    attn_pre<<<dim3(S_LEN / 128, NH), 256, ATTN_SMEM_BYTES>>>(q_p, kf_p, vf_p, ao_p);

    // 4) output projection
    permA_kernel<<<dim3(64, 32), 256>>>(ao_p, af_p, S_LEN, HDIM);
    permB_kernel<<<dim3(16, 64), 256>>>(w_o, bf_p, HDIM, HDIM);
    gemm_pre<<<dim3(16, 32), 256, GEMM_SMEM_BYTES>>>(af_p, bf_p, out,
                                                     S_LEN, HDIM, HDIM);
}

// round 5
// speedup vs baseline: 7.9191x; 1.0371x over previous
#include <cuda_runtime.h>
#include <cstdint>
#include <cstddef>

// ---------------- problem constants ----------------
#define S_LEN   4096
#define HDIM    2048
#define NH      16
#define NKV     8
#define HD      128
#define QKV_N   4096
#define VOFF    3072                     // NH*HD + NKV*HD
#define ATT_SCALE 0.08838834764831845f   // 128^-0.5
#define EPS_RMS 1e-6f
#define LOG2E   1.4426950408889634f

// ---------------- scratch (device globals: allowed) ----------------
__device__ float g_qkv[(size_t)S_LEN * QKV_N];       // 64 MB
__device__ float g_q[(size_t)NH  * S_LEN * HD];      // 32 MB  [h][s][d]
__device__ float g_k[(size_t)NKV * S_LEN * HD];      // 16 MB  [kv][s][d]
__device__ float g_ao[(size_t)S_LEN * (NH * HD)];    // 32 MB  [s][h*128+d]
// fragment-layout (tf32) scratch, reused across the two GEMMs
__device__ uint32_t g_af[(size_t)32 * 64 * 4096];    // 32 MB  A tiles [mb][kb][4096]
__device__ uint32_t g_bf[(size_t)64 * 32 * 4096];    // 32 MB  B tiles [kb][nb][4096]
__device__ uint32_t g_kf[(size_t)NKV * 64 * 8192];   // 16 MB  K tiles [kv][kt][8192]
__device__ uint32_t g_vf[(size_t)NKV * 64 * 8192];   // 16 MB  V tiles [kv][kt][8192]

// ---------------- helpers ----------------
__device__ __forceinline__ uint32_t f2tf(float x) {
    uint32_t r;
    asm("cvt.rna.tf32.f32 %0, %1;" : "=r"(r) : "f"(x));
    return r;
}

__device__ __forceinline__ float ex2f(float x) {
    float y;
    asm("ex2.approx.f32 %0, %1;" : "=f"(y) : "f"(x));
    return y;
}

__device__ __forceinline__ void mma8(float c[4], const uint32_t a[4], const uint32_t b[2]) {
    asm volatile(
        "mma.sync.aligned.m16n8k8.row.col.f32.tf32.tf32.f32 "
        "{%0,%1,%2,%3}, {%4,%5,%6,%7}, {%8,%9}, {%0,%1,%2,%3};"
        : "+f"(c[0]), "+f"(c[1]), "+f"(c[2]), "+f"(c[3])
        : "r"(a[0]), "r"(a[1]), "r"(a[2]), "r"(a[3]), "r"(b[0]), "r"(b[1]));
}

__device__ __forceinline__ void cpasync16(uint32_t saddr, const void* gptr) {
    asm volatile("cp.async.cg.shared.global [%0], [%1], 16;"
                 :: "r"(saddr), "l"(gptr));
}
#define CP_COMMIT() asm volatile("cp.async.commit_group;")
#define CP_WAIT1()  asm volatile("cp.async.wait_group 1;")
#define CP_WAIT2()  asm volatile("cp.async.wait_group 2;")

// ================= permute kernels (f32 gmem -> tf32 fragment-layout gmem) ====

// A tiles: [M][K] row-major -> [mb][kb][4096]
__global__ void permA_kernel(const float* __restrict__ A, uint32_t* __restrict__ out,
                             int M, int K) {
    __shared__ float t[128 * 36];
    const int kb = blockIdx.x, mb = blockIdx.y, nkb = gridDim.x;
    const int tid = threadIdx.x;
#pragma unroll
    for (int p = 0; p < 4; p++) {
        int idx = tid + p * 256;
        int r = idx >> 3, c4 = (idx & 7) * 4;
        float4 v = *(const float4*)&A[(size_t)(mb * 128 + r) * K + kb * 32 + c4];
        *(float4*)&t[r * 36 + c4] = v;
    }
    __syncthreads();
    uint32_t* dst = out + ((size_t)mb * nkb + kb) * 4096;
#pragma unroll
    for (int q = 0; q < 4; q++) {
        int o = q * 1024 + tid * 4;
        int slot = (o >> 2) & 31, frag = o >> 7;
        int rb = (frag & 7) * 16 + (slot >> 2);
        int cb = (frag >> 3) * 8 + (slot & 3);
        uint4 u;
        u.x = f2tf(t[rb * 36 + cb]);
        u.y = f2tf(t[(rb + 8) * 36 + cb]);
        u.z = f2tf(t[rb * 36 + cb + 4]);
        u.w = f2tf(t[(rb + 8) * 36 + cb + 4]);
        *(uint4*)&dst[o] = u;
    }
}

// B tiles: [K][N] row-major -> [kb][nb][4096]
__global__ void permB_kernel(const float* __restrict__ B, uint32_t* __restrict__ out,
                             int K, int N) {
    __shared__ float t[32 * 132];
    const int nb = blockIdx.x, kb = blockIdx.y, nnb = gridDim.x;
    const int tid = threadIdx.x;
#pragma unroll
    for (int p = 0; p < 4; p++) {
        int idx = tid + p * 256;
        int r = idx >> 5, c4 = (idx & 31) * 4;
        float4 v = *(const float4*)&B[(size_t)(kb * 32 + r) * N + nb * 128 + c4];
        *(float4*)&t[r * 132 + c4] = v;
    }
    __syncthreads();
    uint32_t* dst = out + ((size_t)kb * nnb + nb) * 4096;
#pragma unroll
    for (int q = 0; q < 4; q++) {
        int o = q * 1024 + tid * 4;
        uint32_t u[4];
#pragma unroll
        for (int e = 0; e < 4; e++) {
            int oe = o + e;
            int half = oe & 1, slot = (oe >> 1) & 31, f = oe >> 6;
            int r = (f >> 4) * 8 + half * 4 + (slot & 3);
            int c = (f & 15) * 8 + (slot >> 2);
            u[e] = f2tf(t[r * 132 + c]);
        }
        *(uint4*)&dst[o] = make_uint4(u[0], u[1], u[2], u[3]);
    }
}

// K tiles: g_k [kv][s][d] -> [kv][kt][8192]
__global__ void permK_kernel(const float* __restrict__ gk, uint32_t* __restrict__ out) {
    __shared__ float t[64 * 132];
    const int kt = blockIdx.x, kv = blockIdx.y;
    const int tid = threadIdx.x;
#pragma unroll
    for (int p = 0; p < 8; p++) {
        int idx = tid + p * 256;
        int r = idx >> 5, c4 = (idx & 31) * 4;
        float4 v = *(const float4*)&gk[((size_t)kv * S_LEN + kt * 64 + r) * HD + c4];
        *(float4*)&t[r * 132 + c4] = v;
    }
    __syncthreads();
    uint32_t* dst = out + ((size_t)kv * (S_LEN / 64) + kt) * 8192;
#pragma unroll
    for (int q = 0; q < 8; q++) {
        int o = q * 1024 + tid * 4;
        uint32_t u[4];
#pragma unroll
        for (int e = 0; e < 4; e++) {
            int oe = o + e;
            int half = oe & 1, slot = (oe >> 1) & 31, f = oe >> 6;
            int r = (f & 7) * 8 + (slot >> 2);
            int d = (f >> 3) * 8 + half * 4 + (slot & 3);
            u[e] = f2tf(t[r * 132 + d]);
        }
        *(uint4*)&dst[o] = make_uint4(u[0], u[1], u[2], u[3]);
    }
}

// V tiles: g_qkv strided -> [kv][kt][8192]
__global__ void permV_kernel(const float* __restrict__ gqkv, uint32_t* __restrict__ out) {
    __shared__ float t[64 * 132];
    const int kt = blockIdx.x, kv = blockIdx.y;
    const int tid = threadIdx.x;
#pragma unroll
    for (int p = 0; p < 8; p++) {
        int idx = tid + p * 256;
        int r = idx >> 5, c4 = (idx & 31) * 4;
        float4 v = *(const float4*)&gqkv[(size_t)(kt * 64 + r) * QKV_N + VOFF + kv * HD + c4];
        *(float4*)&t[r * 132 + c4] = v;
    }
    __syncthreads();
    uint32_t* dst = out + ((size_t)kv * (S_LEN / 64) + kt) * 8192;
#pragma unroll
    for (int q = 0; q < 8; q++) {
        int o = q * 1024 + tid * 4;
        uint32_t u[4];
#pragma unroll
        for (int e = 0; e < 4; e++) {
            int oe = o + e;
            int half = oe & 1, slot = (oe >> 1) & 31, f = oe >> 6;
            int d = (f & 15) * 8 + (slot >> 2);
            int r = (f >> 4) * 8 + half * 4 + (slot & 3);
            u[e] = f2tf(t[r * 132 + d]);
        }
        *(uint4*)&dst[o] = make_uint4(u[0], u[1], u[2], u[3]);
    }
}

// ================= tf32 GEMM on pre-permuted tiles =================
#define GEMM_SMEM_BYTES (3 * 8192 * 4)

__global__ __launch_bounds__(256, 2)
void gemm_pre(const uint32_t* __restrict__ Af, const uint32_t* __restrict__ Bf,
              float* __restrict__ C, int M, int N, int K) {
    extern __shared__ uint32_t smg[];
    const int tid  = threadIdx.x;
    const int lane = tid & 31;
    const int warp = tid >> 5;
    const int wm = warp >> 2, wn = warp & 3;
    const int g = lane >> 2, t = lane & 3;
    const int mb = blockIdx.y, nb = blockIdx.x;
    const int nkb = K / 32, nnb = N / 128;
    const uint32_t sbase = (uint32_t)__cvta_generic_to_shared(smg);
    const uint32_t* Asrc = Af + (size_t)mb * nkb * 4096;

    auto issue = [&](int kb, int st) {
        uint32_t dst = sbase + (uint32_t)st * 32768;
        const uint32_t* a = Asrc + (size_t)kb * 4096;
        const uint32_t* b = Bf + ((size_t)kb * nnb + nb) * 4096;
#pragma unroll
        for (int p = 0; p < 4; p++) {
            int i = tid + p * 256;
            cpasync16(dst + i * 16, a + i * 4);
            cpasync16(dst + 16384 + i * 16, b + i * 4);
        }
    };

    issue(0, 0); CP_COMMIT();
    issue(1, 1); CP_COMMIT();

    float acc[4][4][4];
#pragma unroll
    for (int i = 0; i < 4; i++)
#pragma unroll
        for (int j = 0; j < 4; j++)
#pragma unroll
            for (int e = 0; e < 4; e++) acc[i][j][e] = 0.f;

    for (int kb = 0; kb < nkb; kb++) {
        CP_WAIT1();
        __syncthreads();
        if (kb + 2 < nkb) issue(kb + 2, (kb + 2) % 3);
        CP_COMMIT();

        const uint32_t* As = smg + (kb % 3) * 8192;
        const uint32_t* Bs = As + 4096;
#pragma unroll
        for (int ks = 0; ks < 4; ks++) {
            uint32_t a[4][4], b[4][2];
#pragma unroll
            for (int i = 0; i < 4; i++) {
                uint4 av = *(const uint4*)&As[((ks * 8 + wm * 4 + i) * 32 + lane) * 4];
                a[i][0] = av.x; a[i][1] = av.y; a[i][2] = av.z; a[i][3] = av.w;
            }
#pragma unroll
            for (int j = 0; j < 4; j++) {
                uint2 bv = *(const uint2*)&Bs[((ks * 16 + wn * 4 + j) * 32 + lane) * 2];
                b[j][0] = bv.x; b[j][1] = bv.y;
            }
#pragma unroll
            for (int i = 0; i < 4; i++)
#pragma unroll
                for (int j = 0; j < 4; j++)
                    mma8(acc[i][j], a[i], b[j]);
        }
    }

#pragma unroll
    for (int i = 0; i < 4; i++)
#pragma unroll
        for (int j = 0; j < 4; j++) {
            int row0 = mb * 128 + wm * 64 + i * 16 + g;
            int col  = nb * 128 + wn * 32 + j * 8 + 2 * t;
            *(float2*)&C[(size_t)row0 * N + col]       = make_float2(acc[i][j][0], acc[i][j][1]);
            *(float2*)&C[(size_t)(row0 + 8) * N + col] = make_float2(acc[i][j][2], acc[i][j][3]);
        }
}

// ---------------- RMSNorm + mRoPE ----------------
__global__ void normrope_kernel(const float* __restrict__ qkv,
                                const int*   __restrict__ positions,
                                const float* __restrict__ qw,
                                const float* __restrict__ kw,
                                const float* __restrict__ cache,
                                float* __restrict__ gq,
                                float* __restrict__ gk) {
    const int s = blockIdx.x;
    __shared__ float cs[64], sn[64];
    const int tid = threadIdx.x;

    if (tid < 64) {
        int i = tid;
        int m3 = i % 3;
        int sec = (i < 60) ? ((m3 == 1) ? 1 : ((m3 == 2) ? 2 : 0)) : 0;
        int pos = positions[sec * S_LEN + s];
        cs[i] = cache[(size_t)pos * HD + i];
        sn[i] = cache[(size_t)pos * HD + 64 + i];
    }
    __syncthreads();

    const int warp = tid >> 5;
    const int lane = tid & 31;
    const int dbase = lane * 4;

    for (int h = warp; h < NH + NKV; h += 8) {
        const float* src;
        const float* w;
        float* dst;
        if (h < NH) {
            src = qkv + (size_t)s * QKV_N + h * HD;
            w = qw;
            dst = gq + ((size_t)h * S_LEN + s) * HD;
        } else {
            int kh = h - NH;
            src = qkv + (size_t)s * QKV_N + NH * HD + kh * HD;
            w = kw;
            dst = gk + ((size_t)kh * S_LEN + s) * HD;
        }
        float4 xv = *(const float4*)(src + dbase);
        float x[4] = {xv.x, xv.y, xv.z, xv.w};
        float ss = x[0]*x[0] + x[1]*x[1] + x[2]*x[2] + x[3]*x[3];
#pragma unroll
        for (int o = 16; o > 0; o >>= 1)
            ss += __shfl_xor_sync(0xffffffffu, ss, o);
        float inv = rsqrtf(ss * (1.0f / HD) + EPS_RMS);
        float4 wv = *(const float4*)(w + dbase);
        float nx[4] = {x[0]*inv*wv.x, x[1]*inv*wv.y, x[2]*inv*wv.z, x[3]*inv*wv.w};

        float out[4];
        const bool lo = (lane < 16);
#pragma unroll
        for (int j = 0; j < 4; j++) {
            float partner = __shfl_xor_sync(0xffffffffu, nx[j], 16);
            int i2 = (dbase + j) & 63;
            float c = cs[i2], si = sn[i2];
            out[j] = lo ? (nx[j] * c - partner * si)
                        : (nx[j] * c + partner * si);
        }
        *(float4*)(dst + dbase) = make_float4(out[0], out[1], out[2], out[3]);
    }
}

// ================= tf32 flash attention on pre-permuted K/V =================
// Bq=128, Bk=64, 256 threads; warp w owns rows w*16..w*16+15 (warp-local softmax).
// 3-stage cp.async pipeline of 64KB (Ks 32KB + Vs 32KB) fragment tiles.
// smem: stages [0,196608) bytes, Ps at [196608,229376). Qlin aliases stages.
#define ATTN_SMEM_BYTES (229376)

__global__ __launch_bounds__(256, 1)
void attn_pre(const float* __restrict__ gq, const uint32_t* __restrict__ Kf,
              const uint32_t* __restrict__ Vf, float* __restrict__ gao) {
    extern __shared__ uint32_t smu[];
    uint32_t* Ps = smu + 49152;          // [8][8][32][4]
    float* Qlin = (float*)smu;           // [128][132] prologue only

    const int tid  = threadIdx.x;
    const int lane = tid & 31;
    const int w    = tid >> 5;
    const int g = lane >> 2, t = lane & 3;
    const int h  = blockIdx.y;
    const int qt = (int)gridDim.x - 1 - (int)blockIdx.x;
    const int q0 = qt * 128;
    const int kv = h >> 1;
    const int nkt = 2 * qt + 2;
    const uint32_t sbase = (uint32_t)__cvta_generic_to_shared(smu);

    // ---- prologue: Q tile -> smem linear -> register fragments ----
    const float* qbase = gq + ((size_t)h * S_LEN + q0) * HD;
#pragma unroll
    for (int p = 0; p < 16; p++) {
        int idx = tid + p * 256;
        int r = idx >> 5, c4 = (idx & 31) * 4;
        *(float4*)&Qlin[r * 132 + c4] = *(const float4*)&qbase[(size_t)r * HD + c4];
    }
    __syncthreads();

    // fold ATT_SCALE * log2(e) into Q fragments
    const float CC = ATT_SCALE * LOG2E;
    uint32_t aq[16][4];
    {
        int r0 = w * 16 + g;
#pragma unroll
        for (int ks = 0; ks < 16; ks++) {
            aq[ks][0] = f2tf(Qlin[r0 * 132 + ks * 8 + t] * CC);
            aq[ks][1] = f2tf(Qlin[(r0 + 8) * 132 + ks * 8 + t] * CC);
            aq[ks][2] = f2tf(Qlin[r0 * 132 + ks * 8 + t + 4] * CC);
            aq[ks][3] = f2tf(Qlin[(r0 + 8) * 132 + ks * 8 + t + 4] * CC);
        }
    }
    __syncthreads();   // everyone done reading Qlin before cp.async clobbers it

    const uint32_t* Ksrc = Kf + (size_t)kv * (S_LEN / 64) * 8192;
    const uint32_t* Vsrc = Vf + (size_t)kv * (S_LEN / 64) * 8192;
    auto issue = [&](int kt, int st) {
        if (kt < nkt) {
            uint32_t dst = sbase + (uint32_t)st * 65536;
            const uint32_t* kp = Ksrc + (size_t)kt * 8192;
            const uint32_t* vp = Vsrc + (size_t)kt * 8192;
#pragma unroll
            for (int p = 0; p < 8; p++) {
                int i = tid + p * 256;
                cpasync16(dst + i * 16, kp + i * 4);
                cpasync16(dst + 32768 + i * 16, vp + i * 4);
            }
        }
    };
    issue(0, 0); CP_COMMIT();
    issue(1, 1); CP_COMMIT();
    issue(2, 2); CP_COMMIT();

    float oacc[16][4];
#pragma unroll
    for (int j = 0; j < 16; j++)
#pragma unroll
        for (int e = 0; e < 4; e++) oacc[j][e] = 0.f;
    float m2a = -1e30f, m2b = -1e30f;
    float la = 0.f, lb = 0.f;

    const int r0g = q0 + w * 16 + g;

#pragma unroll 1
    for (int kt = 0; kt < nkt; kt++) {
        CP_WAIT2();
        __syncthreads();
        const uint32_t* Ks = smu + (kt % 3) * 16384;
        const uint32_t* Vs = Ks + 8192;

        // ---- scores: 16 rows x 64 cols per warp (pre-scaled, base-2) ----
        float sc[8][4];
#pragma unroll
        for (int j = 0; j < 8; j++)
#pragma unroll
            for (int e = 0; e < 4; e++) sc[j][e] = 0.f;
#pragma unroll
        for (int ks = 0; ks < 16; ks++) {
#pragma unroll
            for (int j = 0; j < 8; j++) {
                uint2 bv = *(const uint2*)&Ks[((ks * 8 + j) * 32 + lane) * 2];
                uint32_t b[2] = {bv.x, bv.y};
                mma8(sc[j], aq[ks], b);
            }
        }

        // ---- causal mask (diagonal tiles only) ----
        if (kt >= 2 * qt) {
            const int k0 = kt * 64;
#pragma unroll
            for (int j = 0; j < 8; j++) {
                int c0 = k0 + j * 8 + 2 * t;
                if (c0     > r0g)     sc[j][0] = -1e30f;
                if (c0 + 1 > r0g)     sc[j][1] = -1e30f;
                if (c0     > r0g + 8) sc[j][2] = -1e30f;
                if (c0 + 1 > r0g + 8) sc[j][3] = -1e30f;
            }
        }

        // ---- online softmax (warp-local, quad reduction, MUFU exp2) ----
        float mx0 = -1e30f, mx1 = -1e30f;
#pragma unroll
        for (int j = 0; j < 8; j++) {
            mx0 = fmaxf(mx0, fmaxf(sc[j][0], sc[j][1]));
            mx1 = fmaxf(mx1, fmaxf(sc[j][2], sc[j][3]));
        }
        mx0 = fmaxf(mx0, __shfl_xor_sync(0xffffffffu, mx0, 1));
        mx0 = fmaxf(mx0, __shfl_xor_sync(0xffffffffu, mx0, 2));
        mx1 = fmaxf(mx1, __shfl_xor_sync(0xffffffffu, mx1, 1));
        mx1 = fmaxf(mx1, __shfl_xor_sync(0xffffffffu, mx1, 2));
        float mn0 = fmaxf(m2a, mx0), mn1 = fmaxf(m2b, mx1);
        float f0 = ex2f(m2a - mn0), f1 = ex2f(m2b - mn1);
        m2a = mn0; m2b = mn1;

        float s0 = 0.f, s1 = 0.f;
#pragma unroll
        for (int j = 0; j < 8; j++) {
            sc[j][0] = ex2f(sc[j][0] - mn0);
            sc[j][1] = ex2f(sc[j][1] - mn0);
            sc[j][2] = ex2f(sc[j][2] - mn1);
            sc[j][3] = ex2f(sc[j][3] - mn1);
            s0 += sc[j][0] + sc[j][1];
            s1 += sc[j][2] + sc[j][3];
        }
        s0 += __shfl_xor_sync(0xffffffffu, s0, 1);
        s0 += __shfl_xor_sync(0xffffffffu, s0, 2);
        s1 += __shfl_xor_sync(0xffffffffu, s1, 1);
        s1 += __shfl_xor_sync(0xffffffffu, s1, 2);
        la = la * f0 + s0;
        lb = lb * f1 + s1;

#pragma unroll
        for (int j = 0; j < 16; j++) {
            oacc[j][0] *= f0; oacc[j][1] *= f0;
            oacc[j][2] *= f1; oacc[j][3] *= f1;
        }

        // ---- store P as A-fragments (warp-private region) ----
        {
            int l0 = g * 4 + ((2 * t) & 3);
            int l1 = g * 4 + ((2 * t + 1) & 3);
            int shi = 2 * (t >> 1);
#pragma unroll
            for (int j = 0; j < 8; j++) {
                uint32_t base = (uint32_t)((j * 8 + w) * 32) * 4;
                Ps[base + l0 * 4 + shi]     = f2tf(sc[j][0]);
                Ps[base + l1 * 4 + shi]     = f2tf(sc[j][1]);
                Ps[base + l0 * 4 + shi + 1] = f2tf(sc[j][2]);
                Ps[base + l1 * 4 + shi + 1] = f2tf(sc[j][3]);
            }
        }
        __syncwarp();

        // ---- O += P @ V ----
#pragma unroll
        for (int kk = 0; kk < 8; kk++) {
            uint4 av = *(const uint4*)&Ps[((kk * 8 + w) * 32 + lane) * 4];
            uint32_t a[4] = {av.x, av.y, av.z, av.w};
#pragma unroll
            for (int j = 0; j < 16; j++) {
                uint2 bv = *(const uint2*)&Vs[((kk * 16 + j) * 32 + lane) * 2];
                uint32_t b[2] = {bv.x, bv.y};
                mma8(oacc[j], a, b);
            }
        }
        __syncthreads();          // all warps done with this stage
        issue(kt + 3, kt % 3);    // refill consumed stage
        CP_COMMIT();
    }

    // ---- epilogue ----
    float inv0 = 1.f / la, inv1 = 1.f / lb;
    int row0 = q0 + w * 16 + g;
#pragma unroll
    for (int j = 0; j < 16; j++) {
        int col = h * HD + j * 8 + 2 * t;
        *(float2*)&gao[(size_t)row0 * HDIM + col] =
            make_float2(oacc[j][0] * inv0, oacc[j][1] * inv0);
        *(float2*)&gao[(size_t)(row0 + 8) * HDIM + col] =
            make_float2(oacc[j][2] * inv1, oacc[j][3] * inv1);
    }
}

// ---------------- launch ----------------
extern "C" void kernel_launch(void* const* d_in, const int* in_sizes, int n_in,
                              void* d_out, int out_size) {
    const float* hidden    = (const float*)d_in[0];
    const int*   positions = (const int*)  d_in[1];
    const float* w_qkv     = (const float*)d_in[2];
    const float* w_o       = (const float*)d_in[3];
    const float* q_norm_w  = (const float*)d_in[4];
    const float* k_norm_w  = (const float*)d_in[5];
    const float* cache     = (const float*)d_in[6];
    float* out = (float*)d_out;

    float *qkv_p, *q_p, *k_p, *ao_p;
    uint32_t *af_p, *bf_p, *kf_p, *vf_p;
    cudaGetSymbolAddress((void**)&qkv_p, g_qkv);
    cudaGetSymbolAddress((void**)&q_p,   g_q);
    cudaGetSymbolAddress((void**)&k_p,   g_k);
    cudaGetSymbolAddress((void**)&ao_p,  g_ao);
    cudaGetSymbolAddress((void**)&af_p,  g_af);
    cudaGetSymbolAddress((void**)&bf_p,  g_bf);
    cudaGetSymbolAddress((void**)&kf_p,  g_kf);
    cudaGetSymbolAddress((void**)&vf_p,  g_vf);

    cudaFuncSetAttribute(gemm_pre, cudaFuncAttributeMaxDynamicSharedMemorySize,
                         GEMM_SMEM_BYTES);
    cudaFuncSetAttribute(attn_pre, cudaFuncAttributeMaxDynamicSharedMemorySize,
                         ATTN_SMEM_BYTES);

    // 1) QKV projection
    permA_kernel<<<dim3(64, 32), 256>>>(hidden, af_p, S_LEN, HDIM);
    permB_kernel<<<dim3(32, 64), 256>>>(w_qkv, bf_p, HDIM, QKV_N);
    gemm_pre<<<dim3(32, 32), 256, GEMM_SMEM_BYTES>>>(af_p, bf_p, qkv_p,
                                                     S_LEN, QKV_N, HDIM);

    // 2) RMSNorm + mRoPE
    normrope_kernel<<<S_LEN, 256>>>(qkv_p, positions, q_norm_w, k_norm_w,
                                    cache, q_p, k_p);

    // 3) permute K/V to fragment tiles, then flash attention
    permK_kernel<<<dim3(S_LEN / 64, NKV), 256>>>(k_p, kf_p);
    permV_kernel<<<dim3(S_LEN / 64, NKV), 256>>>(qkv_p, vf_p);
    attn_pre<<<dim3(S_LEN / 128, NH), 256, ATTN_SMEM_BYTES>>>(q_p, kf_p, vf_p, ao_p);

    // 4) output projection
    permA_kernel<<<dim3(64, 32), 256>>>(ao_p, af_p, S_LEN, HDIM);
    permB_kernel<<<dim3(16, 64), 256>>>(w_o, bf_p, HDIM, HDIM);
    gemm_pre<<<dim3(16, 32), 256, GEMM_SMEM_BYTES>>>(af_p, bf_p, out,
                                                     S_LEN, HDIM, HDIM);
}

// round 8
// speedup vs baseline: 8.0346x; 1.0146x over previous
#include <cuda_runtime.h>
#include <cstdint>
#include <cstddef>

// ---------------- problem constants ----------------
#define S_LEN   4096
#define HDIM    2048
#define NH      16
#define NKV     8
#define HD      128
#define QKV_N   4096
#define VOFF    3072                     // NH*HD + NKV*HD
#define ATT_SCALE 0.08838834764831845f   // 128^-0.5
#define EPS_RMS 1e-6f
#define LOG2E   1.4426950408889634f

// ---------------- scratch (device globals: allowed) ----------------
__device__ float g_qkv[(size_t)S_LEN * QKV_N];       // 64 MB
__device__ float g_q[(size_t)NH  * S_LEN * HD];      // 32 MB  [h][s][d]
__device__ float g_k[(size_t)NKV * S_LEN * HD];      // 16 MB  [kv][s][d]
__device__ float g_ao[(size_t)S_LEN * (NH * HD)];    // 32 MB  [s][h*128+d]
__device__ uint32_t g_af[(size_t)32 * 64 * 4096];    // 32 MB  A tiles [mb][kb][4096]
__device__ uint32_t g_bf[(size_t)64 * 32 * 4096];    // 32 MB  B tiles [kb][nb][4096]
__device__ uint32_t g_kf[(size_t)NKV * 64 * 8192];   // 16 MB  K tiles [kv][kt][8192]
__device__ uint32_t g_vf[(size_t)NKV * 64 * 8192];   // 16 MB  V tiles [kv][kt][8192]

// ---------------- helpers ----------------
__device__ __forceinline__ uint32_t f2tf(float x) {
    uint32_t r;
    asm("cvt.rna.tf32.f32 %0, %1;" : "=r"(r) : "f"(x));
    return r;
}

__device__ __forceinline__ float ex2f(float x) {
    float y;
    asm("ex2.approx.f32 %0, %1;" : "=f"(y) : "f"(x));
    return y;
}

__device__ __forceinline__ void mma8(float c[4], const uint32_t a[4], const uint32_t b[2]) {
    asm volatile(
        "mma.sync.aligned.m16n8k8.row.col.f32.tf32.tf32.f32 "
        "{%0,%1,%2,%3}, {%4,%5,%6,%7}, {%8,%9}, {%0,%1,%2,%3};"
        : "+f"(c[0]), "+f"(c[1]), "+f"(c[2]), "+f"(c[3])
        : "r"(a[0]), "r"(a[1]), "r"(a[2]), "r"(a[3]), "r"(b[0]), "r"(b[1]));
}

__device__ __forceinline__ void cpasync16(uint32_t saddr, const void* gptr) {
    asm volatile("cp.async.cg.shared.global [%0], [%1], 16;"
                 :: "r"(saddr), "l"(gptr));
}
#define CP_COMMIT() asm volatile("cp.async.commit_group;")
#define CP_WAIT1()  asm volatile("cp.async.wait_group 1;")
#define CP_WAIT2()  asm volatile("cp.async.wait_group 2;")

// ================= permute kernels (f32 gmem -> tf32 fragment-layout gmem) ====

// A tiles: [M][K] row-major -> [mb][kb][4096]  (unchanged from Round 4/5)
__global__ void permA_kernel(const float* __restrict__ A, uint32_t* __restrict__ out,
                             int M, int K) {
    __shared__ float t[128 * 36];
    const int kb = blockIdx.x, mb = blockIdx.y, nkb = gridDim.x;
    const int tid = threadIdx.x;
#pragma unroll
    for (int p = 0; p < 4; p++) {
        int idx = tid + p * 256;
        int r = idx >> 3, c4 = (idx & 7) * 4;
        float4 v = *(const float4*)&A[(size_t)(mb * 128 + r) * K + kb * 32 + c4];
        *(float4*)&t[r * 36 + c4] = v;
    }
    __syncthreads();
    uint32_t* dst = out + ((size_t)mb * nkb + kb) * 4096;
#pragma unroll
    for (int q = 0; q < 4; q++) {
        int o = q * 1024 + tid * 4;
        int slot = (o >> 2) & 31, frag = o >> 7;
        int rb = (frag & 7) * 16 + (slot >> 2);
        int cb = (frag >> 3) * 8 + (slot & 3);
        uint4 u;
        u.x = f2tf(t[rb * 36 + cb]);
        u.y = f2tf(t[(rb + 8) * 36 + cb]);
        u.z = f2tf(t[rb * 36 + cb + 4]);
        u.w = f2tf(t[(rb + 8) * 36 + cb + 4]);
        *(uint4*)&dst[o] = u;
    }
}

// B tiles: [K][N] row-major -> [kb][nb][4096], PAIRED layout:
// o = ((ks*8 + nf2)*32 + lane)*4 + jl*2 + half,  nf = 2*nf2 + jl
// value = B[r][c] with r = ks*8 + half*4 + (lane&3), c = nf*8 + (lane>>2)
__global__ void permB_kernel(const float* __restrict__ B, uint32_t* __restrict__ out,
                             int K, int N) {
    __shared__ float t[32 * 132];
    const int nb = blockIdx.x, kb = blockIdx.y, nnb = gridDim.x;
    const int tid = threadIdx.x;
#pragma unroll
    for (int p = 0; p < 4; p++) {
        int idx = tid + p * 256;
        int r = idx >> 5, c4 = (idx & 31) * 4;
        float4 v = *(const float4*)&B[(size_t)(kb * 32 + r) * N + nb * 128 + c4];
        *(float4*)&t[r * 132 + c4] = v;
    }
    __syncthreads();
    uint32_t* dst = out + ((size_t)kb * nnb + nb) * 4096;
#pragma unroll
    for (int q = 0; q < 4; q++) {
        int o = q * 1024 + tid * 4;
        uint32_t u[4];
#pragma unroll
        for (int e = 0; e < 4; e++) {
            int oe = o + e;
            int jl = (oe >> 1) & 1, h = oe & 1;
            int l = (oe >> 2) & 31;
            int nf2 = (oe >> 7) & 7, ks = oe >> 10;
            int nf = 2 * nf2 + jl;
            int r = ks * 8 + h * 4 + (l & 3);
            int c = nf * 8 + (l >> 2);
            u[e] = f2tf(t[r * 132 + c]);
        }
        *(uint4*)&dst[o] = make_uint4(u[0], u[1], u[2], u[3]);
    }
}

// K tiles: g_k [kv][s][d] -> [kv][kt][8192], PAIRED layout:
// o = ((ks*4 + jj)*32 + lane)*4 + jl*2 + half,  j = 2*jj + jl
// value = K[r][d] with r = j*8 + (lane>>2), d = ks*8 + half*4 + (lane&3)
__global__ void permK_kernel(const float* __restrict__ gk, uint32_t* __restrict__ out) {
    __shared__ float t[64 * 132];
    const int kt = blockIdx.x, kv = blockIdx.y;
    const int tid = threadIdx.x;
#pragma unroll
    for (int p = 0; p < 8; p++) {
        int idx = tid + p * 256;
        int r = idx >> 5, c4 = (idx & 31) * 4;
        float4 v = *(const float4*)&gk[((size_t)kv * S_LEN + kt * 64 + r) * HD + c4];
        *(float4*)&t[r * 132 + c4] = v;
    }
    __syncthreads();
    uint32_t* dst = out + ((size_t)kv * (S_LEN / 64) + kt) * 8192;
#pragma unroll
    for (int q = 0; q < 8; q++) {
        int o = q * 1024 + tid * 4;
        uint32_t u[4];
#pragma unroll
        for (int e = 0; e < 4; e++) {
            int oe = o + e;
            int jl = (oe >> 1) & 1, h = oe & 1;
            int l = (oe >> 2) & 31;
            int jj = (oe >> 7) & 3, ks = oe >> 9;
            int j = 2 * jj + jl;
            int r = j * 8 + (l >> 2);
            int d = ks * 8 + h * 4 + (l & 3);
            u[e] = f2tf(t[r * 132 + d]);
        }
        *(uint4*)&dst[o] = make_uint4(u[0], u[1], u[2], u[3]);
    }
}

// V tiles: g_qkv strided -> [kv][kt][8192], PAIRED layout:
// o = ((kk*8 + jj)*32 + lane)*4 + jl*2 + half,  jv = 2*jj + jl
// value = V[r][d] with r = kk*8 + half*4 + (lane&3), d = jv*8 + (lane>>2)
__global__ void permV_kernel(const float* __restrict__ gqkv, uint32_t* __restrict__ out) {
    __shared__ float t[64 * 132];
    const int kt = blockIdx.x, kv = blockIdx.y;
    const int tid = threadIdx.x;
#pragma unroll
    for (int p = 0; p < 8; p++) {
        int idx = tid + p * 256;
        int r = idx >> 5, c4 = (idx & 31) * 4;
        float4 v = *(const float4*)&gqkv[(size_t)(kt * 64 + r) * QKV_N + VOFF + kv * HD + c4];
        *(float4*)&t[r * 132 + c4] = v;
    }
    __syncthreads();
    uint32_t* dst = out + ((size_t)kv * (S_LEN / 64) + kt) * 8192;
#pragma unroll
    for (int q = 0; q < 8; q++) {
        int o = q * 1024 + tid * 4;
        uint32_t u[4];
#pragma unroll
        for (int e = 0; e < 4; e++) {
            int oe = o + e;
            int jl = (oe >> 1) & 1, h = oe & 1;
            int l = (oe >> 2) & 31;
            int jj = (oe >> 7) & 7, kk = oe >> 10;
            int jv = 2 * jj + jl;
            int r = kk * 8 + h * 4 + (l & 3);
            int d = jv * 8 + (l >> 2);
            u[e] = f2tf(t[r * 132 + d]);
        }
        *(uint4*)&dst[o] = make_uint4(u[0], u[1], u[2], u[3]);
    }
}

// ================= tf32 GEMM (mma.sync) on pre-permuted tiles =================
#define GEMM_SMEM_BYTES (3 * 8192 * 4)

__global__ __launch_bounds__(256, 2)
void gemm_pre(const uint32_t* __restrict__ Af, const uint32_t* __restrict__ Bf,
              float* __restrict__ C, int M, int N, int K) {
    extern __shared__ uint32_t smg[];
    const int tid  = threadIdx.x;
    const int lane = tid & 31;
    const int warp = tid >> 5;
    const int wm = warp >> 2, wn = warp & 3;
    const int g = lane >> 2, t = lane & 3;
    const int mb = blockIdx.y, nb = blockIdx.x;
    const int nkb = K / 32, nnb = N / 128;
    const uint32_t sbase = (uint32_t)__cvta_generic_to_shared(smg);
    const uint32_t* Asrc = Af + (size_t)mb * nkb * 4096;

    auto issue = [&](int kb, int st) {
        uint32_t dst = sbase + (uint32_t)st * 32768;
        const uint32_t* a = Asrc + (size_t)kb * 4096;
        const uint32_t* b = Bf + ((size_t)kb * nnb + nb) * 4096;
#pragma unroll
        for (int p = 0; p < 4; p++) {
            int i = tid + p * 256;
            cpasync16(dst + i * 16, a + i * 4);
            cpasync16(dst + 16384 + i * 16, b + i * 4);
        }
    };

    issue(0, 0); CP_COMMIT();
    issue(1, 1); CP_COMMIT();

    float acc[4][4][4];
#pragma unroll
    for (int i = 0; i < 4; i++)
#pragma unroll
        for (int j = 0; j < 4; j++)
#pragma unroll
            for (int e = 0; e < 4; e++) acc[i][j][e] = 0.f;

    for (int kb = 0; kb < nkb; kb++) {
        CP_WAIT1();
        __syncthreads();
        if (kb + 2 < nkb) issue(kb + 2, (kb + 2) % 3);
        CP_COMMIT();

        const uint32_t* As = smg + (kb % 3) * 8192;
        const uint32_t* Bs = As + 4096;
#pragma unroll
        for (int ks = 0; ks < 4; ks++) {
            uint32_t a[4][4], b[4][2];
#pragma unroll
            for (int i = 0; i < 4; i++) {
                uint4 av = *(const uint4*)&As[((ks * 8 + wm * 4 + i) * 32 + lane) * 4];
                a[i][0] = av.x; a[i][1] = av.y; a[i][2] = av.z; a[i][3] = av.w;
            }
#pragma unroll
            for (int j2 = 0; j2 < 2; j2++) {
                uint4 bv = *(const uint4*)&Bs[((ks * 8 + wn * 2 + j2) * 32 + lane) * 4];
                b[2 * j2][0]     = bv.x; b[2 * j2][1]     = bv.y;
                b[2 * j2 + 1][0] = bv.z; b[2 * j2 + 1][1] = bv.w;
            }
#pragma unroll
            for (int i = 0; i < 4; i++)
#pragma unroll
                for (int j = 0; j < 4; j++)
                    mma8(acc[i][j], a[i], b[j]);
        }
    }

#pragma unroll
    for (int i = 0; i < 4; i++)
#pragma unroll
        for (int j = 0; j < 4; j++) {
            int row0 = mb * 128 + wm * 64 + i * 16 + g;
            int col  = nb * 128 + wn * 32 + j * 8 + 2 * t;
            *(float2*)&C[(size_t)row0 * N + col]       = make_float2(acc[i][j][0], acc[i][j][1]);
            *(float2*)&C[(size_t)(row0 + 8) * N + col] = make_float2(acc[i][j][2], acc[i][j][3]);
        }
}

// ---------------- RMSNorm + mRoPE (unchanged) ----------------
__global__ void normrope_kernel(const float* __restrict__ qkv,
                                const int*   __restrict__ positions,
                                const float* __restrict__ qw,
                                const float* __restrict__ kw,
                                const float* __restrict__ cache,
                                float* __restrict__ gq,
                                float* __restrict__ gk) {
    const int s = blockIdx.x;
    __shared__ float cs[64], sn[64];
    const int tid = threadIdx.x;

    if (tid < 64) {
        int i = tid;
        int m3 = i % 3;
        int sec = (i < 60) ? ((m3 == 1) ? 1 : ((m3 == 2) ? 2 : 0)) : 0;
        int pos = positions[sec * S_LEN + s];
        cs[i] = cache[(size_t)pos * HD + i];
        sn[i] = cache[(size_t)pos * HD + 64 + i];
    }
    __syncthreads();

    const int warp = tid >> 5;
    const int lane = tid & 31;
    const int dbase = lane * 4;

    for (int h = warp; h < NH + NKV; h += 8) {
        const float* src;
        const float* w;
        float* dst;
        if (h < NH) {
            src = qkv + (size_t)s * QKV_N + h * HD;
            w = qw;
            dst = gq + ((size_t)h * S_LEN + s) * HD;
        } else {
            int kh = h - NH;
            src = qkv + (size_t)s * QKV_N + NH * HD + kh * HD;
            w = kw;
            dst = gk + ((size_t)kh * S_LEN + s) * HD;
        }
        float4 xv = *(const float4*)(src + dbase);
        float x[4] = {xv.x, xv.y, xv.z, xv.w};
        float ss = x[0]*x[0] + x[1]*x[1] + x[2]*x[2] + x[3]*x[3];
#pragma unroll
        for (int o = 16; o > 0; o >>= 1)
            ss += __shfl_xor_sync(0xffffffffu, ss, o);
        float inv = rsqrtf(ss * (1.0f / HD) + EPS_RMS);
        float4 wv = *(const float4*)(w + dbase);
        float nx[4] = {x[0]*inv*wv.x, x[1]*inv*wv.y, x[2]*inv*wv.z, x[3]*inv*wv.w};

        float out[4];
        const bool lo = (lane < 16);
#pragma unroll
        for (int j = 0; j < 4; j++) {
            float partner = __shfl_xor_sync(0xffffffffu, nx[j], 16);
            int i2 = (dbase + j) & 63;
            float c = cs[i2], si = sn[i2];
            out[j] = lo ? (nx[j] * c - partner * si)
                        : (nx[j] * c + partner * si);
        }
        *(float4*)(dst + dbase) = make_float4(out[0], out[1], out[2], out[3]);
    }
}

// ================= tf32 flash attention (paired K/V loads) =================
#define ATTN_SMEM_BYTES (229376)

__global__ __launch_bounds__(256, 1)
void attn_pre(const float* __restrict__ gq, const uint32_t* __restrict__ Kf,
              const uint32_t* __restrict__ Vf, float* __restrict__ gao) {
    extern __shared__ uint32_t smu[];
    uint32_t* Ps = smu + 49152;
    float* Qlin = (float*)smu;

    const int tid  = threadIdx.x;
    const int lane = tid & 31;
    const int w    = tid >> 5;
    const int g = lane >> 2, t = lane & 3;
    const int h  = blockIdx.y;
    const int qt = (int)gridDim.x - 1 - (int)blockIdx.x;
    const int q0 = qt * 128;
    const int kv = h >> 1;
    const int nkt = 2 * qt + 2;
    const uint32_t sbase = (uint32_t)__cvta_generic_to_shared(smu);

    const float* qbase = gq + ((size_t)h * S_LEN + q0) * HD;
#pragma unroll
    for (int p = 0; p < 16; p++) {
        int idx = tid + p * 256;
        int r = idx >> 5, c4 = (idx & 31) * 4;
        *(float4*)&Qlin[r * 132 + c4] = *(const float4*)&qbase[(size_t)r * HD + c4];
    }
    __syncthreads();

    const float CC = ATT_SCALE * LOG2E;
    uint32_t aq[16][4];
    {
        int r0 = w * 16 + g;
#pragma unroll
        for (int ks = 0; ks < 16; ks++) {
            aq[ks][0] = f2tf(Qlin[r0 * 132 + ks * 8 + t] * CC);
            aq[ks][1] = f2tf(Qlin[(r0 + 8) * 132 + ks * 8 + t] * CC);
            aq[ks][2] = f2tf(Qlin[r0 * 132 + ks * 8 + t + 4] * CC);
            aq[ks][3] = f2tf(Qlin[(r0 + 8) * 132 + ks * 8 + t + 4] * CC);
        }
    }
    __syncthreads();

    const uint32_t* Ksrc = Kf + (size_t)kv * (S_LEN / 64) * 8192;
    const uint32_t* Vsrc = Vf + (size_t)kv * (S_LEN / 64) * 8192;
    auto issue = [&](int kt, int st) {
        if (kt < nkt) {
            uint32_t dst = sbase + (uint32_t)st * 65536;
            const uint32_t* kp = Ksrc + (size_t)kt * 8192;
            const uint32_t* vp = Vsrc + (size_t)kt * 8192;
#pragma unroll
            for (int p = 0; p < 8; p++) {
                int i = tid + p * 256;
                cpasync16(dst + i * 16, kp + i * 4);
                cpasync16(dst + 32768 + i * 16, vp + i * 4);
            }
        }
    };
    issue(0, 0); CP_COMMIT();
    issue(1, 1); CP_COMMIT();
    issue(2, 2); CP_COMMIT();

    float oacc[16][4];
#pragma unroll
    for (int j = 0; j < 16; j++)
#pragma unroll
        for (int e = 0; e < 4; e++) oacc[j][e] = 0.f;
    float m2a = -1e30f, m2b = -1e30f;
    float la = 0.f, lb = 0.f;

    const int r0g = q0 + w * 16 + g;

#pragma unroll 1
    for (int kt = 0; kt < nkt; kt++) {
        CP_WAIT2();
        __syncthreads();
        const uint32_t* Ks = smu + (kt % 3) * 16384;
        const uint32_t* Vs = Ks + 8192;

        // ---- scores: paired K-fragment loads (LDS.128) ----
        float sc[8][4];
#pragma unroll
        for (int j = 0; j < 8; j++)
#pragma unroll
            for (int e = 0; e < 4; e++) sc[j][e] = 0.f;
#pragma unroll
        for (int ks = 0; ks < 16; ks++) {
#pragma unroll
            for (int jj = 0; jj < 4; jj++) {
                uint4 bv = *(const uint4*)&Ks[((ks * 4 + jj) * 32 + lane) * 4];
                uint32_t b0[2] = {bv.x, bv.y};
                uint32_t b1[2] = {bv.z, bv.w};
                mma8(sc[2 * jj],     aq[ks], b0);
                mma8(sc[2 * jj + 1], aq[ks], b1);
            }
        }

        if (kt >= 2 * qt) {
            const int k0 = kt * 64;
#pragma unroll
            for (int j = 0; j < 8; j++) {
                int c0 = k0 + j * 8 + 2 * t;
                if (c0     > r0g)     sc[j][0] = -1e30f;
                if (c0 + 1 > r0g)     sc[j][1] = -1e30f;
                if (c0     > r0g + 8) sc[j][2] = -1e30f;
                if (c0 + 1 > r0g + 8) sc[j][3] = -1e30f;
            }
        }

        float mx0 = -1e30f, mx1 = -1e30f;
#pragma unroll
        for (int j = 0; j < 8; j++) {
            mx0 = fmaxf(mx0, fmaxf(sc[j][0], sc[j][1]));
            mx1 = fmaxf(mx1, fmaxf(sc[j][2], sc[j][3]));
        }
        mx0 = fmaxf(mx0, __shfl_xor_sync(0xffffffffu, mx0, 1));
        mx0 = fmaxf(mx0, __shfl_xor_sync(0xffffffffu, mx0, 2));
        mx1 = fmaxf(mx1, __shfl_xor_sync(0xffffffffu, mx1, 1));
        mx1 = fmaxf(mx1, __shfl_xor_sync(0xffffffffu, mx1, 2));
        float mn0 = fmaxf(m2a, mx0), mn1 = fmaxf(m2b, mx1);
        float f0 = ex2f(m2a - mn0), f1 = ex2f(m2b - mn1);
        m2a = mn0; m2b = mn1;

        float s0 = 0.f, s1 = 0.f;
#pragma unroll
        for (int j = 0; j < 8; j++) {
            sc[j][0] = ex2f(sc[j][0] - mn0);
            sc[j][1] = ex2f(sc[j][1] - mn0);
            sc[j][2] = ex2f(sc[j][2] - mn1);
            sc[j][3] = ex2f(sc[j][3] - mn1);
            s0 += sc[j][0] + sc[j][1];
            s1 += sc[j][2] + sc[j][3];
        }
        s0 += __shfl_xor_sync(0xffffffffu, s0, 1);
        s0 += __shfl_xor_sync(0xffffffffu, s0, 2);
        s1 += __shfl_xor_sync(0xffffffffu, s1, 1);
        s1 += __shfl_xor_sync(0xffffffffu, s1, 2);
        la = la * f0 + s0;
        lb = lb * f1 + s1;

#pragma unroll
        for (int j = 0; j < 16; j++) {
            oacc[j][0] *= f0; oacc[j][1] *= f0;
            oacc[j][2] *= f1; oacc[j][3] *= f1;
        }

        {
            int l0 = g * 4 + ((2 * t) & 3);
            int l1 = g * 4 + ((2 * t + 1) & 3);
            int shi = 2 * (t >> 1);
#pragma unroll
            for (int j = 0; j < 8; j++) {
                uint32_t base = (uint32_t)((j * 8 + w) * 32) * 4;
                Ps[base + l0 * 4 + shi]     = f2tf(sc[j][0]);
                Ps[base + l1 * 4 + shi]     = f2tf(sc[j][1]);
                Ps[base + l0 * 4 + shi + 1] = f2tf(sc[j][2]);
                Ps[base + l1 * 4 + shi + 1] = f2tf(sc[j][3]);
            }
        }
        __syncwarp();

        // ---- O += P @ V: paired V-fragment loads (LDS.128) ----
#pragma unroll
        for (int kk = 0; kk < 8; kk++) {
            uint4 av = *(const uint4*)&Ps[((kk * 8 + w) * 32 + lane) * 4];
            uint32_t a[4] = {av.x, av.y, av.z, av.w};
#pragma unroll
            for (int jj = 0; jj < 8; jj++) {
                uint4 bv = *(const uint4*)&Vs[((kk * 8 + jj) * 32 + lane) * 4];
                uint32_t b0[2] = {bv.x, bv.y};
                uint32_t b1[2] = {bv.z, bv.w};
                mma8(oacc[2 * jj],     a, b0);
                mma8(oacc[2 * jj + 1], a, b1);
            }
        }
        __syncthreads();
        issue(kt + 3, kt % 3);
        CP_COMMIT();
    }

    float inv0 = 1.f / la, inv1 = 1.f / lb;
    int row0 = q0 + w * 16 + g;
#pragma unroll
    for (int j = 0; j < 16; j++) {
        int col = h * HD + j * 8 + 2 * t;
        *(float2*)&gao[(size_t)row0 * HDIM + col] =
            make_float2(oacc[j][0] * inv0, oacc[j][1] * inv0);
        *(float2*)&gao[(size_t)(row0 + 8) * HDIM + col] =
            make_float2(oacc[j][2] * inv1, oacc[j][3] * inv1);
    }
}

// ---------------- launch ----------------
extern "C" void kernel_launch(void* const* d_in, const int* in_sizes, int n_in,
                              void* d_out, int out_size) {
    const float* hidden    = (const float*)d_in[0];
    const int*   positions = (const int*)  d_in[1];
    const float* w_qkv     = (const float*)d_in[2];
    const float* w_o       = (const float*)d_in[3];
    const float* q_norm_w  = (const float*)d_in[4];
    const float* k_norm_w  = (const float*)d_in[5];
    const float* cache     = (const float*)d_in[6];
    float* out = (float*)d_out;

    float *qkv_p, *q_p, *k_p, *ao_p;
    uint32_t *af_p, *bf_p, *kf_p, *vf_p;
    cudaGetSymbolAddress((void**)&qkv_p, g_qkv);
    cudaGetSymbolAddress((void**)&q_p,   g_q);
    cudaGetSymbolAddress((void**)&k_p,   g_k);
    cudaGetSymbolAddress((void**)&ao_p,  g_ao);
    cudaGetSymbolAddress((void**)&af_p,  g_af);
    cudaGetSymbolAddress((void**)&bf_p,  g_bf);
    cudaGetSymbolAddress((void**)&kf_p,  g_kf);
    cudaGetSymbolAddress((void**)&vf_p,  g_vf);

    cudaFuncSetAttribute(gemm_pre, cudaFuncAttributeMaxDynamicSharedMemorySize,
                         GEMM_SMEM_BYTES);
    cudaFuncSetAttribute(attn_pre, cudaFuncAttributeMaxDynamicSharedMemorySize,
                         ATTN_SMEM_BYTES);

    // 1) QKV projection
    permA_kernel<<<dim3(64, 32), 256>>>(hidden, af_p, S_LEN, HDIM);
    permB_kernel<<<dim3(32, 64), 256>>>(w_qkv, bf_p, HDIM, QKV_N);
    gemm_pre<<<dim3(32, 32), 256, GEMM_SMEM_BYTES>>>(af_p, bf_p, qkv_p,
                                                     S_LEN, QKV_N, HDIM);

    // 2) RMSNorm + mRoPE
    normrope_kernel<<<S_LEN, 256>>>(qkv_p, positions, q_norm_w, k_norm_w,
                                    cache, q_p, k_p);

    // 3) permute K/V, flash attention
    permK_kernel<<<dim3(S_LEN / 64, NKV), 256>>>(k_p, kf_p);
    permV_kernel<<<dim3(S_LEN / 64, NKV), 256>>>(qkv_p, vf_p);
    attn_pre<<<dim3(S_LEN / 128, NH), 256, ATTN_SMEM_BYTES>>>(q_p, kf_p, vf_p, ao_p);

    // 4) output projection
    permA_kernel<<<dim3(64, 32), 256>>>(ao_p, af_p, S_LEN, HDIM);
    permB_kernel<<<dim3(16, 64), 256>>>(w_o, bf_p, HDIM, HDIM);
    gemm_pre<<<dim3(16, 32), 256, GEMM_SMEM_BYTES>>>(af_p, bf_p, out,
                                                     S_LEN, HDIM, HDIM);
}

// round 9
// speedup vs baseline: 8.1568x; 1.0152x over previous
#include <cuda_runtime.h>
#include <cstdint>
#include <cstddef>

// ---------------- problem constants ----------------
#define S_LEN   4096
#define HDIM    2048
#define NH      16
#define NKV     8
#define HD      128
#define QKV_N   4096
#define VOFF    3072                     // NH*HD + NKV*HD
#define ATT_SCALE 0.08838834764831845f   // 128^-0.5
#define EPS_RMS 1e-6f
#define LOG2E   1.4426950408889634f

// ---------------- scratch (device globals: allowed) ----------------
__device__ float g_qkv[(size_t)S_LEN * QKV_N];       // 64 MB
__device__ float g_q[(size_t)NH  * S_LEN * HD];      // 32 MB  [h][s][d]
__device__ float g_k[(size_t)NKV * S_LEN * HD];      // 16 MB  [kv][s][d]
__device__ float g_ao[(size_t)S_LEN * (NH * HD)];    // 32 MB  [s][h*128+d]
__device__ uint32_t g_af[(size_t)32 * 64 * 4096];    // 32 MB  A tiles [mb][kb][4096]
__device__ uint32_t g_bf[(size_t)64 * 32 * 4096];    // 32 MB  B tiles [kb][nb][4096]
__device__ uint32_t g_kf[(size_t)NKV * 128 * 4096];  // 16 MB  K tiles [kv][kt32][4096]
__device__ uint32_t g_vf[(size_t)NKV * 128 * 4096];  // 16 MB  V tiles [kv][kt32][4096]

// ---------------- helpers ----------------
__device__ __forceinline__ uint32_t f2tf(float x) {
    uint32_t r;
    asm("cvt.rna.tf32.f32 %0, %1;" : "=r"(r) : "f"(x));
    return r;
}

__device__ __forceinline__ float ex2f(float x) {
    float y;
    asm("ex2.approx.f32 %0, %1;" : "=f"(y) : "f"(x));
    return y;
}

__device__ __forceinline__ void mma8(float c[4], const uint32_t a[4], const uint32_t b[2]) {
    asm volatile(
        "mma.sync.aligned.m16n8k8.row.col.f32.tf32.tf32.f32 "
        "{%0,%1,%2,%3}, {%4,%5,%6,%7}, {%8,%9}, {%0,%1,%2,%3};"
        : "+f"(c[0]), "+f"(c[1]), "+f"(c[2]), "+f"(c[3])
        : "r"(a[0]), "r"(a[1]), "r"(a[2]), "r"(a[3]), "r"(b[0]), "r"(b[1]));
}

__device__ __forceinline__ void cpasync16(uint32_t saddr, const void* gptr) {
    asm volatile("cp.async.cg.shared.global [%0], [%1], 16;"
                 :: "r"(saddr), "l"(gptr));
}
#define CP_COMMIT() asm volatile("cp.async.commit_group;")
#define CP_WAIT1()  asm volatile("cp.async.wait_group 1;")
#define CP_WAIT2()  asm volatile("cp.async.wait_group 2;")

// ================= permute kernels (f32 gmem -> tf32 fragment-layout gmem) ====

// A tiles: [M][K] row-major -> [mb][kb][4096]  (unchanged)
__global__ void permA_kernel(const float* __restrict__ A, uint32_t* __restrict__ out,
                             int M, int K) {
    __shared__ float t[128 * 36];
    const int kb = blockIdx.x, mb = blockIdx.y, nkb = gridDim.x;
    const int tid = threadIdx.x;
#pragma unroll
    for (int p = 0; p < 4; p++) {
        int idx = tid + p * 256;
        int r = idx >> 3, c4 = (idx & 7) * 4;
        float4 v = *(const float4*)&A[(size_t)(mb * 128 + r) * K + kb * 32 + c4];
        *(float4*)&t[r * 36 + c4] = v;
    }
    __syncthreads();
    uint32_t* dst = out + ((size_t)mb * nkb + kb) * 4096;
#pragma unroll
    for (int q = 0; q < 4; q++) {
        int o = q * 1024 + tid * 4;
        int slot = (o >> 2) & 31, frag = o >> 7;
        int rb = (frag & 7) * 16 + (slot >> 2);
        int cb = (frag >> 3) * 8 + (slot & 3);
        uint4 u;
        u.x = f2tf(t[rb * 36 + cb]);
        u.y = f2tf(t[(rb + 8) * 36 + cb]);
        u.z = f2tf(t[rb * 36 + cb + 4]);
        u.w = f2tf(t[(rb + 8) * 36 + cb + 4]);
        *(uint4*)&dst[o] = u;
    }
}

// B tiles: [K][N] row-major -> [kb][nb][4096], PAIRED layout (unchanged from R8)
__global__ void permB_kernel(const float* __restrict__ B, uint32_t* __restrict__ out,
                             int K, int N) {
    __shared__ float t[32 * 132];
    const int nb = blockIdx.x, kb = blockIdx.y, nnb = gridDim.x;
    const int tid = threadIdx.x;
#pragma unroll
    for (int p = 0; p < 4; p++) {
        int idx = tid + p * 256;
        int r = idx >> 5, c4 = (idx & 31) * 4;
        float4 v = *(const float4*)&B[(size_t)(kb * 32 + r) * N + nb * 128 + c4];
        *(float4*)&t[r * 132 + c4] = v;
    }
    __syncthreads();
    uint32_t* dst = out + ((size_t)kb * nnb + nb) * 4096;
#pragma unroll
    for (int q = 0; q < 4; q++) {
        int o = q * 1024 + tid * 4;
        uint32_t u[4];
#pragma unroll
        for (int e = 0; e < 4; e++) {
            int oe = o + e;
            int jl = (oe >> 1) & 1, h = oe & 1;
            int l = (oe >> 2) & 31;
            int nf2 = (oe >> 7) & 7, ks = oe >> 10;
            int nf = 2 * nf2 + jl;
            int r = ks * 8 + h * 4 + (l & 3);
            int c = nf * 8 + (l >> 2);
            u[e] = f2tf(t[r * 132 + c]);
        }
        *(uint4*)&dst[o] = make_uint4(u[0], u[1], u[2], u[3]);
    }
}

// K tiles: g_k [kv][s][d] -> [kv][kt32][4096], PAIRED layout for Bk=32:
// o = ((ks*2 + jj)*32 + lane)*4 + jl*2 + half,  j = 2*jj + jl  (j<4: 32 keys)
// value = K[r][d], r = j*8 + (lane>>2), d = ks*8 + half*4 + (lane&3)
__global__ void permK_kernel(const float* __restrict__ gk, uint32_t* __restrict__ out) {
    __shared__ float t[32 * 132];
    const int kt = blockIdx.x, kv = blockIdx.y;
    const int tid = threadIdx.x;
#pragma unroll
    for (int p = 0; p < 4; p++) {
        int idx = tid + p * 256;
        int r = idx >> 5, c4 = (idx & 31) * 4;
        float4 v = *(const float4*)&gk[((size_t)kv * S_LEN + kt * 32 + r) * HD + c4];
        *(float4*)&t[r * 132 + c4] = v;
    }
    __syncthreads();
    uint32_t* dst = out + ((size_t)kv * (S_LEN / 32) + kt) * 4096;
#pragma unroll
    for (int q = 0; q < 4; q++) {
        int o = q * 1024 + tid * 4;
        uint32_t u[4];
#pragma unroll
        for (int e = 0; e < 4; e++) {
            int oe = o + e;
            int h = oe & 1, jl = (oe >> 1) & 1;
            int l = (oe >> 2) & 31;
            int jj = (oe >> 7) & 1, ks = oe >> 8;       // ks 0..15
            int j = 2 * jj + jl;
            int r = j * 8 + (l >> 2);
            int d = ks * 8 + h * 4 + (l & 3);
            u[e] = f2tf(t[r * 132 + d]);
        }
        *(uint4*)&dst[o] = make_uint4(u[0], u[1], u[2], u[3]);
    }
}

// V tiles: g_qkv strided -> [kv][kt32][4096], PAIRED layout for Bk=32:
// o = ((kk*8 + jj)*32 + lane)*4 + jl*2 + half,  jv = 2*jj + jl  (jv<16: 128 dims)
// value = V[r][d], r = kk*8 + half*4 + (lane&3)  (r<32), d = jv*8 + (lane>>2)
__global__ void permV_kernel(const float* __restrict__ gqkv, uint32_t* __restrict__ out) {
    __shared__ float t[32 * 132];
    const int kt = blockIdx.x, kv = blockIdx.y;
    const int tid = threadIdx.x;
#pragma unroll
    for (int p = 0; p < 4; p++) {
        int idx = tid + p * 256;
        int r = idx >> 5, c4 = (idx & 31) * 4;
        float4 v = *(const float4*)&gqkv[(size_t)(kt * 32 + r) * QKV_N + VOFF + kv * HD + c4];
        *(float4*)&t[r * 132 + c4] = v;
    }
    __syncthreads();
    uint32_t* dst = out + ((size_t)kv * (S_LEN / 32) + kt) * 4096;
#pragma unroll
    for (int q = 0; q < 4; q++) {
        int o = q * 1024 + tid * 4;
        uint32_t u[4];
#pragma unroll
        for (int e = 0; e < 4; e++) {
            int oe = o + e;
            int h = oe & 1, jl = (oe >> 1) & 1;
            int l = (oe >> 2) & 31;
            int jj = (oe >> 7) & 7, kk = oe >> 10;      // kk 0..3
            int jv = 2 * jj + jl;
            int r = kk * 8 + h * 4 + (l & 3);
            int d = jv * 8 + (l >> 2);
            u[e] = f2tf(t[r * 132 + d]);
        }
        *(uint4*)&dst[o] = make_uint4(u[0], u[1], u[2], u[3]);
    }
}

// ================= tf32 GEMM (mma.sync) on pre-permuted tiles (unchanged R8) ===
#define GEMM_SMEM_BYTES (3 * 8192 * 4)

__global__ __launch_bounds__(256, 2)
void gemm_pre(const uint32_t* __restrict__ Af, const uint32_t* __restrict__ Bf,
              float* __restrict__ C, int M, int N, int K) {
    extern __shared__ uint32_t smg[];
    const int tid  = threadIdx.x;
    const int lane = tid & 31;
    const int warp = tid >> 5;
    const int wm = warp >> 2, wn = warp & 3;
    const int g = lane >> 2, t = lane & 3;
    const int mb = blockIdx.y, nb = blockIdx.x;
    const int nkb = K / 32, nnb = N / 128;
    const uint32_t sbase = (uint32_t)__cvta_generic_to_shared(smg);
    const uint32_t* Asrc = Af + (size_t)mb * nkb * 4096;

    auto issue = [&](int kb, int st) {
        uint32_t dst = sbase + (uint32_t)st * 32768;
        const uint32_t* a = Asrc + (size_t)kb * 4096;
        const uint32_t* b = Bf + ((size_t)kb * nnb + nb) * 4096;
#pragma unroll
        for (int p = 0; p < 4; p++) {
            int i = tid + p * 256;
            cpasync16(dst + i * 16, a + i * 4);
            cpasync16(dst + 16384 + i * 16, b + i * 4);
        }
    };

    issue(0, 0); CP_COMMIT();
    issue(1, 1); CP_COMMIT();

    float acc[4][4][4];
#pragma unroll
    for (int i = 0; i < 4; i++)
#pragma unroll
        for (int j = 0; j < 4; j++)
#pragma unroll
            for (int e = 0; e < 4; e++) acc[i][j][e] = 0.f;

    for (int kb = 0; kb < nkb; kb++) {
        CP_WAIT1();
        __syncthreads();
        if (kb + 2 < nkb) issue(kb + 2, (kb + 2) % 3);
        CP_COMMIT();

        const uint32_t* As = smg + (kb % 3) * 8192;
        const uint32_t* Bs = As + 4096;
#pragma unroll
        for (int ks = 0; ks < 4; ks++) {
            uint32_t a[4][4], b[4][2];
#pragma unroll
            for (int i = 0; i < 4; i++) {
                uint4 av = *(const uint4*)&As[((ks * 8 + wm * 4 + i) * 32 + lane) * 4];
                a[i][0] = av.x; a[i][1] = av.y; a[i][2] = av.z; a[i][3] = av.w;
            }
#pragma unroll
            for (int j2 = 0; j2 < 2; j2++) {
                uint4 bv = *(const uint4*)&Bs[((ks * 8 + wn * 2 + j2) * 32 + lane) * 4];
                b[2 * j2][0]     = bv.x; b[2 * j2][1]     = bv.y;
                b[2 * j2 + 1][0] = bv.z; b[2 * j2 + 1][1] = bv.w;
            }
#pragma unroll
            for (int i = 0; i < 4; i++)
#pragma unroll
                for (int j = 0; j < 4; j++)
                    mma8(acc[i][j], a[i], b[j]);
        }
    }

#pragma unroll
    for (int i = 0; i < 4; i++)
#pragma unroll
        for (int j = 0; j < 4; j++) {
            int row0 = mb * 128 + wm * 64 + i * 16 + g;
            int col  = nb * 128 + wn * 32 + j * 8 + 2 * t;
            *(float2*)&C[(size_t)row0 * N + col]       = make_float2(acc[i][j][0], acc[i][j][1]);
            *(float2*)&C[(size_t)(row0 + 8) * N + col] = make_float2(acc[i][j][2], acc[i][j][3]);
        }
}

// ---------------- RMSNorm + mRoPE (unchanged) ----------------
__global__ void normrope_kernel(const float* __restrict__ qkv,
                                const int*   __restrict__ positions,
                                const float* __restrict__ qw,
                                const float* __restrict__ kw,
                                const float* __restrict__ cache,
                                float* __restrict__ gq,
                                float* __restrict__ gk) {
    const int s = blockIdx.x;
    __shared__ float cs[64], sn[64];
    const int tid = threadIdx.x;

    if (tid < 64) {
        int i = tid;
        int m3 = i % 3;
        int sec = (i < 60) ? ((m3 == 1) ? 1 : ((m3 == 2) ? 2 : 0)) : 0;
        int pos = positions[sec * S_LEN + s];
        cs[i] = cache[(size_t)pos * HD + i];
        sn[i] = cache[(size_t)pos * HD + 64 + i];
    }
    __syncthreads();

    const int warp = tid >> 5;
    const int lane = tid & 31;
    const int dbase = lane * 4;

    for (int h = warp; h < NH + NKV; h += 8) {
        const float* src;
        const float* w;
        float* dst;
        if (h < NH) {
            src = qkv + (size_t)s * QKV_N + h * HD;
            w = qw;
            dst = gq + ((size_t)h * S_LEN + s) * HD;
        } else {
            int kh = h - NH;
            src = qkv + (size_t)s * QKV_N + NH * HD + kh * HD;
            w = kw;
            dst = gk + ((size_t)kh * S_LEN + s) * HD;
        }
        float4 xv = *(const float4*)(src + dbase);
        float x[4] = {xv.x, xv.y, xv.z, xv.w};
        float ss = x[0]*x[0] + x[1]*x[1] + x[2]*x[2] + x[3]*x[3];
#pragma unroll
        for (int o = 16; o > 0; o >>= 1)
            ss += __shfl_xor_sync(0xffffffffu, ss, o);
        float inv = rsqrtf(ss * (1.0f / HD) + EPS_RMS);
        float4 wv = *(const float4*)(w + dbase);
        float nx[4] = {x[0]*inv*wv.x, x[1]*inv*wv.y, x[2]*inv*wv.z, x[3]*inv*wv.w};

        float out[4];
        const bool lo = (lane < 16);
#pragma unroll
        for (int j = 0; j < 4; j++) {
            float partner = __shfl_xor_sync(0xffffffffu, nx[j], 16);
            int i2 = (dbase + j) & 63;
            float c = cs[i2], si = sn[i2];
            out[j] = lo ? (nx[j] * c - partner * si)
                        : (nx[j] * c + partner * si);
        }
        *(float4*)(dst + dbase) = make_float4(out[0], out[1], out[2], out[3]);
    }
}

// ================= tf32 flash attention, Bq=64/Bk=32, occ=2 =================
// 128 threads (4 warps); warp w owns rows w*16..w*16+15 (warp-local softmax).
// 3-stage cp.async pipeline, stage = Ks 16KB + Vs 16KB. Ps 8KB.
// smem = 3*8192 + 2048 u32 = 104 KB -> 2 CTAs/SM.
#define ATTN_SMEM_BYTES ((3 * 8192 + 2048) * 4)

__global__ __launch_bounds__(128, 2)
void attn_pre(const float* __restrict__ gq, const uint32_t* __restrict__ Kf,
              const uint32_t* __restrict__ Vf, float* __restrict__ gao) {
    extern __shared__ uint32_t smu[];
    uint32_t* Ps = smu + 3 * 8192;       // [kk=4][w=4][32][4]
    float* Qlin = (float*)smu;           // [64][132] prologue only (aliases stages)

    const int tid  = threadIdx.x;
    const int lane = tid & 31;
    const int w    = tid >> 5;           // 0..3
    const int g = lane >> 2, t = lane & 3;
    const int h  = blockIdx.y;
    const int qt = (int)gridDim.x - 1 - (int)blockIdx.x;   // heavy first
    const int q0 = qt * 64;
    const int kv = h >> 1;
    const int nkt = 2 * qt + 2;          // 32-wide key tiles
    const uint32_t sbase = (uint32_t)__cvta_generic_to_shared(smu);

    // ---- prologue: Q tile (64x128) -> smem linear -> register fragments ----
    const float* qbase = gq + ((size_t)h * S_LEN + q0) * HD;
#pragma unroll
    for (int p = 0; p < 16; p++) {
        int idx = tid + p * 128;
        int r = idx >> 5, c4 = (idx & 31) * 4;
        *(float4*)&Qlin[r * 132 + c4] = *(const float4*)&qbase[(size_t)r * HD + c4];
    }
    __syncthreads();

    const float CC = ATT_SCALE * LOG2E;
    uint32_t aq[16][4];
    {
        int r0 = w * 16 + g;
#pragma unroll
        for (int ks = 0; ks < 16; ks++) {
            aq[ks][0] = f2tf(Qlin[r0 * 132 + ks * 8 + t] * CC);
            aq[ks][1] = f2tf(Qlin[(r0 + 8) * 132 + ks * 8 + t] * CC);
            aq[ks][2] = f2tf(Qlin[r0 * 132 + ks * 8 + t + 4] * CC);
            aq[ks][3] = f2tf(Qlin[(r0 + 8) * 132 + ks * 8 + t + 4] * CC);
        }
    }
    __syncthreads();   // done reading Qlin before cp.async clobbers it

    const uint32_t* Ksrc = Kf + (size_t)kv * (S_LEN / 32) * 4096;
    const uint32_t* Vsrc = Vf + (size_t)kv * (S_LEN / 32) * 4096;
    auto issue = [&](int kt, int st) {
        if (kt < nkt) {
            uint32_t dst = sbase + (uint32_t)st * 32768;
            const uint32_t* kp = Ksrc + (size_t)kt * 4096;
            const uint32_t* vp = Vsrc + (size_t)kt * 4096;
#pragma unroll
            for (int p = 0; p < 8; p++) {
                int i = tid + p * 128;
                cpasync16(dst + i * 16, kp + i * 4);
                cpasync16(dst + 16384 + i * 16, vp + i * 4);
            }
        }
    };
    issue(0, 0); CP_COMMIT();
    issue(1, 1); CP_COMMIT();
    issue(2, 2); CP_COMMIT();

    float oacc[16][4];
#pragma unroll
    for (int j = 0; j < 16; j++)
#pragma unroll
        for (int e = 0; e < 4; e++) oacc[j][e] = 0.f;
    float m2a = -1e30f, m2b = -1e30f;
    float la = 0.f, lb = 0.f;

    const int r0g = q0 + w * 16 + g;

#pragma unroll 1
    for (int kt = 0; kt < nkt; kt++) {
        CP_WAIT2();
        __syncthreads();
        const uint32_t* Ks = smu + (kt % 3) * 8192;
        const uint32_t* Vs = Ks + 4096;

        // ---- scores: 16 rows x 32 keys per warp (paired LDS.128) ----
        float sc[4][4];
#pragma unroll
        for (int j = 0; j < 4; j++)
#pragma unroll
            for (int e = 0; e < 4; e++) sc[j][e] = 0.f;
#pragma unroll
        for (int ks = 0; ks < 16; ks++) {
#pragma unroll
            for (int jj = 0; jj < 2; jj++) {
                uint4 bv = *(const uint4*)&Ks[((ks * 2 + jj) * 32 + lane) * 4];
                uint32_t b0[2] = {bv.x, bv.y};
                uint32_t b1[2] = {bv.z, bv.w};
                mma8(sc[2 * jj],     aq[ks], b0);
                mma8(sc[2 * jj + 1], aq[ks], b1);
            }
        }

        // ---- causal mask (diagonal tiles only) ----
        if (kt >= 2 * qt) {
            const int k0 = kt * 32;
#pragma unroll
            for (int j = 0; j < 4; j++) {
                int c0 = k0 + j * 8 + 2 * t;
                if (c0     > r0g)     sc[j][0] = -1e30f;
                if (c0 + 1 > r0g)     sc[j][1] = -1e30f;
                if (c0     > r0g + 8) sc[j][2] = -1e30f;
                if (c0 + 1 > r0g + 8) sc[j][3] = -1e30f;
            }
        }

        // ---- online softmax (warp-local, quad reduction) ----
        float mx0 = -1e30f, mx1 = -1e30f;
#pragma unroll
        for (int j = 0; j < 4; j++) {
            mx0 = fmaxf(mx0, fmaxf(sc[j][0], sc[j][1]));
            mx1 = fmaxf(mx1, fmaxf(sc[j][2], sc[j][3]));
        }
        mx0 = fmaxf(mx0, __shfl_xor_sync(0xffffffffu, mx0, 1));
        mx0 = fmaxf(mx0, __shfl_xor_sync(0xffffffffu, mx0, 2));
        mx1 = fmaxf(mx1, __shfl_xor_sync(0xffffffffu, mx1, 1));
        mx1 = fmaxf(mx1, __shfl_xor_sync(0xffffffffu, mx1, 2));
        float mn0 = fmaxf(m2a, mx0), mn1 = fmaxf(m2b, mx1);
        float f0 = ex2f(m2a - mn0), f1 = ex2f(m2b - mn1);
        m2a = mn0; m2b = mn1;

        float s0 = 0.f, s1 = 0.f;
#pragma unroll
        for (int j = 0; j < 4; j++) {
            sc[j][0] = ex2f(sc[j][0] - mn0);
            sc[j][1] = ex2f(sc[j][1] - mn0);
            sc[j][2] = ex2f(sc[j][2] - mn1);
            sc[j][3] = ex2f(sc[j][3] - mn1);
            s0 += sc[j][0] + sc[j][1];
            s1 += sc[j][2] + sc[j][3];
        }
        s0 += __shfl_xor_sync(0xffffffffu, s0, 1);
        s0 += __shfl_xor_sync(0xffffffffu, s0, 2);
        s1 += __shfl_xor_sync(0xffffffffu, s1, 1);
        s1 += __shfl_xor_sync(0xffffffffu, s1, 2);
        la = la * f0 + s0;
        lb = lb * f1 + s1;

#pragma unroll
        for (int j = 0; j < 16; j++) {
            oacc[j][0] *= f0; oacc[j][1] *= f0;
            oacc[j][2] *= f1; oacc[j][3] *= f1;
        }

        // ---- store P as A-fragments (warp-private region) ----
        {
            int l0 = g * 4 + ((2 * t) & 3);
            int l1 = g * 4 + ((2 * t + 1) & 3);
            int shi = 2 * (t >> 1);
#pragma unroll
            for (int j = 0; j < 4; j++) {
                uint32_t base = (uint32_t)((j * 4 + w) * 32) * 4;
                Ps[base + l0 * 4 + shi]     = f2tf(sc[j][0]);
                Ps[base + l1 * 4 + shi]     = f2tf(sc[j][1]);
                Ps[base + l0 * 4 + shi + 1] = f2tf(sc[j][2]);
                Ps[base + l1 * 4 + shi + 1] = f2tf(sc[j][3]);
            }
        }
        __syncwarp();

        // ---- O += P @ V (paired LDS.128) ----
#pragma unroll
        for (int kk = 0; kk < 4; kk++) {
            uint4 av = *(const uint4*)&Ps[((kk * 4 + w) * 32 + lane) * 4];
            uint32_t a[4] = {av.x, av.y, av.z, av.w};
#pragma unroll
            for (int jj = 0; jj < 8; jj++) {
                uint4 bv = *(const uint4*)&Vs[((kk * 8 + jj) * 32 + lane) * 4];
                uint32_t b0[2] = {bv.x, bv.y};
                uint32_t b1[2] = {bv.z, bv.w};
                mma8(oacc[2 * jj],     a, b0);
                mma8(oacc[2 * jj + 1], a, b1);
            }
        }
        __syncthreads();          // all warps done with this stage
        issue(kt + 3, kt % 3);    // refill consumed stage
        CP_COMMIT();
    }

    // ---- epilogue ----
    float inv0 = 1.f / la, inv1 = 1.f / lb;
    int row0 = q0 + w * 16 + g;
#pragma unroll
    for (int j = 0; j < 16; j++) {
        int col = h * HD + j * 8 + 2 * t;
        *(float2*)&gao[(size_t)row0 * HDIM + col] =
            make_float2(oacc[j][0] * inv0, oacc[j][1] * inv0);
        *(float2*)&gao[(size_t)(row0 + 8) * HDIM + col] =
            make_float2(oacc[j][2] * inv1, oacc[j][3] * inv1);
    }
}

// ---------------- launch ----------------
extern "C" void kernel_launch(void* const* d_in, const int* in_sizes, int n_in,
                              void* d_out, int out_size) {
    const float* hidden    = (const float*)d_in[0];
    const int*   positions = (const int*)  d_in[1];
    const float* w_qkv     = (const float*)d_in[2];
    const float* w_o       = (const float*)d_in[3];
    const float* q_norm_w  = (const float*)d_in[4];
    const float* k_norm_w  = (const float*)d_in[5];
    const float* cache     = (const float*)d_in[6];
    float* out = (float*)d_out;

    float *qkv_p, *q_p, *k_p, *ao_p;
    uint32_t *af_p, *bf_p, *kf_p, *vf_p;
    cudaGetSymbolAddress((void**)&qkv_p, g_qkv);
    cudaGetSymbolAddress((void**)&q_p,   g_q);
    cudaGetSymbolAddress((void**)&k_p,   g_k);
    cudaGetSymbolAddress((void**)&ao_p,  g_ao);
    cudaGetSymbolAddress((void**)&af_p,  g_af);
    cudaGetSymbolAddress((void**)&bf_p,  g_bf);
    cudaGetSymbolAddress((void**)&kf_p,  g_kf);
    cudaGetSymbolAddress((void**)&vf_p,  g_vf);

    cudaFuncSetAttribute(gemm_pre, cudaFuncAttributeMaxDynamicSharedMemorySize,
                         GEMM_SMEM_BYTES);
    cudaFuncSetAttribute(attn_pre, cudaFuncAttributeMaxDynamicSharedMemorySize,
                         ATTN_SMEM_BYTES);

    // 1) QKV projection
    permA_kernel<<<dim3(64, 32), 256>>>(hidden, af_p, S_LEN, HDIM);
    permB_kernel<<<dim3(32, 64), 256>>>(w_qkv, bf_p, HDIM, QKV_N);
    gemm_pre<<<dim3(32, 32), 256, GEMM_SMEM_BYTES>>>(af_p, bf_p, qkv_p,
                                                     S_LEN, QKV_N, HDIM);

    // 2) RMSNorm + mRoPE
    normrope_kernel<<<S_LEN, 256>>>(qkv_p, positions, q_norm_w, k_norm_w,
                                    cache, q_p, k_p);

    // 3) permute K/V (32-row tiles), flash attention (Bq=64, occ=2)
    permK_kernel<<<dim3(S_LEN / 32, NKV), 256>>>(k_p, kf_p);
    permV_kernel<<<dim3(S_LEN / 32, NKV), 256>>>(qkv_p, vf_p);
    attn_pre<<<dim3(S_LEN / 64, NH), 128, ATTN_SMEM_BYTES>>>(q_p, kf_p, vf_p, ao_p);

    // 4) output projection
    permA_kernel<<<dim3(64, 32), 256>>>(ao_p, af_p, S_LEN, HDIM);
    permB_kernel<<<dim3(16, 64), 256>>>(w_o, bf_p, HDIM, HDIM);
    gemm_pre<<<dim3(16, 32), 256, GEMM_SMEM_BYTES>>>(af_p, bf_p, out,
                                                     S_LEN, HDIM, HDIM);
}

// round 13
// speedup vs baseline: 14.7394x; 1.8070x over previous
#include <cuda_runtime.h>
#include <cuda_fp16.h>
#include <cstdint>
#include <cstddef>

// ---------------- problem constants ----------------
#define S_LEN   4096
#define HDIM    2048
#define NH      16
#define NKV     8
#define HD      128
#define QKV_N   4096
#define VOFF    3072                     // NH*HD + NKV*HD
#define ATT_SCALE 0.08838834764831845f   // 128^-0.5
#define EPS_RMS 1e-6f
#define LOG2E   1.4426950408889634f

// ---------------- scratch (device globals: allowed) ----------------
__device__ float g_qkv[(size_t)S_LEN * QKV_N];       // 64 MB
__device__ float g_q[(size_t)NH  * S_LEN * HD];      // 32 MB  [h][s][d]
__device__ float g_k[(size_t)NKV * S_LEN * HD];      // 16 MB  [kv][s][d]
__device__ float g_ao[(size_t)S_LEN * (NH * HD)];    // 32 MB  [s][h*128+d]
__device__ uint32_t g_af[(size_t)32 * 64 * 2048];    // 16 MB  A tiles (fp16 frags)
__device__ uint32_t g_bf[(size_t)64 * 32 * 2048];    // 16 MB  B tiles (fp16 frags)
__device__ uint32_t g_kf[(size_t)NKV * 128 * 2048];  //  8 MB  K tiles (fp16 frags)
__device__ uint32_t g_vf[(size_t)NKV * 128 * 2048];  //  8 MB  V tiles (fp16 frags)

// ---------------- helpers ----------------
__device__ __forceinline__ uint32_t f2h2(float lo, float hi) {
    __half2 h = __floats2half2_rn(lo, hi);
    return *(uint32_t*)&h;
}

__device__ __forceinline__ float ex2f(float x) {
    float y;
    asm("ex2.approx.f32 %0, %1;" : "=f"(y) : "f"(x));
    return y;
}

// fp16 mma with fp32 accumulate: D(16x8) += A(16x16) * B(16x8)
__device__ __forceinline__ void mma16(float c[4], const uint32_t a[4], const uint32_t b[2]) {
    asm volatile(
        "mma.sync.aligned.m16n8k16.row.col.f32.f16.f16.f32 "
        "{%0,%1,%2,%3}, {%4,%5,%6,%7}, {%8,%9}, {%0,%1,%2,%3};"
        : "+f"(c[0]), "+f"(c[1]), "+f"(c[2]), "+f"(c[3])
        : "r"(a[0]), "r"(a[1]), "r"(a[2]), "r"(a[3]), "r"(b[0]), "r"(b[1]));
}

__device__ __forceinline__ void cpasync16(uint32_t saddr, const void* gptr) {
    asm volatile("cp.async.cg.shared.global [%0], [%1], 16;"
                 :: "r"(saddr), "l"(gptr));
}
#define CP_COMMIT() asm volatile("cp.async.commit_group;")
#define CP_WAIT1()  asm volatile("cp.async.wait_group 1;")
#define CP_WAIT2()  asm volatile("cp.async.wait_group 2;")

// ================= permute kernels (f32 gmem -> fp16 fragment-layout gmem) ====
// Fragment conventions (m16n8k16, g = lane>>2, t2 = (lane&3)*2):
//  A-frag reg r: row = base + (r&1)*8 + g, k = kbase + (r>>1)*8 + t2, pair (k,k+1)
//  B-frag: b0 = (k = t2, t2+1, col g), b1 = (k = t2+8, t2+9, col g)

// A tiles: [M][K] -> [mb][kb][2048], o = ((ks*8 + mf)*32 + lane)*4 + r
__global__ void permA_kernel(const float* __restrict__ A, uint32_t* __restrict__ out,
                             int M, int K) {
    __shared__ float t[128 * 36];
    const int kb = blockIdx.x, mb = blockIdx.y, nkb = gridDim.x;
    const int tid = threadIdx.x;
#pragma unroll
    for (int p = 0; p < 4; p++) {
        int idx = tid + p * 256;
        int r = idx >> 3, c4 = (idx & 7) * 4;
        float4 v = *(const float4*)&A[(size_t)(mb * 128 + r) * K + kb * 32 + c4];
        *(float4*)&t[r * 36 + c4] = v;
    }
    __syncthreads();
    uint32_t* dst = out + ((size_t)mb * nkb + kb) * 2048;
#pragma unroll
    for (int q = 0; q < 2; q++) {
        int o = q * 1024 + tid * 4;
        int lane = (o >> 2) & 31, mf = (o >> 7) & 7, ks = o >> 10;
        int g = lane >> 2, t2 = (lane & 3) * 2;
        int rb = mf * 16 + g, kb2 = ks * 16 + t2;
        uint4 u;
        u.x = f2h2(t[rb * 36 + kb2],           t[rb * 36 + kb2 + 1]);
        u.y = f2h2(t[(rb + 8) * 36 + kb2],     t[(rb + 8) * 36 + kb2 + 1]);
        u.z = f2h2(t[rb * 36 + kb2 + 8],       t[rb * 36 + kb2 + 9]);
        u.w = f2h2(t[(rb + 8) * 36 + kb2 + 8], t[(rb + 8) * 36 + kb2 + 9]);
        *(uint4*)&dst[o] = u;
    }
}

// B tiles: [K][N] -> [kb][nb][2048], o = ((ks*8 + nf2)*32 + lane)*4 + jl*2 + kk2
__global__ void permB_kernel(const float* __restrict__ B, uint32_t* __restrict__ out,
                             int K, int N) {
    __shared__ float t[32 * 132];
    const int nb = blockIdx.x, kb = blockIdx.y, nnb = gridDim.x;
    const int tid = threadIdx.x;
#pragma unroll
    for (int p = 0; p < 4; p++) {
        int idx = tid + p * 256;
        int r = idx >> 5, c4 = (idx & 31) * 4;
        float4 v = *(const float4*)&B[(size_t)(kb * 32 + r) * N + nb * 128 + c4];
        *(float4*)&t[r * 132 + c4] = v;
    }
    __syncthreads();
    uint32_t* dst = out + ((size_t)kb * nnb + nb) * 2048;
#pragma unroll
    for (int q = 0; q < 2; q++) {
        int o = q * 1024 + tid * 4;
        uint32_t u[4];
#pragma unroll
        for (int e = 0; e < 4; e++) {
            int oe = o + e;
            int kk2 = oe & 1, jl = (oe >> 1) & 1;
            int lane = (oe >> 2) & 31;
            int nf2 = (oe >> 7) & 7, ks = oe >> 10;
            int g = lane >> 2, t2 = (lane & 3) * 2;
            int nf = 2 * nf2 + jl;
            int k = ks * 16 + kk2 * 8 + t2;
            int c = nf * 8 + g;
            u[e] = f2h2(t[k * 132 + c], t[(k + 1) * 132 + c]);
        }
        *(uint4*)&dst[o] = make_uint4(u[0], u[1], u[2], u[3]);
    }
}

// K tiles: g_k [kv][s][d] -> [kv][kt32][2048] (B-op of QK^T: k-dim=d, n=keys)
// o = ((ks*2 + jj)*32 + lane)*4 + jl*2 + kk2, j = 2*jj+jl, r = j*8+g, d = ks*16+kk2*8+t2
__global__ void permK_kernel(const float* __restrict__ gk, uint32_t* __restrict__ out) {
    __shared__ float t[32 * 132];
    const int kt = blockIdx.x, kv = blockIdx.y;
    const int tid = threadIdx.x;
#pragma unroll
    for (int p = 0; p < 4; p++) {
        int idx = tid + p * 256;
        int r = idx >> 5, c4 = (idx & 31) * 4;
        float4 v = *(const float4*)&gk[((size_t)kv * S_LEN + kt * 32 + r) * HD + c4];
        *(float4*)&t[r * 132 + c4] = v;
    }
    __syncthreads();
    uint32_t* dst = out + ((size_t)kv * (S_LEN / 32) + kt) * 2048;
#pragma unroll
    for (int q = 0; q < 2; q++) {
        int o = q * 1024 + tid * 4;
        uint32_t u[4];
#pragma unroll
        for (int e = 0; e < 4; e++) {
            int oe = o + e;
            int kk2 = oe & 1, jl = (oe >> 1) & 1;
            int lane = (oe >> 2) & 31;
            int jj = (oe >> 7) & 1, ks = oe >> 8;       // ks 0..7
            int g = lane >> 2, t2 = (lane & 3) * 2;
            int j = 2 * jj + jl;
            int r = j * 8 + g;
            int d = ks * 16 + kk2 * 8 + t2;
            u[e] = f2h2(t[r * 132 + d], t[r * 132 + d + 1]);
        }
        *(uint4*)&dst[o] = make_uint4(u[0], u[1], u[2], u[3]);
    }
}

// V tiles: g_qkv strided -> [kv][kt32][2048] (B-op of PV: k-dim=keys, n=dims)
// o = ((ks*8 + jj)*32 + lane)*4 + jl*2 + kk2, jv = 2*jj+jl, d = jv*8+g, k = ks*16+kk2*8+t2
__global__ void permV_kernel(const float* __restrict__ gqkv, uint32_t* __restrict__ out) {
    __shared__ float t[32 * 132];
    const int kt = blockIdx.x, kv = blockIdx.y;
    const int tid = threadIdx.x;
#pragma unroll
    for (int p = 0; p < 4; p++) {
        int idx = tid + p * 256;
        int r = idx >> 5, c4 = (idx & 31) * 4;
        float4 v = *(const float4*)&gqkv[(size_t)(kt * 32 + r) * QKV_N + VOFF + kv * HD + c4];
        *(float4*)&t[r * 132 + c4] = v;
    }
    __syncthreads();
    uint32_t* dst = out + ((size_t)kv * (S_LEN / 32) + kt) * 2048;
#pragma unroll
    for (int q = 0; q < 2; q++) {
        int o = q * 1024 + tid * 4;
        uint32_t u[4];
#pragma unroll
        for (int e = 0; e < 4; e++) {
            int oe = o + e;
            int kk2 = oe & 1, jl = (oe >> 1) & 1;
            int lane = (oe >> 2) & 31;
            int jj = (oe >> 7) & 7, ks = oe >> 10;      // ks 0..1
            int g = lane >> 2, t2 = (lane & 3) * 2;
            int jv = 2 * jj + jl;
            int d = jv * 8 + g;
            int k = ks * 16 + kk2 * 8 + t2;
            u[e] = f2h2(t[k * 132 + d], t[(k + 1) * 132 + d]);
        }
        *(uint4*)&dst[o] = make_uint4(u[0], u[1], u[2], u[3]);
    }
}

// ================= fp16 GEMM (mma.sync m16n8k16) on pre-permuted tiles ========
// 128x128 CTA tile, BK=32 (2 k16 steps), 3-stage cp.async, stage = 16KB.
#define GEMM_SMEM_BYTES (3 * 4096 * 4)

__global__ __launch_bounds__(256, 2)
void gemm_h(const uint32_t* __restrict__ Af, const uint32_t* __restrict__ Bf,
            float* __restrict__ C, int M, int N, int K) {
    extern __shared__ uint32_t smg[];
    const int tid  = threadIdx.x;
    const int lane = tid & 31;
    const int warp = tid >> 5;
    const int wm = warp >> 2, wn = warp & 3;
    const int g = lane >> 2, t = lane & 3;
    const int mb = blockIdx.y, nb = blockIdx.x;
    const int nkb = K / 32, nnb = N / 128;
    const uint32_t sbase = (uint32_t)__cvta_generic_to_shared(smg);
    const uint32_t* Asrc = Af + (size_t)mb * nkb * 2048;

    auto issue = [&](int kb, int st) {
        uint32_t dst = sbase + (uint32_t)st * 16384;
        const uint32_t* a = Asrc + (size_t)kb * 2048;
        const uint32_t* b = Bf + ((size_t)kb * nnb + nb) * 2048;
#pragma unroll
        for (int p = 0; p < 2; p++) {
            int i = tid + p * 256;
            cpasync16(dst + i * 16, a + i * 4);
            cpasync16(dst + 8192 + i * 16, b + i * 4);
        }
    };

    issue(0, 0); CP_COMMIT();
    issue(1, 1); CP_COMMIT();

    float acc[4][4][4];
#pragma unroll
    for (int i = 0; i < 4; i++)
#pragma unroll
        for (int j = 0; j < 4; j++)
#pragma unroll
            for (int e = 0; e < 4; e++) acc[i][j][e] = 0.f;

    for (int kb = 0; kb < nkb; kb++) {
        CP_WAIT1();
        __syncthreads();
        if (kb + 2 < nkb) issue(kb + 2, (kb + 2) % 3);
        CP_COMMIT();

        const uint32_t* As = smg + (kb % 3) * 4096;
        const uint32_t* Bs = As + 2048;
#pragma unroll
        for (int ks = 0; ks < 2; ks++) {
            uint32_t a[4][4];
#pragma unroll
            for (int i = 0; i < 4; i++) {
                uint4 av = *(const uint4*)&As[((ks * 8 + wm * 4 + i) * 32 + lane) * 4];
                a[i][0] = av.x; a[i][1] = av.y; a[i][2] = av.z; a[i][3] = av.w;
            }
#pragma unroll
            for (int j2 = 0; j2 < 2; j2++) {
                uint4 bv = *(const uint4*)&Bs[((ks * 8 + wn * 2 + j2) * 32 + lane) * 4];
                uint32_t b0[2] = {bv.x, bv.y};
                uint32_t b1[2] = {bv.z, bv.w};
#pragma unroll
                for (int i = 0; i < 4; i++) {
                    mma16(acc[i][2 * j2],     a[i], b0);
                    mma16(acc[i][2 * j2 + 1], a[i], b1);
                }
            }
        }
    }

#pragma unroll
    for (int i = 0; i < 4; i++)
#pragma unroll
        for (int j = 0; j < 4; j++) {
            int row0 = mb * 128 + wm * 64 + i * 16 + g;
            int col  = nb * 128 + wn * 32 + j * 8 + 2 * t;
            *(float2*)&C[(size_t)row0 * N + col]       = make_float2(acc[i][j][0], acc[i][j][1]);
            *(float2*)&C[(size_t)(row0 + 8) * N + col] = make_float2(acc[i][j][2], acc[i][j][3]);
        }
}

// ---------------- RMSNorm + mRoPE (unchanged) ----------------
__global__ void normrope_kernel(const float* __restrict__ qkv,
                                const int*   __restrict__ positions,
                                const float* __restrict__ qw,
                                const float* __restrict__ kw,
                                const float* __restrict__ cache,
                                float* __restrict__ gq,
                                float* __restrict__ gk) {
    const int s = blockIdx.x;
    __shared__ float cs[64], sn[64];
    const int tid = threadIdx.x;

    if (tid < 64) {
        int i = tid;
        int m3 = i % 3;
        int sec = (i < 60) ? ((m3 == 1) ? 1 : ((m3 == 2) ? 2 : 0)) : 0;
        int pos = positions[sec * S_LEN + s];
        cs[i] = cache[(size_t)pos * HD + i];
        sn[i] = cache[(size_t)pos * HD + 64 + i];
    }
    __syncthreads();

    const int warp = tid >> 5;
    const int lane = tid & 31;
    const int dbase = lane * 4;

    for (int h = warp; h < NH + NKV; h += 8) {
        const float* src;
        const float* w;
        float* dst;
        if (h < NH) {
            src = qkv + (size_t)s * QKV_N + h * HD;
            w = qw;
            dst = gq + ((size_t)h * S_LEN + s) * HD;
        } else {
            int kh = h - NH;
            src = qkv + (size_t)s * QKV_N + NH * HD + kh * HD;
            w = kw;
            dst = gk + ((size_t)kh * S_LEN + s) * HD;
        }
        float4 xv = *(const float4*)(src + dbase);
        float x[4] = {xv.x, xv.y, xv.z, xv.w};
        float ss = x[0]*x[0] + x[1]*x[1] + x[2]*x[2] + x[3]*x[3];
#pragma unroll
        for (int o = 16; o > 0; o >>= 1)
            ss += __shfl_xor_sync(0xffffffffu, ss, o);
        float inv = rsqrtf(ss * (1.0f / HD) + EPS_RMS);
        float4 wv = *(const float4*)(w + dbase);
        float nx[4] = {x[0]*inv*wv.x, x[1]*inv*wv.y, x[2]*inv*wv.z, x[3]*inv*wv.w};

        float out[4];
        const bool lo = (lane < 16);
#pragma unroll
        for (int j = 0; j < 4; j++) {
            float partner = __shfl_xor_sync(0xffffffffu, nx[j], 16);
            int i2 = (dbase + j) & 63;
            float c = cs[i2], si = sn[i2];
            out[j] = lo ? (nx[j] * c - partner * si)
                        : (nx[j] * c + partner * si);
        }
        *(float4*)(dst + dbase) = make_float4(out[0], out[1], out[2], out[3]);
    }
}

// ================= fp16 flash attention, Bq=64/Bk=32 =================
// 128 threads (4 warps); warp w owns rows w*16..w*16+15 (warp-local softmax).
// P stays in registers (fragment layout == softmax output layout). No Ps smem.
// 3-stage cp.async pipeline, stage = Ks 8KB + Vs 8KB.
#define ATTN_SMEM_BYTES (3 * 4096 * 4)

__global__ __launch_bounds__(128, 3)
void attn_h(const float* __restrict__ gq, const uint32_t* __restrict__ Kf,
            const uint32_t* __restrict__ Vf, float* __restrict__ gao) {
    extern __shared__ uint32_t smu[];
    float* Qlin = (float*)smu;           // [64][132] prologue only (aliases stages)

    const int tid  = threadIdx.x;
    const int lane = tid & 31;
    const int w    = tid >> 5;           // 0..3
    const int g = lane >> 2, t = lane & 3;
    const int h  = blockIdx.y;
    const int qt = (int)gridDim.x - 1 - (int)blockIdx.x;   // heavy first
    const int q0 = qt * 64;
    const int kv = h >> 1;
    const int nkt = 2 * qt + 2;          // 32-wide key tiles
    const uint32_t sbase = (uint32_t)__cvta_generic_to_shared(smu);

    // ---- prologue: Q tile (64x128) -> smem linear -> fp16 fragments ----
    const float* qbase = gq + ((size_t)h * S_LEN + q0) * HD;
#pragma unroll
    for (int p = 0; p < 16; p++) {
        int idx = tid + p * 128;
        int r = idx >> 5, c4 = (idx & 31) * 4;
        *(float4*)&Qlin[r * 132 + c4] = *(const float4*)&qbase[(size_t)r * HD + c4];
    }
    __syncthreads();

    const float CC = ATT_SCALE * LOG2E;
    uint32_t aq[8][4];
    {
        int r0 = w * 16 + g;
        int t2 = t * 2;
#pragma unroll
        for (int ks = 0; ks < 8; ks++) {
            int kb = ks * 16 + t2;
            aq[ks][0] = f2h2(Qlin[r0 * 132 + kb] * CC,           Qlin[r0 * 132 + kb + 1] * CC);
            aq[ks][1] = f2h2(Qlin[(r0 + 8) * 132 + kb] * CC,     Qlin[(r0 + 8) * 132 + kb + 1] * CC);
            aq[ks][2] = f2h2(Qlin[r0 * 132 + kb + 8] * CC,       Qlin[r0 * 132 + kb + 9] * CC);
            aq[ks][3] = f2h2(Qlin[(r0 + 8) * 132 + kb + 8] * CC, Qlin[(r0 + 8) * 132 + kb + 9] * CC);
        }
    }
    __syncthreads();   // done reading Qlin before cp.async clobbers it

    const uint32_t* Ksrc = Kf + (size_t)kv * (S_LEN / 32) * 2048;
    const uint32_t* Vsrc = Vf + (size_t)kv * (S_LEN / 32) * 2048;
    auto issue = [&](int kt, int st) {
        if (kt < nkt) {
            uint32_t dst = sbase + (uint32_t)st * 16384;
            const uint32_t* kp = Ksrc + (size_t)kt * 2048;
            const uint32_t* vp = Vsrc + (size_t)kt * 2048;
#pragma unroll
            for (int p = 0; p < 4; p++) {
                int i = tid + p * 128;
                cpasync16(dst + i * 16, kp + i * 4);
                cpasync16(dst + 8192 + i * 16, vp + i * 4);
            }
        }
    };
    issue(0, 0); CP_COMMIT();
    issue(1, 1); CP_COMMIT();
    issue(2, 2); CP_COMMIT();

    float oacc[16][4];
#pragma unroll
    for (int j = 0; j < 16; j++)
#pragma unroll
        for (int e = 0; e < 4; e++) oacc[j][e] = 0.f;
    float m2a = -1e30f, m2b = -1e30f;
    float la = 0.f, lb = 0.f;

    const int r0g = q0 + w * 16 + g;

#pragma unroll 1
    for (int kt = 0; kt < nkt; kt++) {
        CP_WAIT2();
        __syncthreads();
        const uint32_t* Ks = smu + (kt % 3) * 4096;
        const uint32_t* Vs = Ks + 2048;

        // ---- scores: 16 rows x 32 keys per warp ----
        float sc[4][4];
#pragma unroll
        for (int j = 0; j < 4; j++)
#pragma unroll
            for (int e = 0; e < 4; e++) sc[j][e] = 0.f;
#pragma unroll
        for (int ks = 0; ks < 8; ks++) {
#pragma unroll
            for (int jj = 0; jj < 2; jj++) {
                uint4 bv = *(const uint4*)&Ks[((ks * 2 + jj) * 32 + lane) * 4];
                uint32_t b0[2] = {bv.x, bv.y};
                uint32_t b1[2] = {bv.z, bv.w};
                mma16(sc[2 * jj],     aq[ks], b0);
                mma16(sc[2 * jj + 1], aq[ks], b1);
            }
        }

        // ---- causal mask (diagonal tiles only) ----
        if (kt >= 2 * qt) {
            const int k0 = kt * 32;
#pragma unroll
            for (int j = 0; j < 4; j++) {
                int c0 = k0 + j * 8 + 2 * t;
                if (c0     > r0g)     sc[j][0] = -1e30f;
                if (c0 + 1 > r0g)     sc[j][1] = -1e30f;
                if (c0     > r0g + 8) sc[j][2] = -1e30f;
                if (c0 + 1 > r0g + 8) sc[j][3] = -1e30f;
            }
        }

        // ---- online softmax (warp-local, quad reduction) ----
        float mx0 = -1e30f, mx1 = -1e30f;
#pragma unroll
        for (int j = 0; j < 4; j++) {
            mx0 = fmaxf(mx0, fmaxf(sc[j][0], sc[j][1]));
            mx1 = fmaxf(mx1, fmaxf(sc[j][2], sc[j][3]));
        }
        mx0 = fmaxf(mx0, __shfl_xor_sync(0xffffffffu, mx0, 1));
        mx0 = fmaxf(mx0, __shfl_xor_sync(0xffffffffu, mx0, 2));
        mx1 = fmaxf(mx1, __shfl_xor_sync(0xffffffffu, mx1, 1));
        mx1 = fmaxf(mx1, __shfl_xor_sync(0xffffffffu, mx1, 2));
        float mn0 = fmaxf(m2a, mx0), mn1 = fmaxf(m2b, mx1);
        float f0 = ex2f(m2a - mn0), f1 = ex2f(m2b - mn1);
        m2a = mn0; m2b = mn1;

        float s0 = 0.f, s1 = 0.f;
#pragma unroll
        for (int j = 0; j < 4; j++) {
            sc[j][0] = ex2f(sc[j][0] - mn0);
            sc[j][1] = ex2f(sc[j][1] - mn0);
            sc[j][2] = ex2f(sc[j][2] - mn1);
            sc[j][3] = ex2f(sc[j][3] - mn1);
            s0 += sc[j][0] + sc[j][1];
            s1 += sc[j][2] + sc[j][3];
        }
        s0 += __shfl_xor_sync(0xffffffffu, s0, 1);
        s0 += __shfl_xor_sync(0xffffffffu, s0, 2);
        s1 += __shfl_xor_sync(0xffffffffu, s1, 1);
        s1 += __shfl_xor_sync(0xffffffffu, s1, 2);
        la = la * f0 + s0;
        lb = lb * f1 + s1;

#pragma unroll
        for (int j = 0; j < 16; j++) {
            oacc[j][0] *= f0; oacc[j][1] *= f0;
            oacc[j][2] *= f1; oacc[j][3] *= f1;
        }

        // ---- P fragments directly from sc (no smem roundtrip) ----
        uint32_t pa[2][4];
#pragma unroll
        for (int ks2 = 0; ks2 < 2; ks2++) {
            pa[ks2][0] = f2h2(sc[2 * ks2][0],     sc[2 * ks2][1]);
            pa[ks2][1] = f2h2(sc[2 * ks2][2],     sc[2 * ks2][3]);
            pa[ks2][2] = f2h2(sc[2 * ks2 + 1][0], sc[2 * ks2 + 1][1]);
            pa[ks2][3] = f2h2(sc[2 * ks2 + 1][2], sc[2 * ks2 + 1][3]);
        }

        // ---- O += P @ V ----
#pragma unroll
        for (int ks2 = 0; ks2 < 2; ks2++) {
#pragma unroll
            for (int jj = 0; jj < 8; jj++) {
                uint4 bv = *(const uint4*)&Vs[((ks2 * 8 + jj) * 32 + lane) * 4];
                uint32_t b0[2] = {bv.x, bv.y};
                uint32_t b1[2] = {bv.z, bv.w};
                mma16(oacc[2 * jj],     pa[ks2], b0);
                mma16(oacc[2 * jj + 1], pa[ks2], b1);
            }
        }
        __syncthreads();          // all warps done with this stage
        issue(kt + 3, kt % 3);    // refill consumed stage
        CP_COMMIT();
    }

    // ---- epilogue ----
    float inv0 = 1.f / la, inv1 = 1.f / lb;
    int row0 = q0 + w * 16 + g;
#pragma unroll
    for (int j = 0; j < 16; j++) {
        int col = h * HD + j * 8 + 2 * t;
        *(float2*)&gao[(size_t)row0 * HDIM + col] =
            make_float2(oacc[j][0] * inv0, oacc[j][1] * inv0);
        *(float2*)&gao[(size_t)(row0 + 8) * HDIM + col] =
            make_float2(oacc[j][2] * inv1, oacc[j][3] * inv1);
    }
}

// ---------------- launch ----------------
extern "C" void kernel_launch(void* const* d_in, const int* in_sizes, int n_in,
                              void* d_out, int out_size) {
    const float* hidden    = (const float*)d_in[0];
    const int*   positions = (const int*)  d_in[1];
    const float* w_qkv     = (const float*)d_in[2];
    const float* w_o       = (const float*)d_in[3];
    const float* q_norm_w  = (const float*)d_in[4];
    const float* k_norm_w  = (const float*)d_in[5];
    const float* cache     = (const float*)d_in[6];
    float* out = (float*)d_out;

    float *qkv_p, *q_p, *k_p, *ao_p;
    uint32_t *af_p, *bf_p, *kf_p, *vf_p;
    cudaGetSymbolAddress((void**)&qkv_p, g_qkv);
    cudaGetSymbolAddress((void**)&q_p,   g_q);
    cudaGetSymbolAddress((void**)&k_p,   g_k);
    cudaGetSymbolAddress((void**)&ao_p,  g_ao);
    cudaGetSymbolAddress((void**)&af_p,  g_af);
    cudaGetSymbolAddress((void**)&bf_p,  g_bf);
    cudaGetSymbolAddress((void**)&kf_p,  g_kf);
    cudaGetSymbolAddress((void**)&vf_p,  g_vf);

    cudaFuncSetAttribute(gemm_h, cudaFuncAttributeMaxDynamicSharedMemorySize,
                         GEMM_SMEM_BYTES);
    cudaFuncSetAttribute(attn_h, cudaFuncAttributeMaxDynamicSharedMemorySize,
                         ATTN_SMEM_BYTES);

    // 1) QKV projection (fp16 tensor cores)
    permA_kernel<<<dim3(64, 32), 256>>>(hidden, af_p, S_LEN, HDIM);
    permB_kernel<<<dim3(32, 64), 256>>>(w_qkv, bf_p, HDIM, QKV_N);
    gemm_h<<<dim3(32, 32), 256, GEMM_SMEM_BYTES>>>(af_p, bf_p, qkv_p,
                                                   S_LEN, QKV_N, HDIM);

    // 2) RMSNorm + mRoPE
    normrope_kernel<<<S_LEN, 256>>>(qkv_p, positions, q_norm_w, k_norm_w,
                                    cache, q_p, k_p);

    // 3) permute K/V, flash attention (fp16)
    permK_kernel<<<dim3(S_LEN / 32, NKV), 256>>>(k_p, kf_p);
    permV_kernel<<<dim3(S_LEN / 32, NKV), 256>>>(qkv_p, vf_p);
    attn_h<<<dim3(S_LEN / 64, NH), 128, ATTN_SMEM_BYTES>>>(q_p, kf_p, vf_p, ao_p);

    // 4) output projection (fp16 tensor cores)
    permA_kernel<<<dim3(64, 32), 256>>>(ao_p, af_p, S_LEN, HDIM);
    permB_kernel<<<dim3(16, 64), 256>>>(w_o, bf_p, HDIM, HDIM);
    gemm_h<<<dim3(16, 32), 256, GEMM_SMEM_BYTES>>>(af_p, bf_p, out,
                                                   S_LEN, HDIM, HDIM);
}

// round 14
// speedup vs baseline: 14.8010x; 1.0042x over previous
#include <cuda_runtime.h>
#include <cuda_fp16.h>
#include <cstdint>
#include <cstddef>

// ---------------- problem constants ----------------
#define S_LEN   4096
#define HDIM    2048
#define NH      16
#define NKV     8
#define HD      128
#define QKV_N   4096
#define VOFF    3072                     // NH*HD + NKV*HD
#define ATT_SCALE 0.08838834764831845f   // 128^-0.5
#define EPS_RMS 1e-6f
#define LOG2E   1.4426950408889634f

// ---------------- scratch (device globals: allowed) ----------------
__device__ float g_qkv[(size_t)S_LEN * QKV_N];       // 64 MB
__device__ float g_q[(size_t)NH  * S_LEN * HD];      // 32 MB  [h][s][d]
__device__ float g_k[(size_t)NKV * S_LEN * HD];      // 16 MB  [kv][s][d]
__device__ float g_ao[(size_t)S_LEN * (NH * HD)];    // 32 MB  [s][h*128+d]
__device__ uint32_t g_af[(size_t)32 * 64 * 2048];    // 16 MB  A tiles (fp16 frags)
__device__ uint32_t g_bf[(size_t)64 * 32 * 2048];    // 16 MB  B tiles (fp16 frags)
__device__ uint32_t g_kf[(size_t)NKV * 128 * 2048];  //  8 MB  K tiles (fp16 frags)
__device__ uint32_t g_vf[(size_t)NKV * 128 * 2048];  //  8 MB  V tiles (fp16 frags)

// ---------------- helpers ----------------
__device__ __forceinline__ uint32_t f2h2(float lo, float hi) {
    __half2 h = __floats2half2_rn(lo, hi);
    return *(uint32_t*)&h;
}

__device__ __forceinline__ float ex2f(float x) {
    float y;
    asm("ex2.approx.f32 %0, %1;" : "=f"(y) : "f"(x));
    return y;
}

// fp16 mma with fp32 accumulate: D(16x8) += A(16x16) * B(16x8)
__device__ __forceinline__ void mma16(float c[4], const uint32_t a[4], const uint32_t b[2]) {
    asm volatile(
        "mma.sync.aligned.m16n8k16.row.col.f32.f16.f16.f32 "
        "{%0,%1,%2,%3}, {%4,%5,%6,%7}, {%8,%9}, {%0,%1,%2,%3};"
        : "+f"(c[0]), "+f"(c[1]), "+f"(c[2]), "+f"(c[3])
        : "r"(a[0]), "r"(a[1]), "r"(a[2]), "r"(a[3]), "r"(b[0]), "r"(b[1]));
}

__device__ __forceinline__ void cpasync16(uint32_t saddr, const void* gptr) {
    asm volatile("cp.async.cg.shared.global [%0], [%1], 16;"
                 :: "r"(saddr), "l"(gptr));
}
#define CP_COMMIT() asm volatile("cp.async.commit_group;")
#define CP_WAIT1()  asm volatile("cp.async.wait_group 1;")
#define CP_WAIT2()  asm volatile("cp.async.wait_group 2;")

// ================= permute kernels (f32 gmem -> fp16 fragment-layout gmem) ====
// Fragment conventions (m16n8k16, g = lane>>2, t2 = (lane&3)*2):
//  A-frag reg r: row = base + (r&1)*8 + g, k = kbase + (r>>1)*8 + t2, pair (k,k+1)
//  B-frag: b0 = (k = t2, t2+1, col g), b1 = (k = t2+8, t2+9, col g)

// A tiles: [M][K] -> [mb][kb][2048], o = ((ks*8 + mf)*32 + lane)*4 + r
__global__ void permA_kernel(const float* __restrict__ A, uint32_t* __restrict__ out,
                             int M, int K) {
    __shared__ float t[128 * 36];
    const int kb = blockIdx.x, mb = blockIdx.y, nkb = gridDim.x;
    const int tid = threadIdx.x;
#pragma unroll
    for (int p = 0; p < 4; p++) {
        int idx = tid + p * 256;
        int r = idx >> 3, c4 = (idx & 7) * 4;
        float4 v = *(const float4*)&A[(size_t)(mb * 128 + r) * K + kb * 32 + c4];
        *(float4*)&t[r * 36 + c4] = v;
    }
    __syncthreads();
    uint32_t* dst = out + ((size_t)mb * nkb + kb) * 2048;
#pragma unroll
    for (int q = 0; q < 2; q++) {
        int o = q * 1024 + tid * 4;
        int lane = (o >> 2) & 31, mf = (o >> 7) & 7, ks = o >> 10;
        int g = lane >> 2, t2 = (lane & 3) * 2;
        int rb = mf * 16 + g, kb2 = ks * 16 + t2;
        uint4 u;
        u.x = f2h2(t[rb * 36 + kb2],           t[rb * 36 + kb2 + 1]);
        u.y = f2h2(t[(rb + 8) * 36 + kb2],     t[(rb + 8) * 36 + kb2 + 1]);
        u.z = f2h2(t[rb * 36 + kb2 + 8],       t[rb * 36 + kb2 + 9]);
        u.w = f2h2(t[(rb + 8) * 36 + kb2 + 8], t[(rb + 8) * 36 + kb2 + 9]);
        *(uint4*)&dst[o] = u;
    }
}

// B tiles: [K][N] -> [kb][nb][2048], o = ((ks*8 + nf2)*32 + lane)*4 + jl*2 + kk2
__global__ void permB_kernel(const float* __restrict__ B, uint32_t* __restrict__ out,
                             int K, int N) {
    __shared__ float t[32 * 132];
    const int nb = blockIdx.x, kb = blockIdx.y, nnb = gridDim.x;
    const int tid = threadIdx.x;
#pragma unroll
    for (int p = 0; p < 4; p++) {
        int idx = tid + p * 256;
        int r = idx >> 5, c4 = (idx & 31) * 4;
        float4 v = *(const float4*)&B[(size_t)(kb * 32 + r) * N + nb * 128 + c4];
        *(float4*)&t[r * 132 + c4] = v;
    }
    __syncthreads();
    uint32_t* dst = out + ((size_t)kb * nnb + nb) * 2048;
#pragma unroll
    for (int q = 0; q < 2; q++) {
        int o = q * 1024 + tid * 4;
        uint32_t u[4];
#pragma unroll
        for (int e = 0; e < 4; e++) {
            int oe = o + e;
            int kk2 = oe & 1, jl = (oe >> 1) & 1;
            int lane = (oe >> 2) & 31;
            int nf2 = (oe >> 7) & 7, ks = oe >> 10;
            int g = lane >> 2, t2 = (lane & 3) * 2;
            int nf = 2 * nf2 + jl;
            int k = ks * 16 + kk2 * 8 + t2;
            int c = nf * 8 + g;
            u[e] = f2h2(t[k * 132 + c], t[(k + 1) * 132 + c]);
        }
        *(uint4*)&dst[o] = make_uint4(u[0], u[1], u[2], u[3]);
    }
}

// K tiles: g_k [kv][s][d] -> [kv][kt32][2048] (B-op of QK^T: k-dim=d, n=keys)
// o = ((ks*2 + jj)*32 + lane)*4 + jl*2 + kk2, j = 2*jj+jl, r = j*8+g, d = ks*16+kk2*8+t2
__global__ void permK_kernel(const float* __restrict__ gk, uint32_t* __restrict__ out) {
    __shared__ float t[32 * 132];
    const int kt = blockIdx.x, kv = blockIdx.y;
    const int tid = threadIdx.x;
#pragma unroll
    for (int p = 0; p < 4; p++) {
        int idx = tid + p * 256;
        int r = idx >> 5, c4 = (idx & 31) * 4;
        float4 v = *(const float4*)&gk[((size_t)kv * S_LEN + kt * 32 + r) * HD + c4];
        *(float4*)&t[r * 132 + c4] = v;
    }
    __syncthreads();
    uint32_t* dst = out + ((size_t)kv * (S_LEN / 32) + kt) * 2048;
#pragma unroll
    for (int q = 0; q < 2; q++) {
        int o = q * 1024 + tid * 4;
        uint32_t u[4];
#pragma unroll
        for (int e = 0; e < 4; e++) {
            int oe = o + e;
            int kk2 = oe & 1, jl = (oe >> 1) & 1;
            int lane = (oe >> 2) & 31;
            int jj = (oe >> 7) & 1, ks = oe >> 8;       // ks 0..7
            int g = lane >> 2, t2 = (lane & 3) * 2;
            int j = 2 * jj + jl;
            int r = j * 8 + g;
            int d = ks * 16 + kk2 * 8 + t2;
            u[e] = f2h2(t[r * 132 + d], t[r * 132 + d + 1]);
        }
        *(uint4*)&dst[o] = make_uint4(u[0], u[1], u[2], u[3]);
    }
}

// V tiles: g_qkv strided -> [kv][kt32][2048] (B-op of PV: k-dim=keys, n=dims)
// o = ((ks*8 + jj)*32 + lane)*4 + jl*2 + kk2, jv = 2*jj+jl, d = jv*8+g, k = ks*16+kk2*8+t2
__global__ void permV_kernel(const float* __restrict__ gqkv, uint32_t* __restrict__ out) {
    __shared__ float t[32 * 132];
    const int kt = blockIdx.x, kv = blockIdx.y;
    const int tid = threadIdx.x;
#pragma unroll
    for (int p = 0; p < 4; p++) {
        int idx = tid + p * 256;
        int r = idx >> 5, c4 = (idx & 31) * 4;
        float4 v = *(const float4*)&gqkv[(size_t)(kt * 32 + r) * QKV_N + VOFF + kv * HD + c4];
        *(float4*)&t[r * 132 + c4] = v;
    }
    __syncthreads();
    uint32_t* dst = out + ((size_t)kv * (S_LEN / 32) + kt) * 2048;
#pragma unroll
    for (int q = 0; q < 2; q++) {
        int o = q * 1024 + tid * 4;
        uint32_t u[4];
#pragma unroll
        for (int e = 0; e < 4; e++) {
            int oe = o + e;
            int kk2 = oe & 1, jl = (oe >> 1) & 1;
            int lane = (oe >> 2) & 31;
            int jj = (oe >> 7) & 7, ks = oe >> 10;      // ks 0..1
            int g = lane >> 2, t2 = (lane & 3) * 2;
            int jv = 2 * jj + jl;
            int d = jv * 8 + g;
            int k = ks * 16 + kk2 * 8 + t2;
            u[e] = f2h2(t[k * 132 + d], t[(k + 1) * 132 + d]);
        }
        *(uint4*)&dst[o] = make_uint4(u[0], u[1], u[2], u[3]);
    }
}

// ================= fp16 GEMM (mma.sync m16n8k16) on pre-permuted tiles ========
// 128x128 CTA tile, BK=32 (2 k16 steps), 3-stage cp.async, stage = 16KB.
#define GEMM_SMEM_BYTES (3 * 4096 * 4)

__global__ __launch_bounds__(256, 2)
void gemm_h(const uint32_t* __restrict__ Af, const uint32_t* __restrict__ Bf,
            float* __restrict__ C, int M, int N, int K) {
    extern __shared__ uint32_t smg[];
    const int tid  = threadIdx.x;
    const int lane = tid & 31;
    const int warp = tid >> 5;
    const int wm = warp >> 2, wn = warp & 3;
    const int g = lane >> 2, t = lane & 3;
    const int mb = blockIdx.y, nb = blockIdx.x;
    const int nkb = K / 32, nnb = N / 128;
    const uint32_t sbase = (uint32_t)__cvta_generic_to_shared(smg);
    const uint32_t* Asrc = Af + (size_t)mb * nkb * 2048;

    auto issue = [&](int kb, int st) {
        uint32_t dst = sbase + (uint32_t)st * 16384;
        const uint32_t* a = Asrc + (size_t)kb * 2048;
        const uint32_t* b = Bf + ((size_t)kb * nnb + nb) * 2048;
#pragma unroll
        for (int p = 0; p < 2; p++) {
            int i = tid + p * 256;
            cpasync16(dst + i * 16, a + i * 4);
            cpasync16(dst + 8192 + i * 16, b + i * 4);
        }
    };

    issue(0, 0); CP_COMMIT();
    issue(1, 1); CP_COMMIT();

    float acc[4][4][4];
#pragma unroll
    for (int i = 0; i < 4; i++)
#pragma unroll
        for (int j = 0; j < 4; j++)
#pragma unroll
            for (int e = 0; e < 4; e++) acc[i][j][e] = 0.f;

    for (int kb = 0; kb < nkb; kb++) {
        CP_WAIT1();
        __syncthreads();
        if (kb + 2 < nkb) issue(kb + 2, (kb + 2) % 3);
        CP_COMMIT();

        const uint32_t* As = smg + (kb % 3) * 4096;
        const uint32_t* Bs = As + 2048;
#pragma unroll
        for (int ks = 0; ks < 2; ks++) {
            uint32_t a[4][4];
#pragma unroll
            for (int i = 0; i < 4; i++) {
                uint4 av = *(const uint4*)&As[((ks * 8 + wm * 4 + i) * 32 + lane) * 4];
                a[i][0] = av.x; a[i][1] = av.y; a[i][2] = av.z; a[i][3] = av.w;
            }
#pragma unroll
            for (int j2 = 0; j2 < 2; j2++) {
                uint4 bv = *(const uint4*)&Bs[((ks * 8 + wn * 2 + j2) * 32 + lane) * 4];
                uint32_t b0[2] = {bv.x, bv.y};
                uint32_t b1[2] = {bv.z, bv.w};
#pragma unroll
                for (int i = 0; i < 4; i++) {
                    mma16(acc[i][2 * j2],     a[i], b0);
                    mma16(acc[i][2 * j2 + 1], a[i], b1);
                }
            }
        }
    }

#pragma unroll
    for (int i = 0; i < 4; i++)
#pragma unroll
        for (int j = 0; j < 4; j++) {
            int row0 = mb * 128 + wm * 64 + i * 16 + g;
            int col  = nb * 128 + wn * 32 + j * 8 + 2 * t;
            *(float2*)&C[(size_t)row0 * N + col]       = make_float2(acc[i][j][0], acc[i][j][1]);
            *(float2*)&C[(size_t)(row0 + 8) * N + col] = make_float2(acc[i][j][2], acc[i][j][3]);
        }
}

// ---------------- RMSNorm + mRoPE (unchanged) ----------------
__global__ void normrope_kernel(const float* __restrict__ qkv,
                                const int*   __restrict__ positions,
                                const float* __restrict__ qw,
                                const float* __restrict__ kw,
                                const float* __restrict__ cache,
                                float* __restrict__ gq,
                                float* __restrict__ gk) {
    const int s = blockIdx.x;
    __shared__ float cs[64], sn[64];
    const int tid = threadIdx.x;

    if (tid < 64) {
        int i = tid;
        int m3 = i % 3;
        int sec = (i < 60) ? ((m3 == 1) ? 1 : ((m3 == 2) ? 2 : 0)) : 0;
        int pos = positions[sec * S_LEN + s];
        cs[i] = cache[(size_t)pos * HD + i];
        sn[i] = cache[(size_t)pos * HD + 64 + i];
    }
    __syncthreads();

    const int warp = tid >> 5;
    const int lane = tid & 31;
    const int dbase = lane * 4;

    for (int h = warp; h < NH + NKV; h += 8) {
        const float* src;
        const float* w;
        float* dst;
        if (h < NH) {
            src = qkv + (size_t)s * QKV_N + h * HD;
            w = qw;
            dst = gq + ((size_t)h * S_LEN + s) * HD;
        } else {
            int kh = h - NH;
            src = qkv + (size_t)s * QKV_N + NH * HD + kh * HD;
            w = kw;
            dst = gk + ((size_t)kh * S_LEN + s) * HD;
        }
        float4 xv = *(const float4*)(src + dbase);
        float x[4] = {xv.x, xv.y, xv.z, xv.w};
        float ss = x[0]*x[0] + x[1]*x[1] + x[2]*x[2] + x[3]*x[3];
#pragma unroll
        for (int o = 16; o > 0; o >>= 1)
            ss += __shfl_xor_sync(0xffffffffu, ss, o);
        float inv = rsqrtf(ss * (1.0f / HD) + EPS_RMS);
        float4 wv = *(const float4*)(w + dbase);
        float nx[4] = {x[0]*inv*wv.x, x[1]*inv*wv.y, x[2]*inv*wv.z, x[3]*inv*wv.w};

        float out[4];
        const bool lo = (lane < 16);
#pragma unroll
        for (int j = 0; j < 4; j++) {
            float partner = __shfl_xor_sync(0xffffffffu, nx[j], 16);
            int i2 = (dbase + j) & 63;
            float c = cs[i2], si = sn[i2];
            out[j] = lo ? (nx[j] * c - partner * si)
                        : (nx[j] * c + partner * si);
        }
        *(float4*)(dst + dbase) = make_float4(out[0], out[1], out[2], out[3]);
    }
}

// ================= fp16 flash attention, Bq=64/Bk=32 =================
// 128 threads (4 warps); warp w owns rows w*16..w*16+15 (warp-local softmax).
// P stays in registers (fragment layout == softmax output layout). No Ps smem.
// 3-stage cp.async pipeline, stage = Ks 8KB + Vs 8KB.
#define ATTN_SMEM_BYTES (3 * 4096 * 4)

__global__ __launch_bounds__(128, 3)
void attn_h(const float* __restrict__ gq, const uint32_t* __restrict__ Kf,
            const uint32_t* __restrict__ Vf, float* __restrict__ gao) {
    extern __shared__ uint32_t smu[];
    float* Qlin = (float*)smu;           // [64][132] prologue only (aliases stages)

    const int tid  = threadIdx.x;
    const int lane = tid & 31;
    const int w    = tid >> 5;           // 0..3
    const int g = lane >> 2, t = lane & 3;
    const int h  = blockIdx.y;
    const int qt = (int)gridDim.x - 1 - (int)blockIdx.x;   // heavy first
    const int q0 = qt * 64;
    const int kv = h >> 1;
    const int nkt = 2 * qt + 2;          // 32-wide key tiles
    const uint32_t sbase = (uint32_t)__cvta_generic_to_shared(smu);

    // ---- prologue: Q tile (64x128) -> smem linear -> fp16 fragments ----
    const float* qbase = gq + ((size_t)h * S_LEN + q0) * HD;
#pragma unroll
    for (int p = 0; p < 16; p++) {
        int idx = tid + p * 128;
        int r = idx >> 5, c4 = (idx & 31) * 4;
        *(float4*)&Qlin[r * 132 + c4] = *(const float4*)&qbase[(size_t)r * HD + c4];
    }
    __syncthreads();

    const float CC = ATT_SCALE * LOG2E;
    uint32_t aq[8][4];
    {
        int r0 = w * 16 + g;
        int t2 = t * 2;
#pragma unroll
        for (int ks = 0; ks < 8; ks++) {
            int kb = ks * 16 + t2;
            aq[ks][0] = f2h2(Qlin[r0 * 132 + kb] * CC,           Qlin[r0 * 132 + kb + 1] * CC);
            aq[ks][1] = f2h2(Qlin[(r0 + 8) * 132 + kb] * CC,     Qlin[(r0 + 8) * 132 + kb + 1] * CC);
            aq[ks][2] = f2h2(Qlin[r0 * 132 + kb + 8] * CC,       Qlin[r0 * 132 + kb + 9] * CC);
            aq[ks][3] = f2h2(Qlin[(r0 + 8) * 132 + kb + 8] * CC, Qlin[(r0 + 8) * 132 + kb + 9] * CC);
        }
    }
    __syncthreads();   // done reading Qlin before cp.async clobbers it

    const uint32_t* Ksrc = Kf + (size_t)kv * (S_LEN / 32) * 2048;
    const uint32_t* Vsrc = Vf + (size_t)kv * (S_LEN / 32) * 2048;
    auto issue = [&](int kt, int st) {
        if (kt < nkt) {
            uint32_t dst = sbase + (uint32_t)st * 16384;
            const uint32_t* kp = Ksrc + (size_t)kt * 2048;
            const uint32_t* vp = Vsrc + (size_t)kt * 2048;
#pragma unroll
            for (int p = 0; p < 4; p++) {
                int i = tid + p * 128;
                cpasync16(dst + i * 16, kp + i * 4);
                cpasync16(dst + 8192 + i * 16, vp + i * 4);
            }
        }
    };
    issue(0, 0); CP_COMMIT();
    issue(1, 1); CP_COMMIT();
    issue(2, 2); CP_COMMIT();

    float oacc[16][4];
#pragma unroll
    for (int j = 0; j < 16; j++)
#pragma unroll
        for (int e = 0; e < 4; e++) oacc[j][e] = 0.f;
    float m2a = -1e30f, m2b = -1e30f;
    float la = 0.f, lb = 0.f;

    const int r0g = q0 + w * 16 + g;

#pragma unroll 1
    for (int kt = 0; kt < nkt; kt++) {
        CP_WAIT2();
        __syncthreads();
        const uint32_t* Ks = smu + (kt % 3) * 4096;
        const uint32_t* Vs = Ks + 2048;

        // ---- scores: 16 rows x 32 keys per warp ----
        float sc[4][4];
#pragma unroll
        for (int j = 0; j < 4; j++)
#pragma unroll
            for (int e = 0; e < 4; e++) sc[j][e] = 0.f;
#pragma unroll
        for (int ks = 0; ks < 8; ks++) {
#pragma unroll
            for (int jj = 0; jj < 2; jj++) {
                uint4 bv = *(const uint4*)&Ks[((ks * 2 + jj) * 32 + lane) * 4];
                uint32_t b0[2] = {bv.x, bv.y};
                uint32_t b1[2] = {bv.z, bv.w};
                mma16(sc[2 * jj],     aq[ks], b0);
                mma16(sc[2 * jj + 1], aq[ks], b1);
            }
        }

        // ---- causal mask (diagonal tiles only) ----
        if (kt >= 2 * qt) {
            const int k0 = kt * 32;
#pragma unroll
            for (int j = 0; j < 4; j++) {
                int c0 = k0 + j * 8 + 2 * t;
                if (c0     > r0g)     sc[j][0] = -1e30f;
                if (c0 + 1 > r0g)     sc[j][1] = -1e30f;
                if (c0     > r0g + 8) sc[j][2] = -1e30f;
                if (c0 + 1 > r0g + 8) sc[j][3] = -1e30f;
            }
        }

        // ---- online softmax (warp-local, quad reduction) ----
        float mx0 = -1e30f, mx1 = -1e30f;
#pragma unroll
        for (int j = 0; j < 4; j++) {
            mx0 = fmaxf(mx0, fmaxf(sc[j][0], sc[j][1]));
            mx1 = fmaxf(mx1, fmaxf(sc[j][2], sc[j][3]));
        }
        mx0 = fmaxf(mx0, __shfl_xor_sync(0xffffffffu, mx0, 1));
        mx0 = fmaxf(mx0, __shfl_xor_sync(0xffffffffu, mx0, 2));
        mx1 = fmaxf(mx1, __shfl_xor_sync(0xffffffffu, mx1, 1));
        mx1 = fmaxf(mx1, __shfl_xor_sync(0xffffffffu, mx1, 2));
        float mn0 = fmaxf(m2a, mx0), mn1 = fmaxf(m2b, mx1);
        float f0 = ex2f(m2a - mn0), f1 = ex2f(m2b - mn1);
        m2a = mn0; m2b = mn1;

        float s0 = 0.f, s1 = 0.f;
#pragma unroll
        for (int j = 0; j < 4; j++) {
            sc[j][0] = ex2f(sc[j][0] - mn0);
            sc[j][1] = ex2f(sc[j][1] - mn0);
            sc[j][2] = ex2f(sc[j][2] - mn1);
            sc[j][3] = ex2f(sc[j][3] - mn1);
            s0 += sc[j][0] + sc[j][1];
            s1 += sc[j][2] + sc[j][3];
        }
        s0 += __shfl_xor_sync(0xffffffffu, s0, 1);
        s0 += __shfl_xor_sync(0xffffffffu, s0, 2);
        s1 += __shfl_xor_sync(0xffffffffu, s1, 1);
        s1 += __shfl_xor_sync(0xffffffffu, s1, 2);
        la = la * f0 + s0;
        lb = lb * f1 + s1;

#pragma unroll
        for (int j = 0; j < 16; j++) {
            oacc[j][0] *= f0; oacc[j][1] *= f0;
            oacc[j][2] *= f1; oacc[j][3] *= f1;
        }

        // ---- P fragments directly from sc (no smem roundtrip) ----
        uint32_t pa[2][4];
#pragma unroll
        for (int ks2 = 0; ks2 < 2; ks2++) {
            pa[ks2][0] = f2h2(sc[2 * ks2][0],     sc[2 * ks2][1]);
            pa[ks2][1] = f2h2(sc[2 * ks2][2],     sc[2 * ks2][3]);
            pa[ks2][2] = f2h2(sc[2 * ks2 + 1][0], sc[2 * ks2 + 1][1]);
            pa[ks2][3] = f2h2(sc[2 * ks2 + 1][2], sc[2 * ks2 + 1][3]);
        }

        // ---- O += P @ V ----
#pragma unroll
        for (int ks2 = 0; ks2 < 2; ks2++) {
#pragma unroll
            for (int jj = 0; jj < 8; jj++) {
                uint4 bv = *(const uint4*)&Vs[((ks2 * 8 + jj) * 32 + lane) * 4];
                uint32_t b0[2] = {bv.x, bv.y};
                uint32_t b1[2] = {bv.z, bv.w};
                mma16(oacc[2 * jj],     pa[ks2], b0);
                mma16(oacc[2 * jj + 1], pa[ks2], b1);
            }
        }
        __syncthreads();          // all warps done with this stage
        issue(kt + 3, kt % 3);    // refill consumed stage
        CP_COMMIT();
    }

    // ---- epilogue ----
    float inv0 = 1.f / la, inv1 = 1.f / lb;
    int row0 = q0 + w * 16 + g;
#pragma unroll
    for (int j = 0; j < 16; j++) {
        int col = h * HD + j * 8 + 2 * t;
        *(float2*)&gao[(size_t)row0 * HDIM + col] =
            make_float2(oacc[j][0] * inv0, oacc[j][1] * inv0);
        *(float2*)&gao[(size_t)(row0 + 8) * HDIM + col] =
            make_float2(oacc[j][2] * inv1, oacc[j][3] * inv1);
    }
}

// ---------------- launch ----------------
extern "C" void kernel_launch(void* const* d_in, const int* in_sizes, int n_in,
                              void* d_out, int out_size) {
    const float* hidden    = (const float*)d_in[0];
    const int*   positions = (const int*)  d_in[1];
    const float* w_qkv     = (const float*)d_in[2];
    const float* w_o       = (const float*)d_in[3];
    const float* q_norm_w  = (const float*)d_in[4];
    const float* k_norm_w  = (const float*)d_in[5];
    const float* cache     = (const float*)d_in[6];
    float* out = (float*)d_out;

    float *qkv_p, *q_p, *k_p, *ao_p;
    uint32_t *af_p, *bf_p, *kf_p, *vf_p;
    cudaGetSymbolAddress((void**)&qkv_p, g_qkv);
    cudaGetSymbolAddress((void**)&q_p,   g_q);
    cudaGetSymbolAddress((void**)&k_p,   g_k);
    cudaGetSymbolAddress((void**)&ao_p,  g_ao);
    cudaGetSymbolAddress((void**)&af_p,  g_af);
    cudaGetSymbolAddress((void**)&bf_p,  g_bf);
    cudaGetSymbolAddress((void**)&kf_p,  g_kf);
    cudaGetSymbolAddress((void**)&vf_p,  g_vf);

    cudaFuncSetAttribute(gemm_h, cudaFuncAttributeMaxDynamicSharedMemorySize,
                         GEMM_SMEM_BYTES);
    cudaFuncSetAttribute(attn_h, cudaFuncAttributeMaxDynamicSharedMemorySize,
                         ATTN_SMEM_BYTES);

    // 1) QKV projection (fp16 tensor cores)
    permA_kernel<<<dim3(64, 32), 256>>>(hidden, af_p, S_LEN, HDIM);
    permB_kernel<<<dim3(32, 64), 256>>>(w_qkv, bf_p, HDIM, QKV_N);
    gemm_h<<<dim3(32, 32), 256, GEMM_SMEM_BYTES>>>(af_p, bf_p, qkv_p,
                                                   S_LEN, QKV_N, HDIM);

    // 2) RMSNorm + mRoPE
    normrope_kernel<<<S_LEN, 256>>>(qkv_p, positions, q_norm_w, k_norm_w,
                                    cache, q_p, k_p);

    // 3) permute K/V, flash attention (fp16)
    permK_kernel<<<dim3(S_LEN / 32, NKV), 256>>>(k_p, kf_p);
    permV_kernel<<<dim3(S_LEN / 32, NKV), 256>>>(qkv_p, vf_p);
    attn_h<<<dim3(S_LEN / 64, NH), 128, ATTN_SMEM_BYTES>>>(q_p, kf_p, vf_p, ao_p);

    // 4) output projection (fp16 tensor cores)
    permA_kernel<<<dim3(64, 32), 256>>>(ao_p, af_p, S_LEN, HDIM);
    permB_kernel<<<dim3(16, 64), 256>>>(w_o, bf_p, HDIM, HDIM);
    gemm_h<<<dim3(16, 32), 256, GEMM_SMEM_BYTES>>>(af_p, bf_p, out,
                                                   S_LEN, HDIM, HDIM);
}

// round 15
// speedup vs baseline: 14.8947x; 1.0063x over previous
#include <cuda_runtime.h>
#include <cuda_fp16.h>
#include <cstdint>
#include <cstddef>

// ---------------- problem constants ----------------
#define S_LEN   4096
#define HDIM    2048
#define NH      16
#define NKV     8
#define HD      128
#define QKV_N   4096
#define VOFF    3072                     // NH*HD + NKV*HD
#define ATT_SCALE 0.08838834764831845f   // 128^-0.5
#define EPS_RMS 1e-6f
#define LOG2E   1.4426950408889634f

// ---------------- scratch (device globals: allowed) ----------------
__device__ float g_qkv[(size_t)S_LEN * QKV_N];       // 64 MB
__device__ float g_q[(size_t)NH  * S_LEN * HD];      // 32 MB  [h][s][d]
__device__ float g_k[(size_t)NKV * S_LEN * HD];      // 16 MB  [kv][s][d]
__device__ uint32_t g_af[(size_t)32 * 64 * 2048];    // 16 MB  A tiles (fp16 frags)
__device__ uint32_t g_bf[(size_t)64 * 32 * 2048];    // 16 MB  B tiles (fp16 frags)
__device__ uint32_t g_kf[(size_t)NKV * 128 * 2048];  //  8 MB  K tiles (fp16 frags)
__device__ uint32_t g_vf[(size_t)NKV * 128 * 2048];  //  8 MB  V tiles (fp16 frags)

// ---------------- helpers ----------------
__device__ __forceinline__ uint32_t f2h2(float lo, float hi) {
    __half2 h = __floats2half2_rn(lo, hi);
    return *(uint32_t*)&h;
}

__device__ __forceinline__ float ex2f(float x) {
    float y;
    asm("ex2.approx.f32 %0, %1;" : "=f"(y) : "f"(x));
    return y;
}

// fp16 mma with fp32 accumulate: D(16x8) += A(16x16) * B(16x8)
__device__ __forceinline__ void mma16(float c[4], const uint32_t a[4], const uint32_t b[2]) {
    asm volatile(
        "mma.sync.aligned.m16n8k16.row.col.f32.f16.f16.f32 "
        "{%0,%1,%2,%3}, {%4,%5,%6,%7}, {%8,%9}, {%0,%1,%2,%3};"
        : "+f"(c[0]), "+f"(c[1]), "+f"(c[2]), "+f"(c[3])
        : "r"(a[0]), "r"(a[1]), "r"(a[2]), "r"(a[3]), "r"(b[0]), "r"(b[1]));
}

__device__ __forceinline__ void cpasync16(uint32_t saddr, const void* gptr) {
    asm volatile("cp.async.cg.shared.global [%0], [%1], 16;"
                 :: "r"(saddr), "l"(gptr));
}
#define CP_COMMIT() asm volatile("cp.async.commit_group;")
#define CP_WAIT1()  asm volatile("cp.async.wait_group 1;")
#define CP_WAIT2()  asm volatile("cp.async.wait_group 2;")

// ================= permute kernels (f32 gmem -> fp16 fragment-layout gmem) ====
// Fragment conventions (m16n8k16, g = lane>>2, t2 = (lane&3)*2):
//  A-frag reg r: row = base + (r&1)*8 + g, k = kbase + (r>>1)*8 + t2, pair (k,k+1)
//  B-frag: b0 = (k = t2, t2+1, col g), b1 = (k = t2+8, t2+9, col g)

// A tiles: [M][K] -> [mb][kb][2048], o = ((ks*8 + mf)*32 + lane)*4 + r
__global__ void permA_kernel(const float* __restrict__ A, uint32_t* __restrict__ out,
                             int M, int K) {
    __shared__ float t[128 * 36];
    const int kb = blockIdx.x, mb = blockIdx.y, nkb = gridDim.x;
    const int tid = threadIdx.x;
#pragma unroll
    for (int p = 0; p < 4; p++) {
        int idx = tid + p * 256;
        int r = idx >> 3, c4 = (idx & 7) * 4;
        float4 v = *(const float4*)&A[(size_t)(mb * 128 + r) * K + kb * 32 + c4];
        *(float4*)&t[r * 36 + c4] = v;
    }
    __syncthreads();
    uint32_t* dst = out + ((size_t)mb * nkb + kb) * 2048;
#pragma unroll
    for (int q = 0; q < 2; q++) {
        int o = q * 1024 + tid * 4;
        int lane = (o >> 2) & 31, mf = (o >> 7) & 7, ks = o >> 10;
        int g = lane >> 2, t2 = (lane & 3) * 2;
        int rb = mf * 16 + g, kb2 = ks * 16 + t2;
        uint4 u;
        u.x = f2h2(t[rb * 36 + kb2],           t[rb * 36 + kb2 + 1]);
        u.y = f2h2(t[(rb + 8) * 36 + kb2],     t[(rb + 8) * 36 + kb2 + 1]);
        u.z = f2h2(t[rb * 36 + kb2 + 8],       t[rb * 36 + kb2 + 9]);
        u.w = f2h2(t[(rb + 8) * 36 + kb2 + 8], t[(rb + 8) * 36 + kb2 + 9]);
        *(uint4*)&dst[o] = u;
    }
}

// B tiles: [K][N] -> [kb][nb][2048], o = ((ks*8 + nf2)*32 + lane)*4 + jl*2 + kk2
__global__ void permB_kernel(const float* __restrict__ B, uint32_t* __restrict__ out,
                             int K, int N) {
    __shared__ float t[32 * 132];
    const int nb = blockIdx.x, kb = blockIdx.y, nnb = gridDim.x;
    const int tid = threadIdx.x;
#pragma unroll
    for (int p = 0; p < 4; p++) {
        int idx = tid + p * 256;
        int r = idx >> 5, c4 = (idx & 31) * 4;
        float4 v = *(const float4*)&B[(size_t)(kb * 32 + r) * N + nb * 128 + c4];
        *(float4*)&t[r * 132 + c4] = v;
    }
    __syncthreads();
    uint32_t* dst = out + ((size_t)kb * nnb + nb) * 2048;
#pragma unroll
    for (int q = 0; q < 2; q++) {
        int o = q * 1024 + tid * 4;
        uint32_t u[4];
#pragma unroll
        for (int e = 0; e < 4; e++) {
            int oe = o + e;
            int kk2 = oe & 1, jl = (oe >> 1) & 1;
            int lane = (oe >> 2) & 31;
            int nf2 = (oe >> 7) & 7, ks = oe >> 10;
            int g = lane >> 2, t2 = (lane & 3) * 2;
            int nf = 2 * nf2 + jl;
            int k = ks * 16 + kk2 * 8 + t2;
            int c = nf * 8 + g;
            u[e] = f2h2(t[k * 132 + c], t[(k + 1) * 132 + c]);
        }
        *(uint4*)&dst[o] = make_uint4(u[0], u[1], u[2], u[3]);
    }
}

// K tiles: g_k [kv][s][d] -> [kv][kt32][2048] (B-op of QK^T: k-dim=d, n=keys)
__global__ void permK_kernel(const float* __restrict__ gk, uint32_t* __restrict__ out) {
    __shared__ float t[32 * 132];
    const int kt = blockIdx.x, kv = blockIdx.y;
    const int tid = threadIdx.x;
#pragma unroll
    for (int p = 0; p < 4; p++) {
        int idx = tid + p * 256;
        int r = idx >> 5, c4 = (idx & 31) * 4;
        float4 v = *(const float4*)&gk[((size_t)kv * S_LEN + kt * 32 + r) * HD + c4];
        *(float4*)&t[r * 132 + c4] = v;
    }
    __syncthreads();
    uint32_t* dst = out + ((size_t)kv * (S_LEN / 32) + kt) * 2048;
#pragma unroll
    for (int q = 0; q < 2; q++) {
        int o = q * 1024 + tid * 4;
        uint32_t u[4];
#pragma unroll
        for (int e = 0; e < 4; e++) {
            int oe = o + e;
            int kk2 = oe & 1, jl = (oe >> 1) & 1;
            int lane = (oe >> 2) & 31;
            int jj = (oe >> 7) & 1, ks = oe >> 8;       // ks 0..7
            int g = lane >> 2, t2 = (lane & 3) * 2;
            int j = 2 * jj + jl;
            int r = j * 8 + g;
            int d = ks * 16 + kk2 * 8 + t2;
            u[e] = f2h2(t[r * 132 + d], t[r * 132 + d + 1]);
        }
        *(uint4*)&dst[o] = make_uint4(u[0], u[1], u[2], u[3]);
    }
}

// V tiles: g_qkv strided -> [kv][kt32][2048] (B-op of PV: k-dim=keys, n=dims)
__global__ void permV_kernel(const float* __restrict__ gqkv, uint32_t* __restrict__ out) {
    __shared__ float t[32 * 132];
    const int kt = blockIdx.x, kv = blockIdx.y;
    const int tid = threadIdx.x;
#pragma unroll
    for (int p = 0; p < 4; p++) {
        int idx = tid + p * 256;
        int r = idx >> 5, c4 = (idx & 31) * 4;
        float4 v = *(const float4*)&gqkv[(size_t)(kt * 32 + r) * QKV_N + VOFF + kv * HD + c4];
        *(float4*)&t[r * 132 + c4] = v;
    }
    __syncthreads();
    uint32_t* dst = out + ((size_t)kv * (S_LEN / 32) + kt) * 2048;
#pragma unroll
    for (int q = 0; q < 2; q++) {
        int o = q * 1024 + tid * 4;
        uint32_t u[4];
#pragma unroll
        for (int e = 0; e < 4; e++) {
            int oe = o + e;
            int kk2 = oe & 1, jl = (oe >> 1) & 1;
            int lane = (oe >> 2) & 31;
            int jj = (oe >> 7) & 7, ks = oe >> 10;      // ks 0..1
            int g = lane >> 2, t2 = (lane & 3) * 2;
            int jv = 2 * jj + jl;
            int d = jv * 8 + g;
            int k = ks * 16 + kk2 * 8 + t2;
            u[e] = f2h2(t[k * 132 + d], t[(k + 1) * 132 + d]);
        }
        *(uint4*)&dst[o] = make_uint4(u[0], u[1], u[2], u[3]);
    }
}

// ================= fp16 GEMM (mma.sync m16n8k16) on pre-permuted tiles ========
#define GEMM_SMEM_BYTES (3 * 4096 * 4)

__global__ __launch_bounds__(256, 2)
void gemm_h(const uint32_t* __restrict__ Af, const uint32_t* __restrict__ Bf,
            float* __restrict__ C, int M, int N, int K) {
    extern __shared__ uint32_t smg[];
    const int tid  = threadIdx.x;
    const int lane = tid & 31;
    const int warp = tid >> 5;
    const int wm = warp >> 2, wn = warp & 3;
    const int g = lane >> 2, t = lane & 3;
    const int mb = blockIdx.y, nb = blockIdx.x;
    const int nkb = K / 32, nnb = N / 128;
    const uint32_t sbase = (uint32_t)__cvta_generic_to_shared(smg);
    const uint32_t* Asrc = Af + (size_t)mb * nkb * 2048;

    auto issue = [&](int kb, int st) {
        uint32_t dst = sbase + (uint32_t)st * 16384;
        const uint32_t* a = Asrc + (size_t)kb * 2048;
        const uint32_t* b = Bf + ((size_t)kb * nnb + nb) * 2048;
#pragma unroll
        for (int p = 0; p < 2; p++) {
            int i = tid + p * 256;
            cpasync16(dst + i * 16, a + i * 4);
            cpasync16(dst + 8192 + i * 16, b + i * 4);
        }
    };

    issue(0, 0); CP_COMMIT();
    issue(1, 1); CP_COMMIT();

    float acc[4][4][4];
#pragma unroll
    for (int i = 0; i < 4; i++)
#pragma unroll
        for (int j = 0; j < 4; j++)
#pragma unroll
            for (int e = 0; e < 4; e++) acc[i][j][e] = 0.f;

    for (int kb = 0; kb < nkb; kb++) {
        CP_WAIT1();
        __syncthreads();
        if (kb + 2 < nkb) issue(kb + 2, (kb + 2) % 3);
        CP_COMMIT();

        const uint32_t* As = smg + (kb % 3) * 4096;
        const uint32_t* Bs = As + 2048;
#pragma unroll
        for (int ks = 0; ks < 2; ks++) {
            uint32_t a[4][4];
#pragma unroll
            for (int i = 0; i < 4; i++) {
                uint4 av = *(const uint4*)&As[((ks * 8 + wm * 4 + i) * 32 + lane) * 4];
                a[i][0] = av.x; a[i][1] = av.y; a[i][2] = av.z; a[i][3] = av.w;
            }
#pragma unroll
            for (int j2 = 0; j2 < 2; j2++) {
                uint4 bv = *(const uint4*)&Bs[((ks * 8 + wn * 2 + j2) * 32 + lane) * 4];
                uint32_t b0[2] = {bv.x, bv.y};
                uint32_t b1[2] = {bv.z, bv.w};
#pragma unroll
                for (int i = 0; i < 4; i++) {
                    mma16(acc[i][2 * j2],     a[i], b0);
                    mma16(acc[i][2 * j2 + 1], a[i], b1);
                }
            }
        }
    }

#pragma unroll
    for (int i = 0; i < 4; i++)
#pragma unroll
        for (int j = 0; j < 4; j++) {
            int row0 = mb * 128 + wm * 64 + i * 16 + g;
            int col  = nb * 128 + wn * 32 + j * 8 + 2 * t;
            *(float2*)&C[(size_t)row0 * N + col]       = make_float2(acc[i][j][0], acc[i][j][1]);
            *(float2*)&C[(size_t)(row0 + 8) * N + col] = make_float2(acc[i][j][2], acc[i][j][3]);
        }
}

// ---------------- RMSNorm + mRoPE (unchanged) ----------------
__global__ void normrope_kernel(const float* __restrict__ qkv,
                                const int*   __restrict__ positions,
                                const float* __restrict__ qw,
                                const float* __restrict__ kw,
                                const float* __restrict__ cache,
                                float* __restrict__ gq,
                                float* __restrict__ gk) {
    const int s = blockIdx.x;
    __shared__ float cs[64], sn[64];
    const int tid = threadIdx.x;

    if (tid < 64) {
        int i = tid;
        int m3 = i % 3;
        int sec = (i < 60) ? ((m3 == 1) ? 1 : ((m3 == 2) ? 2 : 0)) : 0;
        int pos = positions[sec * S_LEN + s];
        cs[i] = cache[(size_t)pos * HD + i];
        sn[i] = cache[(size_t)pos * HD + 64 + i];
    }
    __syncthreads();

    const int warp = tid >> 5;
    const int lane = tid & 31;
    const int dbase = lane * 4;

    for (int h = warp; h < NH + NKV; h += 8) {
        const float* src;
        const float* w;
        float* dst;
        if (h < NH) {
            src = qkv + (size_t)s * QKV_N + h * HD;
            w = qw;
            dst = gq + ((size_t)h * S_LEN + s) * HD;
        } else {
            int kh = h - NH;
            src = qkv + (size_t)s * QKV_N + NH * HD + kh * HD;
            w = kw;
            dst = gk + ((size_t)kh * S_LEN + s) * HD;
        }
        float4 xv = *(const float4*)(src + dbase);
        float x[4] = {xv.x, xv.y, xv.z, xv.w};
        float ss = x[0]*x[0] + x[1]*x[1] + x[2]*x[2] + x[3]*x[3];
#pragma unroll
        for (int o = 16; o > 0; o >>= 1)
            ss += __shfl_xor_sync(0xffffffffu, ss, o);
        float inv = rsqrtf(ss * (1.0f / HD) + EPS_RMS);
        float4 wv = *(const float4*)(w + dbase);
        float nx[4] = {x[0]*inv*wv.x, x[1]*inv*wv.y, x[2]*inv*wv.z, x[3]*inv*wv.w};

        float out[4];
        const bool lo = (lane < 16);
#pragma unroll
        for (int j = 0; j < 4; j++) {
            float partner = __shfl_xor_sync(0xffffffffu, nx[j], 16);
            int i2 = (dbase + j) & 63;
            float c = cs[i2], si = sn[i2];
            out[j] = lo ? (nx[j] * c - partner * si)
                        : (nx[j] * c + partner * si);
        }
        *(float4*)(dst + dbase) = make_float4(out[0], out[1], out[2], out[3]);
    }
}

// ================= fp16 flash attention, Bq=64/Bk=32 =================
// Output written DIRECTLY as O-proj A-fragment tiles (g_af): C-frag register
// pairs (cols 2t,2t+1; rows g,g+8) are exactly A-frag (k-pair t2; rows g,g+8).
#define ATTN_SMEM_BYTES (3 * 4096 * 4)

__global__ __launch_bounds__(128, 3)
void attn_h(const float* __restrict__ gq, const uint32_t* __restrict__ Kf,
            const uint32_t* __restrict__ Vf, uint32_t* __restrict__ af) {
    extern __shared__ uint32_t smu[];
    float* Qlin = (float*)smu;           // [64][132] prologue only (aliases stages)

    const int tid  = threadIdx.x;
    const int lane = tid & 31;
    const int w    = tid >> 5;           // 0..3
    const int g = lane >> 2, t = lane & 3;
    const int h  = blockIdx.y;
    const int qt = (int)gridDim.x - 1 - (int)blockIdx.x;   // heavy first
    const int q0 = qt * 64;
    const int kv = h >> 1;
    const int nkt = 2 * qt + 2;          // 32-wide key tiles
    const uint32_t sbase = (uint32_t)__cvta_generic_to_shared(smu);

    // ---- prologue: Q tile (64x128) -> smem linear -> fp16 fragments ----
    const float* qbase = gq + ((size_t)h * S_LEN + q0) * HD;
#pragma unroll
    for (int p = 0; p < 16; p++) {
        int idx = tid + p * 128;
        int r = idx >> 5, c4 = (idx & 31) * 4;
        *(float4*)&Qlin[r * 132 + c4] = *(const float4*)&qbase[(size_t)r * HD + c4];
    }
    __syncthreads();

    const float CC = ATT_SCALE * LOG2E;
    uint32_t aq[8][4];
    {
        int r0 = w * 16 + g;
        int t2 = t * 2;
#pragma unroll
        for (int ks = 0; ks < 8; ks++) {
            int kb = ks * 16 + t2;
            aq[ks][0] = f2h2(Qlin[r0 * 132 + kb] * CC,           Qlin[r0 * 132 + kb + 1] * CC);
            aq[ks][1] = f2h2(Qlin[(r0 + 8) * 132 + kb] * CC,     Qlin[(r0 + 8) * 132 + kb + 1] * CC);
            aq[ks][2] = f2h2(Qlin[r0 * 132 + kb + 8] * CC,       Qlin[r0 * 132 + kb + 9] * CC);
            aq[ks][3] = f2h2(Qlin[(r0 + 8) * 132 + kb + 8] * CC, Qlin[(r0 + 8) * 132 + kb + 9] * CC);
        }
    }
    __syncthreads();   // done reading Qlin before cp.async clobbers it

    const uint32_t* Ksrc = Kf + (size_t)kv * (S_LEN / 32) * 2048;
    const uint32_t* Vsrc = Vf + (size_t)kv * (S_LEN / 32) * 2048;
    auto issue = [&](int kt, int st) {
        if (kt < nkt) {
            uint32_t dst = sbase + (uint32_t)st * 16384;
            const uint32_t* kp = Ksrc + (size_t)kt * 2048;
            const uint32_t* vp = Vsrc + (size_t)kt * 2048;
#pragma unroll
            for (int p = 0; p < 4; p++) {
                int i = tid + p * 128;
                cpasync16(dst + i * 16, kp + i * 4);
                cpasync16(dst + 8192 + i * 16, vp + i * 4);
            }
        }
    };
    issue(0, 0); CP_COMMIT();
    issue(1, 1); CP_COMMIT();
    issue(2, 2); CP_COMMIT();

    float oacc[16][4];
#pragma unroll
    for (int j = 0; j < 16; j++)
#pragma unroll
        for (int e = 0; e < 4; e++) oacc[j][e] = 0.f;
    float m2a = -1e30f, m2b = -1e30f;
    float la = 0.f, lb = 0.f;

    const int r0g = q0 + w * 16 + g;

#pragma unroll 1
    for (int kt = 0; kt < nkt; kt++) {
        CP_WAIT2();
        __syncthreads();
        const uint32_t* Ks = smu + (kt % 3) * 4096;
        const uint32_t* Vs = Ks + 2048;

        // ---- scores: 16 rows x 32 keys per warp ----
        float sc[4][4];
#pragma unroll
        for (int j = 0; j < 4; j++)
#pragma unroll
            for (int e = 0; e < 4; e++) sc[j][e] = 0.f;
#pragma unroll
        for (int ks = 0; ks < 8; ks++) {
#pragma unroll
            for (int jj = 0; jj < 2; jj++) {
                uint4 bv = *(const uint4*)&Ks[((ks * 2 + jj) * 32 + lane) * 4];
                uint32_t b0[2] = {bv.x, bv.y};
                uint32_t b1[2] = {bv.z, bv.w};
                mma16(sc[2 * jj],     aq[ks], b0);
                mma16(sc[2 * jj + 1], aq[ks], b1);
            }
        }

        // ---- causal mask (diagonal tiles only) ----
        if (kt >= 2 * qt) {
            const int k0 = kt * 32;
#pragma unroll
            for (int j = 0; j < 4; j++) {
                int c0 = k0 + j * 8 + 2 * t;
                if (c0     > r0g)     sc[j][0] = -1e30f;
                if (c0 + 1 > r0g)     sc[j][1] = -1e30f;
                if (c0     > r0g + 8) sc[j][2] = -1e30f;
                if (c0 + 1 > r0g + 8) sc[j][3] = -1e30f;
            }
        }

        // ---- online softmax (warp-local, quad reduction) ----
        float mx0 = -1e30f, mx1 = -1e30f;
#pragma unroll
        for (int j = 0; j < 4; j++) {
            mx0 = fmaxf(mx0, fmaxf(sc[j][0], sc[j][1]));
            mx1 = fmaxf(mx1, fmaxf(sc[j][2], sc[j][3]));
        }
        mx0 = fmaxf(mx0, __shfl_xor_sync(0xffffffffu, mx0, 1));
        mx0 = fmaxf(mx0, __shfl_xor_sync(0xffffffffu, mx0, 2));
        mx1 = fmaxf(mx1, __shfl_xor_sync(0xffffffffu, mx1, 1));
        mx1 = fmaxf(mx1, __shfl_xor_sync(0xffffffffu, mx1, 2));
        float mn0 = fmaxf(m2a, mx0), mn1 = fmaxf(m2b, mx1);
        float f0 = ex2f(m2a - mn0), f1 = ex2f(m2b - mn1);
        m2a = mn0; m2b = mn1;

        float s0 = 0.f, s1 = 0.f;
#pragma unroll
        for (int j = 0; j < 4; j++) {
            sc[j][0] = ex2f(sc[j][0] - mn0);
            sc[j][1] = ex2f(sc[j][1] - mn0);
            sc[j][2] = ex2f(sc[j][2] - mn1);
            sc[j][3] = ex2f(sc[j][3] - mn1);
            s0 += sc[j][0] + sc[j][1];
            s1 += sc[j][2] + sc[j][3];
        }
        s0 += __shfl_xor_sync(0xffffffffu, s0, 1);
        s0 += __shfl_xor_sync(0xffffffffu, s0, 2);
        s1 += __shfl_xor_sync(0xffffffffu, s1, 1);
        s1 += __shfl_xor_sync(0xffffffffu, s1, 2);
        la = la * f0 + s0;
        lb = lb * f1 + s1;

#pragma unroll
        for (int j = 0; j < 16; j++) {
            oacc[j][0] *= f0; oacc[j][1] *= f0;
            oacc[j][2] *= f1; oacc[j][3] *= f1;
        }

        // ---- P fragments directly from sc (no smem roundtrip) ----
        uint32_t pa[2][4];
#pragma unroll
        for (int ks2 = 0; ks2 < 2; ks2++) {
            pa[ks2][0] = f2h2(sc[2 * ks2][0],     sc[2 * ks2][1]);
            pa[ks2][1] = f2h2(sc[2 * ks2][2],     sc[2 * ks2][3]);
            pa[ks2][2] = f2h2(sc[2 * ks2 + 1][0], sc[2 * ks2 + 1][1]);
            pa[ks2][3] = f2h2(sc[2 * ks2 + 1][2], sc[2 * ks2 + 1][3]);
        }

        // ---- O += P @ V ----
#pragma unroll
        for (int ks2 = 0; ks2 < 2; ks2++) {
#pragma unroll
            for (int jj = 0; jj < 8; jj++) {
                uint4 bv = *(const uint4*)&Vs[((ks2 * 8 + jj) * 32 + lane) * 4];
                uint32_t b0[2] = {bv.x, bv.y};
                uint32_t b1[2] = {bv.z, bv.w};
                mma16(oacc[2 * jj],     pa[ks2], b0);
                mma16(oacc[2 * jj + 1], pa[ks2], b1);
            }
        }
        __syncthreads();          // all warps done with this stage
        issue(kt + 3, kt % 3);    // refill consumed stage
        CP_COMMIT();
    }

    // ---- epilogue: write O directly as O-proj A-fragment tiles ----
    // rows: row0 = q0 + w*16 + g (and +8). mb = q0>>7, mf = 4*(qt&1) + w.
    // cols: c = h*128 + j*8 + 2t => kb = h*4 + (j>>2), ks = (j>>1)&1, k%16 half = j&1.
    // A-frag uint4 at o=((ks*8+mf)*32+lane)*4 packs (j even, j odd) pair:
    //   u.x=row0 k-lo, u.y=row0+8 k-lo, u.z=row0 k-hi, u.w=row0+8 k-hi
    {
        float inv0 = 1.f / la, inv1 = 1.f / lb;
        const int mb = q0 >> 7;
        const int mf = 4 * (qt & 1) + w;
#pragma unroll
        for (int jp = 0; jp < 8; jp++) {           // pairs (j=2jp, 2jp+1)
            int j = 2 * jp;
            int kb = h * 4 + (j >> 2);
            int ks = (j >> 1) & 1;
            uint32_t* dst = af + ((size_t)mb * 64 + kb) * 2048
                               + ((ks * 8 + mf) * 32 + lane) * 4;
            uint4 u;
            u.x = f2h2(oacc[j][0] * inv0,     oacc[j][1] * inv0);
            u.y = f2h2(oacc[j][2] * inv1,     oacc[j][3] * inv1);
            u.z = f2h2(oacc[j + 1][0] * inv0, oacc[j + 1][1] * inv0);
            u.w = f2h2(oacc[j + 1][2] * inv1, oacc[j + 1][3] * inv1);
            *(uint4*)dst = u;
        }
    }
}

// ---------------- launch ----------------
extern "C" void kernel_launch(void* const* d_in, const int* in_sizes, int n_in,
                              void* d_out, int out_size) {
    const float* hidden    = (const float*)d_in[0];
    const int*   positions = (const int*)  d_in[1];
    const float* w_qkv     = (const float*)d_in[2];
    const float* w_o       = (const float*)d_in[3];
    const float* q_norm_w  = (const float*)d_in[4];
    const float* k_norm_w  = (const float*)d_in[5];
    const float* cache     = (const float*)d_in[6];
    float* out = (float*)d_out;

    float *qkv_p, *q_p, *k_p;
    uint32_t *af_p, *bf_p, *kf_p, *vf_p;
    cudaGetSymbolAddress((void**)&qkv_p, g_qkv);
    cudaGetSymbolAddress((void**)&q_p,   g_q);
    cudaGetSymbolAddress((void**)&k_p,   g_k);
    cudaGetSymbolAddress((void**)&af_p,  g_af);
    cudaGetSymbolAddress((void**)&bf_p,  g_bf);
    cudaGetSymbolAddress((void**)&kf_p,  g_kf);
    cudaGetSymbolAddress((void**)&vf_p,  g_vf);

    cudaFuncSetAttribute(gemm_h, cudaFuncAttributeMaxDynamicSharedMemorySize,
                         GEMM_SMEM_BYTES);
    cudaFuncSetAttribute(attn_h, cudaFuncAttributeMaxDynamicSharedMemorySize,
                         ATTN_SMEM_BYTES);

    // 1) QKV projection (fp16 tensor cores)
    permA_kernel<<<dim3(64, 32), 256>>>(hidden, af_p, S_LEN, HDIM);
    permB_kernel<<<dim3(32, 64), 256>>>(w_qkv, bf_p, HDIM, QKV_N);
    gemm_h<<<dim3(32, 32), 256, GEMM_SMEM_BYTES>>>(af_p, bf_p, qkv_p,
                                                   S_LEN, QKV_N, HDIM);

    // 2) RMSNorm + mRoPE
    normrope_kernel<<<S_LEN, 256>>>(qkv_p, positions, q_norm_w, k_norm_w,
                                    cache, q_p, k_p);

    // 3) permute K/V, flash attention (fp16) -> writes O as A-frag tiles into g_af
    permK_kernel<<<dim3(S_LEN / 32, NKV), 256>>>(k_p, kf_p);
    permV_kernel<<<dim3(S_LEN / 32, NKV), 256>>>(qkv_p, vf_p);
    attn_h<<<dim3(S_LEN / 64, NH), 128, ATTN_SMEM_BYTES>>>(q_p, kf_p, vf_p, af_p);

    // 4) output projection (fp16 tensor cores) — A tiles come straight from attention
    permB_kernel<<<dim3(16, 64), 256>>>(w_o, bf_p, HDIM, HDIM);
    gemm_h<<<dim3(16, 32), 256, GEMM_SMEM_BYTES>>>(af_p, bf_p, out,
                                                   S_LEN, HDIM, HDIM);
}

// round 16
// speedup vs baseline: 14.9514x; 1.0038x over previous
#include <cuda_runtime.h>
#include <cuda_fp16.h>
#include <cstdint>
#include <cstddef>

// ---------------- problem constants ----------------
#define S_LEN   4096
#define HDIM    2048
#define NH      16
#define NKV     8
#define HD      128
#define QKV_N   4096
#define VOFF    3072                     // NH*HD + NKV*HD
#define ATT_SCALE 0.08838834764831845f   // 128^-0.5
#define EPS_RMS 1e-6f
#define LOG2E   1.4426950408889634f

// ---------------- scratch (device globals: allowed) ----------------
__device__ float g_qkv[(size_t)S_LEN * QKV_N];       // 64 MB
__device__ uint32_t g_af[(size_t)32 * 64 * 2048];    // 16 MB  A tiles (fp16 frags)
__device__ uint32_t g_bf[(size_t)64 * 32 * 2048];    // 16 MB  B tiles (fp16 frags)
__device__ uint32_t g_qf[(size_t)NH * 256 * 1024];   // 16 MB  Q frags [h][grp16][1024]
__device__ uint32_t g_kf[(size_t)NKV * 128 * 2048];  //  8 MB  K tiles (fp16 frags)
__device__ uint32_t g_vf[(size_t)NKV * 128 * 2048];  //  8 MB  V tiles (fp16 frags)

// ---------------- helpers ----------------
__device__ __forceinline__ uint32_t f2h2(float lo, float hi) {
    __half2 h = __floats2half2_rn(lo, hi);
    return *(uint32_t*)&h;
}

__device__ __forceinline__ float ex2f(float x) {
    float y;
    asm("ex2.approx.f32 %0, %1;" : "=f"(y) : "f"(x));
    return y;
}

// fp16 mma with fp32 accumulate: D(16x8) += A(16x16) * B(16x8)
__device__ __forceinline__ void mma16(float c[4], const uint32_t a[4], const uint32_t b[2]) {
    asm volatile(
        "mma.sync.aligned.m16n8k16.row.col.f32.f16.f16.f32 "
        "{%0,%1,%2,%3}, {%4,%5,%6,%7}, {%8,%9}, {%0,%1,%2,%3};"
        : "+f"(c[0]), "+f"(c[1]), "+f"(c[2]), "+f"(c[3])
        : "r"(a[0]), "r"(a[1]), "r"(a[2]), "r"(a[3]), "r"(b[0]), "r"(b[1]));
}

__device__ __forceinline__ void cpasync16(uint32_t saddr, const void* gptr) {
    asm volatile("cp.async.cg.shared.global [%0], [%1], 16;"
                 :: "r"(saddr), "l"(gptr));
}
#define CP_COMMIT() asm volatile("cp.async.commit_group;")
#define CP_WAIT1()  asm volatile("cp.async.wait_group 1;")
#define CP_WAIT2()  asm volatile("cp.async.wait_group 2;")

// ================= permute kernels (GEMM operands) ====
// Fragment conventions (m16n8k16, g = lane>>2, t2 = (lane&3)*2):
//  A-frag reg r: row = base + (r&1)*8 + g, k = kbase + (r>>1)*8 + t2, pair (k,k+1)
//  B-frag: b0 = (k = t2, t2+1, col g), b1 = (k = t2+8, t2+9, col g)

// A tiles: [M][K] -> [mb][kb][2048], o = ((ks*8 + mf)*32 + lane)*4 + r
__global__ void permA_kernel(const float* __restrict__ A, uint32_t* __restrict__ out,
                             int M, int K) {
    __shared__ float t[128 * 36];
    const int kb = blockIdx.x, mb = blockIdx.y, nkb = gridDim.x;
    const int tid = threadIdx.x;
#pragma unroll
    for (int p = 0; p < 4; p++) {
        int idx = tid + p * 256;
        int r = idx >> 3, c4 = (idx & 7) * 4;
        float4 v = *(const float4*)&A[(size_t)(mb * 128 + r) * K + kb * 32 + c4];
        *(float4*)&t[r * 36 + c4] = v;
    }
    __syncthreads();
    uint32_t* dst = out + ((size_t)mb * nkb + kb) * 2048;
#pragma unroll
    for (int q = 0; q < 2; q++) {
        int o = q * 1024 + tid * 4;
        int lane = (o >> 2) & 31, mf = (o >> 7) & 7, ks = o >> 10;
        int g = lane >> 2, t2 = (lane & 3) * 2;
        int rb = mf * 16 + g, kb2 = ks * 16 + t2;
        uint4 u;
        u.x = f2h2(t[rb * 36 + kb2],           t[rb * 36 + kb2 + 1]);
        u.y = f2h2(t[(rb + 8) * 36 + kb2],     t[(rb + 8) * 36 + kb2 + 1]);
        u.z = f2h2(t[rb * 36 + kb2 + 8],       t[rb * 36 + kb2 + 9]);
        u.w = f2h2(t[(rb + 8) * 36 + kb2 + 8], t[(rb + 8) * 36 + kb2 + 9]);
        *(uint4*)&dst[o] = u;
    }
}

// B tiles: [K][N] -> [kb][nb][2048], o = ((ks*8 + nf2)*32 + lane)*4 + jl*2 + kk2
__global__ void permB_kernel(const float* __restrict__ B, uint32_t* __restrict__ out,
                             int K, int N) {
    __shared__ float t[32 * 132];
    const int nb = blockIdx.x, kb = blockIdx.y, nnb = gridDim.x;
    const int tid = threadIdx.x;
#pragma unroll
    for (int p = 0; p < 4; p++) {
        int idx = tid + p * 256;
        int r = idx >> 5, c4 = (idx & 31) * 4;
        float4 v = *(const float4*)&B[(size_t)(kb * 32 + r) * N + nb * 128 + c4];
        *(float4*)&t[r * 132 + c4] = v;
    }
    __syncthreads();
    uint32_t* dst = out + ((size_t)kb * nnb + nb) * 2048;
#pragma unroll
    for (int q = 0; q < 2; q++) {
        int o = q * 1024 + tid * 4;
        uint32_t u[4];
#pragma unroll
        for (int e = 0; e < 4; e++) {
            int oe = o + e;
            int kk2 = oe & 1, jl = (oe >> 1) & 1;
            int lane = (oe >> 2) & 31;
            int nf2 = (oe >> 7) & 7, ks = oe >> 10;
            int g = lane >> 2, t2 = (lane & 3) * 2;
            int nf = 2 * nf2 + jl;
            int k = ks * 16 + kk2 * 8 + t2;
            int c = nf * 8 + g;
            u[e] = f2h2(t[k * 132 + c], t[(k + 1) * 132 + c]);
        }
        *(uint4*)&dst[o] = make_uint4(u[0], u[1], u[2], u[3]);
    }
}

// ================= fused RMSNorm + mRoPE + Q/K/V fragment emit =================
// grid (128 token-tiles, 4 head-groups), 256 threads.
// yg handles heads yg*6..yg*6+5 (q heads h<16, k heads 16..23) and V kv = yg*2, yg*2+1.
__global__ __launch_bounds__(256, 4)
void nrqkv_kernel(const float* __restrict__ qkv, const int* __restrict__ positions,
                  const float* __restrict__ qw, const float* __restrict__ kw,
                  const float* __restrict__ cache,
                  uint32_t* __restrict__ qf, uint32_t* __restrict__ kf,
                  uint32_t* __restrict__ vf) {
    __shared__ float cs[32][64], sn[32][64];
    __shared__ float tile[32][132];
    const int tid = threadIdx.x;
    const int tb = blockIdx.x;
    const int yg = blockIdx.y;
    const int tile0 = tb * 32;

    for (int idx = tid; idx < 2048; idx += 256) {
        int ts = idx >> 6, i = idx & 63;
        int m3 = i % 3;
        int sec = (i < 60) ? ((m3 == 1) ? 1 : ((m3 == 2) ? 2 : 0)) : 0;
        int pos = positions[sec * S_LEN + tile0 + ts];
        cs[ts][i] = cache[(size_t)pos * HD + i];
        sn[ts][i] = cache[(size_t)pos * HD + 64 + i];
    }
    __syncthreads();

    const int warp = tid >> 5, lane = tid & 31;
    const int dbase = lane * 4;
    const bool lo = (lane < 16);
    const float CC = ATT_SCALE * LOG2E;

    for (int hh = 0; hh < 6; hh++) {
        const int h = yg * 6 + hh;                     // 0..23
        const float* wnorm = (h < NH) ? qw : kw;
        // q heads at h*128; k heads at 2048+(h-16)*128 = h*128 (contiguous) — same formula.
#pragma unroll
        for (int it = 0; it < 4; it++) {
            int ts = warp + it * 8;
            const float* src = qkv + (size_t)(tile0 + ts) * QKV_N + h * HD;
            float4 xv = *(const float4*)(src + dbase);
            float x[4] = {xv.x, xv.y, xv.z, xv.w};
            float ss = x[0]*x[0] + x[1]*x[1] + x[2]*x[2] + x[3]*x[3];
#pragma unroll
            for (int o = 16; o > 0; o >>= 1)
                ss += __shfl_xor_sync(0xffffffffu, ss, o);
            float inv = rsqrtf(ss * (1.0f / HD) + EPS_RMS);
            float4 wv = *(const float4*)(wnorm + dbase);
            float nx[4] = {x[0]*inv*wv.x, x[1]*inv*wv.y, x[2]*inv*wv.z, x[3]*inv*wv.w};
            float out[4];
#pragma unroll
            for (int j = 0; j < 4; j++) {
                float partner = __shfl_xor_sync(0xffffffffu, nx[j], 16);
                int i2 = (dbase + j) & 63;
                float c = cs[ts][i2], si = sn[ts][i2];
                out[j] = lo ? (nx[j] * c - partner * si)
                            : (nx[j] * c + partner * si);
            }
            *(float4*)&tile[ts][dbase] = make_float4(out[0], out[1], out[2], out[3]);
        }
        __syncthreads();

        if (h < NH) {
            // Q A-fragments (scale pre-folded). Per 16-token grp: 1024 u32; tid->(ks=warp,lane).
            int g = lane >> 2, t2 = (lane & 3) * 2;
            int kd = warp * 16 + t2;
#pragma unroll
            for (int grp = 0; grp < 2; grp++) {
                int row = grp * 16 + g;
                uint4 u;
                u.x = f2h2(tile[row][kd] * CC,         tile[row][kd + 1] * CC);
                u.y = f2h2(tile[row + 8][kd] * CC,     tile[row + 8][kd + 1] * CC);
                u.z = f2h2(tile[row][kd + 8] * CC,     tile[row][kd + 9] * CC);
                u.w = f2h2(tile[row + 8][kd + 8] * CC, tile[row + 8][kd + 9] * CC);
                *(uint4*)&qf[((size_t)h * 256 + tb * 2 + grp) * 1024 + tid * 4] = u;
            }
        } else {
            // K B-fragments (same math as old permK)
            int kv = h - NH;
            uint32_t* dst = kf + ((size_t)kv * 128 + tb) * 2048;
#pragma unroll
            for (int q = 0; q < 2; q++) {
                int o = q * 1024 + tid * 4;
                uint32_t u[4];
#pragma unroll
                for (int e = 0; e < 4; e++) {
                    int oe = o + e;
                    int kk2 = oe & 1, jl = (oe >> 1) & 1;
                    int l = (oe >> 2) & 31;
                    int jj = (oe >> 7) & 1, ks = oe >> 8;
                    int g2 = l >> 2, t22 = (l & 3) * 2;
                    int j = 2 * jj + jl;
                    int r = j * 8 + g2;
                    int d = ks * 16 + kk2 * 8 + t22;
                    u[e] = f2h2(tile[r][d], tile[r][d + 1]);
                }
                *(uint4*)&dst[o] = make_uint4(u[0], u[1], u[2], u[3]);
            }
        }
        __syncthreads();
    }

    // ---- V fragments (no norm/rope), 2 kv heads per block ----
#pragma unroll
    for (int vv = 0; vv < 2; vv++) {
        int kv = yg * 2 + vv;
        for (int idx = tid * 4; idx < 32 * 128; idx += 1024) {
            int r = idx >> 7, c4 = idx & 127;
            *(float4*)&tile[r][c4] =
                *(const float4*)&qkv[(size_t)(tile0 + r) * QKV_N + VOFF + kv * HD + c4];
        }
        __syncthreads();
        uint32_t* dst = vf + ((size_t)kv * 128 + tb) * 2048;
#pragma unroll
        for (int q = 0; q < 2; q++) {
            int o = q * 1024 + tid * 4;
            uint32_t u[4];
#pragma unroll
            for (int e = 0; e < 4; e++) {
                int oe = o + e;
                int kk2 = oe & 1, jl = (oe >> 1) & 1;
                int l = (oe >> 2) & 31;
                int jj = (oe >> 7) & 7, ks = oe >> 10;
                int g2 = l >> 2, t22 = (l & 3) * 2;
                int jv = 2 * jj + jl;
                int d = jv * 8 + g2;
                int k = ks * 16 + kk2 * 8 + t22;
                u[e] = f2h2(tile[k][d], tile[k + 1][d]);
            }
            *(uint4*)&dst[o] = make_uint4(u[0], u[1], u[2], u[3]);
        }
        __syncthreads();
    }
}

// ================= fp16 GEMM (mma.sync m16n8k16) on pre-permuted tiles ========
#define GEMM_SMEM_BYTES (3 * 4096 * 4)

__global__ __launch_bounds__(256, 2)
void gemm_h(const uint32_t* __restrict__ Af, const uint32_t* __restrict__ Bf,
            float* __restrict__ C, int M, int N, int K) {
    extern __shared__ uint32_t smg[];
    const int tid  = threadIdx.x;
    const int lane = tid & 31;
    const int warp = tid >> 5;
    const int wm = warp >> 2, wn = warp & 3;
    const int g = lane >> 2, t = lane & 3;
    const int mb = blockIdx.y, nb = blockIdx.x;
    const int nkb = K / 32, nnb = N / 128;
    const uint32_t sbase = (uint32_t)__cvta_generic_to_shared(smg);
    const uint32_t* Asrc = Af + (size_t)mb * nkb * 2048;

    auto issue = [&](int kb, int st) {
        uint32_t dst = sbase + (uint32_t)st * 16384;
        const uint32_t* a = Asrc + (size_t)kb * 2048;
        const uint32_t* b = Bf + ((size_t)kb * nnb + nb) * 2048;
#pragma unroll
        for (int p = 0; p < 2; p++) {
            int i = tid + p * 256;
            cpasync16(dst + i * 16, a + i * 4);
            cpasync16(dst + 8192 + i * 16, b + i * 4);
        }
    };

    issue(0, 0); CP_COMMIT();
    issue(1, 1); CP_COMMIT();

    float acc[4][4][4];
#pragma unroll
    for (int i = 0; i < 4; i++)
#pragma unroll
        for (int j = 0; j < 4; j++)
#pragma unroll
            for (int e = 0; e < 4; e++) acc[i][j][e] = 0.f;

    for (int kb = 0; kb < nkb; kb++) {
        CP_WAIT1();
        __syncthreads();
        if (kb + 2 < nkb) issue(kb + 2, (kb + 2) % 3);
        CP_COMMIT();

        const uint32_t* As = smg + (kb % 3) * 4096;
        const uint32_t* Bs = As + 2048;
#pragma unroll
        for (int ks = 0; ks < 2; ks++) {
            uint32_t a[4][4];
#pragma unroll
            for (int i = 0; i < 4; i++) {
                uint4 av = *(const uint4*)&As[((ks * 8 + wm * 4 + i) * 32 + lane) * 4];
                a[i][0] = av.x; a[i][1] = av.y; a[i][2] = av.z; a[i][3] = av.w;
            }
#pragma unroll
            for (int j2 = 0; j2 < 2; j2++) {
                uint4 bv = *(const uint4*)&Bs[((ks * 8 + wn * 2 + j2) * 32 + lane) * 4];
                uint32_t b0[2] = {bv.x, bv.y};
                uint32_t b1[2] = {bv.z, bv.w};
#pragma unroll
                for (int i = 0; i < 4; i++) {
                    mma16(acc[i][2 * j2],     a[i], b0);
                    mma16(acc[i][2 * j2 + 1], a[i], b1);
                }
            }
        }
    }

#pragma unroll
    for (int i = 0; i < 4; i++)
#pragma unroll
        for (int j = 0; j < 4; j++) {
            int row0 = mb * 128 + wm * 64 + i * 16 + g;
            int col  = nb * 128 + wn * 32 + j * 8 + 2 * t;
            *(float2*)&C[(size_t)row0 * N + col]       = make_float2(acc[i][j][0], acc[i][j][1]);
            *(float2*)&C[(size_t)(row0 + 8) * N + col] = make_float2(acc[i][j][2], acc[i][j][3]);
        }
}

// ================= fp16 flash attention, Bq=64/Bk=32 =================
// Q fragments pre-built (scale folded) in g_qf. O written directly as O-proj
// A-fragment tiles into g_af.
#define ATTN_SMEM_BYTES (3 * 4096 * 4)

__global__ __launch_bounds__(128, 3)
void attn_h(const uint32_t* __restrict__ qf, const uint32_t* __restrict__ Kf,
            const uint32_t* __restrict__ Vf, uint32_t* __restrict__ af) {
    extern __shared__ uint32_t smu[];

    const int tid  = threadIdx.x;
    const int lane = tid & 31;
    const int w    = tid >> 5;           // 0..3
    const int g = lane >> 2, t = lane & 3;
    const int h  = blockIdx.y;
    const int qt = (int)gridDim.x - 1 - (int)blockIdx.x;   // heavy first
    const int q0 = qt * 64;
    const int kv = h >> 1;
    const int nkt = 2 * qt + 2;          // 32-wide key tiles
    const uint32_t sbase = (uint32_t)__cvta_generic_to_shared(smu);

    const uint32_t* Ksrc = Kf + (size_t)kv * (S_LEN / 32) * 2048;
    const uint32_t* Vsrc = Vf + (size_t)kv * (S_LEN / 32) * 2048;
    auto issue = [&](int kt, int st) {
        if (kt < nkt) {
            uint32_t dst = sbase + (uint32_t)st * 16384;
            const uint32_t* kp = Ksrc + (size_t)kt * 2048;
            const uint32_t* vp = Vsrc + (size_t)kt * 2048;
#pragma unroll
            for (int p = 0; p < 4; p++) {
                int i = tid + p * 128;
                cpasync16(dst + i * 16, kp + i * 4);
                cpasync16(dst + 8192 + i * 16, vp + i * 4);
            }
        }
    };
    issue(0, 0); CP_COMMIT();
    issue(1, 1); CP_COMMIT();
    issue(2, 2); CP_COMMIT();

    // ---- Q fragments: direct coalesced loads (overlap the cp.async fills) ----
    uint32_t aq[8][4];
    {
        const uint32_t* qsrc = qf + ((size_t)h * 256 + (q0 >> 4) + w) * 1024;
#pragma unroll
        for (int ks = 0; ks < 8; ks++) {
            uint4 v = *(const uint4*)&qsrc[(ks * 32 + lane) * 4];
            aq[ks][0] = v.x; aq[ks][1] = v.y; aq[ks][2] = v.z; aq[ks][3] = v.w;
        }
    }

    float oacc[16][4];
#pragma unroll
    for (int j = 0; j < 16; j++)
#pragma unroll
        for (int e = 0; e < 4; e++) oacc[j][e] = 0.f;
    float m2a = -1e30f, m2b = -1e30f;
    float la = 0.f, lb = 0.f;

    const int r0g = q0 + w * 16 + g;

#pragma unroll 1
    for (int kt = 0; kt < nkt; kt++) {
        CP_WAIT2();
        __syncthreads();
        const uint32_t* Ks = smu + (kt % 3) * 4096;
        const uint32_t* Vs = Ks + 2048;

        // ---- scores: 16 rows x 32 keys per warp ----
        float sc[4][4];
#pragma unroll
        for (int j = 0; j < 4; j++)
#pragma unroll
            for (int e = 0; e < 4; e++) sc[j][e] = 0.f;
#pragma unroll
        for (int ks = 0; ks < 8; ks++) {
#pragma unroll
            for (int jj = 0; jj < 2; jj++) {
                uint4 bv = *(const uint4*)&Ks[((ks * 2 + jj) * 32 + lane) * 4];
                uint32_t b0[2] = {bv.x, bv.y};
                uint32_t b1[2] = {bv.z, bv.w};
                mma16(sc[2 * jj],     aq[ks], b0);
                mma16(sc[2 * jj + 1], aq[ks], b1);
            }
        }

        // ---- causal mask (diagonal tiles only) ----
        if (kt >= 2 * qt) {
            const int k0 = kt * 32;
#pragma unroll
            for (int j = 0; j < 4; j++) {
                int c0 = k0 + j * 8 + 2 * t;
                if (c0     > r0g)     sc[j][0] = -1e30f;
                if (c0 + 1 > r0g)     sc[j][1] = -1e30f;
                if (c0     > r0g + 8) sc[j][2] = -1e30f;
                if (c0 + 1 > r0g + 8) sc[j][3] = -1e30f;
            }
        }

        // ---- online softmax (warp-local, quad reduction) ----
        float mx0 = -1e30f, mx1 = -1e30f;
#pragma unroll
        for (int j = 0; j < 4; j++) {
            mx0 = fmaxf(mx0, fmaxf(sc[j][0], sc[j][1]));
            mx1 = fmaxf(mx1, fmaxf(sc[j][2], sc[j][3]));
        }
        mx0 = fmaxf(mx0, __shfl_xor_sync(0xffffffffu, mx0, 1));
        mx0 = fmaxf(mx0, __shfl_xor_sync(0xffffffffu, mx0, 2));
        mx1 = fmaxf(mx1, __shfl_xor_sync(0xffffffffu, mx1, 1));
        mx1 = fmaxf(mx1, __shfl_xor_sync(0xffffffffu, mx1, 2));
        float mn0 = fmaxf(m2a, mx0), mn1 = fmaxf(m2b, mx1);
        float f0 = ex2f(m2a - mn0), f1 = ex2f(m2b - mn1);
        m2a = mn0; m2b = mn1;

        float s0 = 0.f, s1 = 0.f;
#pragma unroll
        for (int j = 0; j < 4; j++) {
            sc[j][0] = ex2f(sc[j][0] - mn0);
            sc[j][1] = ex2f(sc[j][1] - mn0);
            sc[j][2] = ex2f(sc[j][2] - mn1);
            sc[j][3] = ex2f(sc[j][3] - mn1);
            s0 += sc[j][0] + sc[j][1];
            s1 += sc[j][2] + sc[j][3];
        }
        s0 += __shfl_xor_sync(0xffffffffu, s0, 1);
        s0 += __shfl_xor_sync(0xffffffffu, s0, 2);
        s1 += __shfl_xor_sync(0xffffffffu, s1, 1);
        s1 += __shfl_xor_sync(0xffffffffu, s1, 2);
        la = la * f0 + s0;
        lb = lb * f1 + s1;

#pragma unroll
        for (int j = 0; j < 16; j++) {
            oacc[j][0] *= f0; oacc[j][1] *= f0;
            oacc[j][2] *= f1; oacc[j][3] *= f1;
        }

        // ---- P fragments directly from sc (no smem roundtrip) ----
        uint32_t pa[2][4];
#pragma unroll
        for (int ks2 = 0; ks2 < 2; ks2++) {
            pa[ks2][0] = f2h2(sc[2 * ks2][0],     sc[2 * ks2][1]);
            pa[ks2][1] = f2h2(sc[2 * ks2][2],     sc[2 * ks2][3]);
            pa[ks2][2] = f2h2(sc[2 * ks2 + 1][0], sc[2 * ks2 + 1][1]);
            pa[ks2][3] = f2h2(sc[2 * ks2 + 1][2], sc[2 * ks2 + 1][3]);
        }

        // ---- O += P @ V ----
#pragma unroll
        for (int ks2 = 0; ks2 < 2; ks2++) {
#pragma unroll
            for (int jj = 0; jj < 8; jj++) {
                uint4 bv = *(const uint4*)&Vs[((ks2 * 8 + jj) * 32 + lane) * 4];
                uint32_t b0[2] = {bv.x, bv.y};
                uint32_t b1[2] = {bv.z, bv.w};
                mma16(oacc[2 * jj],     pa[ks2], b0);
                mma16(oacc[2 * jj + 1], pa[ks2], b1);
            }
        }
        __syncthreads();          // all warps done with this stage
        issue(kt + 3, kt % 3);    // refill consumed stage
        CP_COMMIT();
    }

    // ---- epilogue: write O directly as O-proj A-fragment tiles ----
    {
        float inv0 = 1.f / la, inv1 = 1.f / lb;
        const int mb = q0 >> 7;
        const int mf = 4 * (qt & 1) + w;
#pragma unroll
        for (int jp = 0; jp < 8; jp++) {           // pairs (j=2jp, 2jp+1)
            int j = 2 * jp;
            int kb = h * 4 + (j >> 2);
            int ks = (j >> 1) & 1;
            uint32_t* dst = af + ((size_t)mb * 64 + kb) * 2048
                               + ((ks * 8 + mf) * 32 + lane) * 4;
            uint4 u;
            u.x = f2h2(oacc[j][0] * inv0,     oacc[j][1] * inv0);
            u.y = f2h2(oacc[j][2] * inv1,     oacc[j][3] * inv1);
            u.z = f2h2(oacc[j + 1][0] * inv0, oacc[j + 1][1] * inv0);
            u.w = f2h2(oacc[j + 1][2] * inv1, oacc[j + 1][3] * inv1);
            *(uint4*)dst = u;
        }
    }
}

// ---------------- launch ----------------
extern "C" void kernel_launch(void* const* d_in, const int* in_sizes, int n_in,
                              void* d_out, int out_size) {
    const float* hidden    = (const float*)d_in[0];
    const int*   positions = (const int*)  d_in[1];
    const float* w_qkv     = (const float*)d_in[2];
    const float* w_o       = (const float*)d_in[3];
    const float* q_norm_w  = (const float*)d_in[4];
    const float* k_norm_w  = (const float*)d_in[5];
    const float* cache     = (const float*)d_in[6];
    float* out = (float*)d_out;

    float *qkv_p;
    uint32_t *af_p, *bf_p, *qf_p, *kf_p, *vf_p;
    cudaGetSymbolAddress((void**)&qkv_p, g_qkv);
    cudaGetSymbolAddress((void**)&af_p,  g_af);
    cudaGetSymbolAddress((void**)&bf_p,  g_bf);
    cudaGetSymbolAddress((void**)&qf_p,  g_qf);
    cudaGetSymbolAddress((void**)&kf_p,  g_kf);
    cudaGetSymbolAddress((void**)&vf_p,  g_vf);

    cudaFuncSetAttribute(gemm_h, cudaFuncAttributeMaxDynamicSharedMemorySize,
                         GEMM_SMEM_BYTES);
    cudaFuncSetAttribute(attn_h, cudaFuncAttributeMaxDynamicSharedMemorySize,
                         ATTN_SMEM_BYTES);

    // 1) QKV projection (fp16 tensor cores)
    permA_kernel<<<dim3(64, 32), 256>>>(hidden, af_p, S_LEN, HDIM);
    permB_kernel<<<dim3(32, 64), 256>>>(w_qkv, bf_p, HDIM, QKV_N);
    gemm_h<<<dim3(32, 32), 256, GEMM_SMEM_BYTES>>>(af_p, bf_p, qkv_p,
                                                   S_LEN, QKV_N, HDIM);

    // 2) fused RMSNorm + mRoPE + Q/K/V fragment emit
    nrqkv_kernel<<<dim3(S_LEN / 32, 4), 256>>>(qkv_p, positions, q_norm_w,
                                               k_norm_w, cache, qf_p, kf_p, vf_p);

    // 3) flash attention (fp16) -> writes O as A-frag tiles into g_af
    attn_h<<<dim3(S_LEN / 64, NH), 128, ATTN_SMEM_BYTES>>>(qf_p, kf_p, vf_p, af_p);

    // 4) output projection (fp16 tensor cores)
    permB_kernel<<<dim3(16, 64), 256>>>(w_o, bf_p, HDIM, HDIM);
    gemm_h<<<dim3(16, 32), 256, GEMM_SMEM_BYTES>>>(af_p, bf_p, out,
                                                   S_LEN, HDIM, HDIM);
}